// round 1
// baseline (speedup 1.0000x reference)
#include <cuda_runtime.h>

// ---------------------------------------------------------------------------
// MultiHeadAttention WITHOUT softmax  ==  purely linear operator.
//   out_b = query_b @ Wbig_b + bbig_b
// where Wbig_b = Wq @ P_b,  P_b = stack_h( (scale*K_{b,h}^T V_{b,h}) @ Wo_h ),
//       bbig_b = bq @ P_b + bo,
//       K = key@Wk + bk,  V = value@Wv + bv.
// All fp32 SIMT (precision-safe); ~60 GFLOP total.
// ---------------------------------------------------------------------------

namespace {
constexpr int Bn  = 4;
constexpr int Ssz = 2048;
constexpr int Dd  = 1024;      // model dim (= input dim = heads*head_dim)
constexpr int Hh  = 16;
constexpr int HD  = 64;
}

// Scratch (device globals -- allocation-free per harness rules)
__device__ float g_K[(size_t)Bn * Ssz * Dd];       // 32 MB
__device__ float g_V[(size_t)Bn * Ssz * Dd];       // 32 MB
__device__ float g_M[(size_t)Bn * Hh * HD * HD];   //  1 MB
__device__ float g_P[(size_t)Bn * Dd * Dd];        // 16 MB
__device__ float g_W[(size_t)Bn * Dd * Dd];        // 16 MB
__device__ float g_b[(size_t)Bn * Dd];

// ---------------------------------------------------------------------------
// General batched GEMM: C = A @ B (+ bias), row-major, fp32.
// 128x128 tile, BK=8, 256 threads, 8x8 per-thread microtile.
// Requires M%128==0, N%128==0, K%8==0 (true for all uses here).
// ---------------------------------------------------------------------------
__global__ void __launch_bounds__(256) gemm128(
    const float* __restrict__ A, const float* __restrict__ B,
    const float* __restrict__ bias, float* __restrict__ C,
    int N, int K,
    long sA, long sB, long sBias, long sC)
{
    const int batch = blockIdx.z;
    A += (long)batch * sA;
    B += (long)batch * sB;
    C += (long)batch * sC;
    if (bias) bias += (long)batch * sBias;

    const int m0 = blockIdx.y * 128;
    const int n0 = blockIdx.x * 128;

    __shared__ float As[8][128];
    __shared__ float Bs[8][128];

    const int tid  = threadIdx.x;
    const int aRow = tid >> 1;          // 0..127
    const int aCol = (tid & 1) * 4;     // 0 or 4
    const int bRow = tid >> 5;          // 0..7
    const int bCol = (tid & 31) * 4;    // 0..124
    const int tx   = tid & 15;
    const int ty   = tid >> 4;

    const float* Aptr = A + (long)(m0 + aRow) * K + aCol;
    const float* Bptr = B + (long)bRow * N + n0 + bCol;

    float acc[8][8];
    #pragma unroll
    for (int i = 0; i < 8; i++)
        #pragma unroll
        for (int j = 0; j < 8; j++) acc[i][j] = 0.f;

    for (int k0 = 0; k0 < K; k0 += 8) {
        float4 av = *(const float4*)(Aptr + k0);
        float4 bv = *(const float4*)(Bptr + (long)k0 * N);
        __syncthreads();
        As[aCol + 0][aRow] = av.x;
        As[aCol + 1][aRow] = av.y;
        As[aCol + 2][aRow] = av.z;
        As[aCol + 3][aRow] = av.w;
        *(float4*)&Bs[bRow][bCol] = bv;
        __syncthreads();

        #pragma unroll
        for (int kk = 0; kk < 8; kk++) {
            float4 a0 = *(const float4*)&As[kk][ty * 8];
            float4 a1 = *(const float4*)&As[kk][ty * 8 + 4];
            float4 b0 = *(const float4*)&Bs[kk][tx * 8];
            float4 b1 = *(const float4*)&Bs[kk][tx * 8 + 4];
            float ra[8] = {a0.x, a0.y, a0.z, a0.w, a1.x, a1.y, a1.z, a1.w};
            float rb[8] = {b0.x, b0.y, b0.z, b0.w, b1.x, b1.y, b1.z, b1.w};
            #pragma unroll
            for (int i = 0; i < 8; i++)
                #pragma unroll
                for (int j = 0; j < 8; j++)
                    acc[i][j] += ra[i] * rb[j];
        }
    }

    // epilogue
    float bb[8];
    #pragma unroll
    for (int j = 0; j < 8; j++)
        bb[j] = bias ? bias[n0 + tx * 8 + j] : 0.f;

    #pragma unroll
    for (int i = 0; i < 8; i++) {
        float* cp = C + (long)(m0 + ty * 8 + i) * N + n0 + tx * 8;
        float4 v0 = make_float4(acc[i][0] + bb[0], acc[i][1] + bb[1],
                                acc[i][2] + bb[2], acc[i][3] + bb[3]);
        float4 v1 = make_float4(acc[i][4] + bb[4], acc[i][5] + bb[5],
                                acc[i][6] + bb[6], acc[i][7] + bb[7]);
        *(float4*)cp = v0;
        *(float4*)(cp + 4) = v1;
    }
}

// ---------------------------------------------------------------------------
// M_{b,h}[i][j] = scale * sum_s K[b,s,h*64+i] * V[b,s,h*64+j]
// grid (Hh, Bn), 256 threads, 4x4 per-thread microtile over the 64x64 output.
// ---------------------------------------------------------------------------
__global__ void __launch_bounds__(256) kvM_kernel(
    const float* __restrict__ Kg, const float* __restrict__ Vg,
    float* __restrict__ Mout)
{
    const int h = blockIdx.x;
    const int b = blockIdx.y;
    const float* Kp = Kg + (long)b * Ssz * Dd + h * HD;
    const float* Vp = Vg + (long)b * Ssz * Dd + h * HD;

    __shared__ float Kt[32][64];
    __shared__ float Vt[32][64];

    const int tid = threadIdx.x;
    const int ti = tid & 15;     // i-block (4 rows)
    const int tj = tid >> 4;     // j-block (4 cols)
    const int lr = tid >> 3;     // 0..31 load row
    const int lc = (tid & 7) * 8;

    float acc[4][4];
    #pragma unroll
    for (int a = 0; a < 4; a++)
        #pragma unroll
        for (int c = 0; c < 4; c++) acc[a][c] = 0.f;

    for (int s0 = 0; s0 < Ssz; s0 += 32) {
        const float* kp = Kp + (long)(s0 + lr) * Dd + lc;
        const float* vp = Vp + (long)(s0 + lr) * Dd + lc;
        float4 k0 = *(const float4*)kp;
        float4 k1 = *(const float4*)(kp + 4);
        float4 v0 = *(const float4*)vp;
        float4 v1 = *(const float4*)(vp + 4);
        __syncthreads();
        *(float4*)&Kt[lr][lc]     = k0;
        *(float4*)&Kt[lr][lc + 4] = k1;
        *(float4*)&Vt[lr][lc]     = v0;
        *(float4*)&Vt[lr][lc + 4] = v1;
        __syncthreads();

        #pragma unroll 8
        for (int ss = 0; ss < 32; ss++) {
            float4 ka = *(const float4*)&Kt[ss][ti * 4];
            float4 va = *(const float4*)&Vt[ss][tj * 4];
            float rk[4] = {ka.x, ka.y, ka.z, ka.w};
            float rv[4] = {va.x, va.y, va.z, va.w};
            #pragma unroll
            for (int a = 0; a < 4; a++)
                #pragma unroll
                for (int c = 0; c < 4; c++)
                    acc[a][c] += rk[a] * rv[c];
        }
    }

    const float scale = 0.125f;  // 1/sqrt(64)
    float* Mp = Mout + ((long)(b * Hh + h)) * HD * HD;
    #pragma unroll
    for (int a = 0; a < 4; a++) {
        float4 v = make_float4(acc[a][0] * scale, acc[a][1] * scale,
                               acc[a][2] * scale, acc[a][3] * scale);
        *(float4*)&Mp[(ti * 4 + a) * HD + tj * 4] = v;
    }
}

// ---------------------------------------------------------------------------
// P_b rows [h*64 .. h*64+63]  =  M_{b,h} @ Wo[h*64: h*64+64, :]
// grid (Dd/128, Hh, Bn), 256 threads; each thread: 8 rows x 4 cols.
// ---------------------------------------------------------------------------
__global__ void __launch_bounds__(256) P_kernel(
    const float* __restrict__ Mmat, const float* __restrict__ Wo,
    float* __restrict__ P)
{
    const int nb = blockIdx.x;
    const int h  = blockIdx.y;
    const int b  = blockIdx.z;

    __shared__ float Ms[64][64];
    const float* Mp = Mmat + ((long)(b * Hh + h)) * HD * HD;
    for (int i = threadIdx.x; i < HD * HD; i += 256)
        Ms[i >> 6][i & 63] = Mp[i];
    __syncthreads();

    const int tid  = threadIdx.x;
    const int col  = nb * 128 + (tid & 31) * 4;
    const int row0 = (tid >> 5) * 8;

    float acc[8][4];
    #pragma unroll
    for (int i = 0; i < 8; i++)
        #pragma unroll
        for (int c = 0; c < 4; c++) acc[i][c] = 0.f;

    const float* Wp = Wo + (long)(h * HD) * Dd + col;
    #pragma unroll 4
    for (int j = 0; j < HD; j++) {
        float4 w = *(const float4*)(Wp + (long)j * Dd);
        #pragma unroll
        for (int i = 0; i < 8; i++) {
            float m = Ms[row0 + i][j];
            acc[i][0] += m * w.x;
            acc[i][1] += m * w.y;
            acc[i][2] += m * w.z;
            acc[i][3] += m * w.w;
        }
    }

    float* Pp = P + (long)b * Dd * Dd + (long)(h * HD) * Dd;
    #pragma unroll
    for (int i = 0; i < 8; i++) {
        float4 v = make_float4(acc[i][0], acc[i][1], acc[i][2], acc[i][3]);
        *(float4*)(Pp + (long)(row0 + i) * Dd + col) = v;
    }
}

// ---------------------------------------------------------------------------
// bbig_b[n] = sum_r bq[r] * P_b[r][n] + bo[n]
// ---------------------------------------------------------------------------
__global__ void __launch_bounds__(256) bbig_kernel(
    const float* __restrict__ P, const float* __restrict__ bq,
    const float* __restrict__ bo, float* __restrict__ bbig)
{
    const int b = blockIdx.y;
    const int n = blockIdx.x * 256 + threadIdx.x;
    const float* Pp = P + (long)b * Dd * Dd;
    float acc = bo[n];
    for (int r = 0; r < Dd; r++)
        acc += bq[r] * Pp[(long)r * Dd + n];
    bbig[b * Dd + n] = acc;
}

// ---------------------------------------------------------------------------
extern "C" void kernel_launch(void* const* d_in, const int* in_sizes, int n_in,
                              void* d_out, int out_size)
{
    const float* query = (const float*)d_in[0];
    const float* key   = (const float*)d_in[1];
    const float* value = (const float*)d_in[2];
    const float* Wq    = (const float*)d_in[3];
    const float* bq    = (const float*)d_in[4];
    const float* Wk    = (const float*)d_in[5];
    const float* bk    = (const float*)d_in[6];
    const float* Wv    = (const float*)d_in[7];
    const float* bv    = (const float*)d_in[8];
    const float* Wo    = (const float*)d_in[9];
    const float* bo    = (const float*)d_in[10];
    float* out = (float*)d_out;

    float *pK, *pV, *pM, *pP, *pW, *pB;
    cudaGetSymbolAddress((void**)&pK, g_K);
    cudaGetSymbolAddress((void**)&pV, g_V);
    cudaGetSymbolAddress((void**)&pM, g_M);
    cudaGetSymbolAddress((void**)&pP, g_P);
    cudaGetSymbolAddress((void**)&pW, g_W);
    cudaGetSymbolAddress((void**)&pB, g_b);

    // 1) K = key @ Wk + bk      [8192,1024] = [8192,1024]@[1024,1024]
    gemm128<<<dim3(Dd / 128, (Bn * Ssz) / 128, 1), 256>>>(
        key, Wk, bk, pK, Dd, Dd, 0, 0, 0, 0);
    // 2) V = value @ Wv + bv
    gemm128<<<dim3(Dd / 128, (Bn * Ssz) / 128, 1), 256>>>(
        value, Wv, bv, pV, Dd, Dd, 0, 0, 0, 0);
    // 3) M_{b,h} = scale * K_h^T V_h
    kvM_kernel<<<dim3(Hh, Bn), 256>>>(pK, pV, pM);
    // 4) P_b = stack_h( M_{b,h} @ Wo_h )
    P_kernel<<<dim3(Dd / 128, Hh, Bn), 256>>>(pM, Wo, pP);
    // 5) Wbig_b = Wq @ P_b   (batched over b; A shared)
    gemm128<<<dim3(Dd / 128, Dd / 128, Bn), 256>>>(
        Wq, pP, nullptr, pW, Dd, Dd,
        0, (long)Dd * Dd, 0, (long)Dd * Dd);
    // 6) bbig_b = bq @ P_b + bo
    bbig_kernel<<<dim3(Dd / 256, Bn), 256>>>(pP, bq, bo, pB);
    // 7) out_b = query_b @ Wbig_b + bbig_b
    gemm128<<<dim3(Dd / 128, Ssz / 128, Bn), 256>>>(
        query, pW, pB, out, Dd, Dd,
        (long)Ssz * Dd, (long)Dd * Dd, Dd, (long)Ssz * Dd);
}

// round 3
// speedup vs baseline: 1.7396x; 1.7396x over previous
#include <cuda_runtime.h>
#include <cuda_bf16.h>
#include <cstdint>

// ===========================================================================
// MultiHeadAttention WITHOUT softmax == linear operator.
//   K = key@Wk + bk ; V = value@Wv + bv            (mma.sync bf16-split)
//   M_{b,h} = scale * K_h^T V_h                    (SIMT, tiny)
//   P_b = stack_h(M_{b,h} @ Wo_h)                  (SIMT, tiny)
//   WbigT_b = P_b^T @ Wq^T                         (mma.sync bf16-split)
//   bbig_b = bq@P_b + bo                           (SIMT, tiny)
//   out_b = query_b @ Wbig_b + bbig_b              (mma.sync bf16-split)
// fp32 accuracy via bf16 hi/lo split: A*B ~= Ah*Bh + Ah*Bl + Al*Bh
// NOTE: toolchain emits .target sm_100 (no 'a') -> tcgen05 unavailable;
// using portable ldmatrix + mma.sync (HMMA) + cp.async instead.
// ===========================================================================

namespace {
constexpr int Bn  = 4;
constexpr int Ssz = 2048;
constexpr int Dd  = 1024;
constexpr int Hh  = 16;
constexpr int HD  = 64;
constexpr int GME = Bn * Ssz * Dd;   // 8M elements
}

// ------------------------- scratch (device globals) ------------------------
__device__ float g_K[GME];
__device__ float g_V[GME];
__device__ float g_M[Bn * Hh * HD * HD];
__device__ float g_P[(size_t)Bn * Dd * Dd];
__device__ float g_b[Bn * Dd];

__device__ __nv_bfloat16 g_q_hi[GME],  g_q_lo[GME];
__device__ __nv_bfloat16 g_k_hi[GME],  g_k_lo[GME];
__device__ __nv_bfloat16 g_v_hi[GME],  g_v_lo[GME];
__device__ __nv_bfloat16 g_wq_hi[Dd * Dd],  g_wq_lo[Dd * Dd];
__device__ __nv_bfloat16 g_wkT_hi[Dd * Dd], g_wkT_lo[Dd * Dd];
__device__ __nv_bfloat16 g_wvT_hi[Dd * Dd], g_wvT_lo[Dd * Dd];
__device__ __nv_bfloat16 g_pT_hi[(size_t)Bn * Dd * Dd], g_pT_lo[(size_t)Bn * Dd * Dd];
__device__ __nv_bfloat16 g_wbT_hi[(size_t)Bn * Dd * Dd], g_wbT_lo[(size_t)Bn * Dd * Dd];

// ------------------------------ PTX helpers --------------------------------
__device__ __forceinline__ uint32_t smem_u32(const void* p) {
    uint32_t a;
    asm("{ .reg .u64 t; cvta.to.shared.u64 t, %1; cvt.u32.u64 %0, t; }"
        : "=r"(a) : "l"(p));
    return a;
}

#define LDSM4(r, addr)                                                        \
    asm volatile("ldmatrix.sync.aligned.m8n8.x4.shared.b16 "                  \
                 "{%0,%1,%2,%3}, [%4];"                                       \
                 : "=r"((r)[0]), "=r"((r)[1]), "=r"((r)[2]), "=r"((r)[3])     \
                 : "r"(addr))

#define MMA_BF16(d, a, b)                                                     \
    asm volatile("mma.sync.aligned.m16n8k16.row.col.f32.bf16.bf16.f32 "       \
                 "{%0,%1,%2,%3}, {%4,%5,%6,%7}, {%8,%9}, {%0,%1,%2,%3};"      \
                 : "+f"((d)[0]), "+f"((d)[1]), "+f"((d)[2]), "+f"((d)[3])     \
                 : "r"((a)[0]), "r"((a)[1]), "r"((a)[2]), "r"((a)[3]),        \
                   "r"((b)[0]), "r"((b)[1]))

#define CP_ASYNC16(dst, src)                                                  \
    asm volatile("cp.async.cg.shared.global [%0], [%1], 16;"                  \
                 :: "r"(dst), "l"(src))
#define CP_COMMIT()  asm volatile("cp.async.commit_group;")
#define CP_WAIT1()   asm volatile("cp.async.wait_group 1;")
#define CP_WAIT0()   asm volatile("cp.async.wait_group 0;")

// ===========================================================================
// Tensor-core GEMM: C[M,N] = A[M,K] @ Bt[N,K]^T (+ bias[n]).
// fp32-accurate via bf16 hi/lo split (3 MMA terms).
// 128x128 CTA tile, K-chunk 32 (bf16), 3-stage cp.async pipeline.
// 8 warps in 4(m) x 2(n) grid; warp tile 32x64.
// Output: Cf (fp32 + bias) OR Chi/Clo (bf16 split pair).
// ===========================================================================
namespace {
constexpr int TILE_B      = 128 * 32 * 2;          // 8 KB per bf16 tile
constexpr int STAGE_BYTES = 4 * TILE_B;            // Ahi, Alo, Bhi, Blo
constexpr int STAGES      = 3;
constexpr int GEMM_SMEM   = STAGES * STAGE_BYTES;  // 96 KB
}

__global__ void __launch_bounds__(256) gemm_tc(
    const __nv_bfloat16* __restrict__ Ahi, const __nv_bfloat16* __restrict__ Alo, long sA,
    const __nv_bfloat16* __restrict__ Bhi, const __nv_bfloat16* __restrict__ Blo, long sB,
    const float* __restrict__ bias, long sBias,
    float* __restrict__ Cf,
    __nv_bfloat16* __restrict__ Chi, __nv_bfloat16* __restrict__ Clo,
    long sC, int Ndim, int Kdim)
{
    extern __shared__ char smem[];
    const uint32_t sb = smem_u32(smem);
    const int tid = threadIdx.x;
    const int wid = tid >> 5;
    const int l   = tid & 31;
    const int zb  = blockIdx.z;

    Ahi += (long)zb * sA;  Alo += (long)zb * sA;
    Bhi += (long)zb * sB;  Blo += (long)zb * sB;
    if (bias) bias += (long)zb * sBias;

    const int m0 = blockIdx.y * 128;
    const int n0 = blockIdx.x * 128;
    const int NC = Kdim >> 5;          // chunks of 32 bf16-K

    // ---- cp.async assignment: idx = tid*2 + i -> (row = idx>>2, c4 = idx&3)
    const int r0i = (tid * 2) >> 2, c40 = (tid * 2) & 3;
    const int r1i = (tid * 2 + 1) >> 2, c41 = (tid * 2 + 1) & 3;
    const __nv_bfloat16* gsrc[4] = {
        Ahi + (long)m0 * Kdim, Alo + (long)m0 * Kdim,
        Bhi + (long)n0 * Kdim, Blo + (long)n0 * Kdim };

    const uint32_t so0 = r0i * 64 + ((c40 ^ ((r0i >> 1) & 3)) << 4);
    const uint32_t so1 = r1i * 64 + ((c41 ^ ((r1i >> 1) & 3)) << 4);

    auto issue_stage = [&](int s, int c) {
        const uint32_t base = sb + s * STAGE_BYTES;
        #pragma unroll
        for (int t = 0; t < 4; t++) {
            CP_ASYNC16(base + t * TILE_B + so0,
                       gsrc[t] + (long)r0i * Kdim + c * 32 + c40 * 8);
            CP_ASYNC16(base + t * TILE_B + so1,
                       gsrc[t] + (long)r1i * Kdim + c * 32 + c41 * 8);
        }
    };

    // prologue: stages 0,1
    issue_stage(0, 0); CP_COMMIT();
    issue_stage(1, 1); CP_COMMIT();

    const int wm = wid & 3;       // m-warp: rows wm*32
    const int wn = wid >> 2;      // n-warp: cols wn*64

    float acc[2][8][4];
    #pragma unroll
    for (int i = 0; i < 2; i++)
        #pragma unroll
        for (int j = 0; j < 8; j++)
            #pragma unroll
            for (int q = 0; q < 4; q++) acc[i][j][q] = 0.f;

    // ldmatrix offsets (stage-relative), precomputed per ks
    // A: row = wm*32 + i*16 + (l&15), c4 = ks*2 + (l>>4)
    // B: row = wn*64 + p*16 + (l&7) + ((l&16)>>1), c4 = ks*2 + ((l>>3)&1)
    uint32_t aoff[2][2], boff[2][4];
    #pragma unroll
    for (int ks = 0; ks < 2; ks++) {
        #pragma unroll
        for (int i = 0; i < 2; i++) {
            int row = wm * 32 + i * 16 + (l & 15);
            int c4  = ks * 2 + (l >> 4);
            aoff[ks][i] = row * 64 + ((c4 ^ ((row >> 1) & 3)) << 4);
        }
        #pragma unroll
        for (int p = 0; p < 4; p++) {
            int row = wn * 64 + p * 16 + (l & 7) + ((l & 16) >> 1);
            int c4  = ks * 2 + ((l >> 3) & 1);
            boff[ks][p] = row * 64 + ((c4 ^ ((row >> 1) & 3)) << 4);
        }
    }

    for (int c = 0; c < NC; c++) {
        if (c + 1 < NC) { CP_WAIT1(); } else { CP_WAIT0(); }
        __syncthreads();
        if (c + 2 < NC) { issue_stage((c + 2) % STAGES, c + 2); CP_COMMIT(); }

        const uint32_t base = sb + (c % STAGES) * STAGE_BYTES;
        #pragma unroll
        for (int ks = 0; ks < 2; ks++) {
            uint32_t ah[2][4], al[2][4];
            #pragma unroll
            for (int i = 0; i < 2; i++) {
                LDSM4(ah[i], base + aoff[ks][i]);
                LDSM4(al[i], base + TILE_B + aoff[ks][i]);
            }
            uint32_t bh[8][2], bl[8][2];
            #pragma unroll
            for (int p = 0; p < 4; p++) {
                uint32_t rh[4], rl[4];
                LDSM4(rh, base + 2 * TILE_B + boff[ks][p]);
                LDSM4(rl, base + 3 * TILE_B + boff[ks][p]);
                bh[2*p][0] = rh[0]; bh[2*p][1] = rh[1];
                bh[2*p+1][0] = rh[2]; bh[2*p+1][1] = rh[3];
                bl[2*p][0] = rl[0]; bl[2*p][1] = rl[1];
                bl[2*p+1][0] = rl[2]; bl[2*p+1][1] = rl[3];
            }
            #pragma unroll
            for (int i = 0; i < 2; i++)
                #pragma unroll
                for (int j = 0; j < 8; j++) {
                    MMA_BF16(acc[i][j], ah[i], bh[j]);
                    MMA_BF16(acc[i][j], ah[i], bl[j]);
                    MMA_BF16(acc[i][j], al[i], bh[j]);
                }
        }
        __syncthreads();
    }

    // ---- epilogue: straight from registers
    const int mr = m0 + wm * 32 + (l >> 2);
    const int nc = n0 + wn * 64 + (l & 3) * 2;
    #pragma unroll
    for (int i = 0; i < 2; i++) {
        #pragma unroll
        for (int j = 0; j < 8; j++) {
            const int rr = mr + i * 16;
            const int cc = nc + j * 8;
            if (Cf) {
                float b0 = bias ? bias[cc] : 0.f;
                float b1 = bias ? bias[cc + 1] : 0.f;
                float2* p0 = (float2*)(Cf + (long)zb * sC + (long)rr * Ndim + cc);
                float2* p1 = (float2*)(Cf + (long)zb * sC + (long)(rr + 8) * Ndim + cc);
                *p0 = make_float2(acc[i][j][0] + b0, acc[i][j][1] + b1);
                *p1 = make_float2(acc[i][j][2] + b0, acc[i][j][3] + b1);
            } else {
                #pragma unroll
                for (int q = 0; q < 4; q++) {
                    float v = acc[i][j][q];
                    int row = rr + (q >> 1) * 8;
                    int col = cc + (q & 1);
                    __nv_bfloat16 h = __float2bfloat16_rn(v);
                    long o = (long)zb * sC + (long)row * Ndim + col;
                    Chi[o] = h;
                    Clo[o] = __float2bfloat16_rn(v - __bfloat162float(h));
                }
            }
        }
    }
}

// ===========================================================================
// small kernels
// ===========================================================================

// elementwise fp32 -> bf16 hi/lo (4 elems/thread)
__global__ void __launch_bounds__(256) split_kernel(
    const float* __restrict__ in, __nv_bfloat16* __restrict__ hi,
    __nv_bfloat16* __restrict__ lo, int n)
{
    int i = (blockIdx.x * 256 + threadIdx.x) * 4;
    if (i >= n) return;
    float4 x = *(const float4*)(in + i);
    float xs[4] = {x.x, x.y, x.z, x.w};
    __nv_bfloat16 h[4], lv[4];
    #pragma unroll
    for (int k = 0; k < 4; k++) {
        h[k] = __float2bfloat16_rn(xs[k]);
        lv[k] = __float2bfloat16_rn(xs[k] - __bfloat162float(h[k]));
    }
    __nv_bfloat162 h01; h01.x = h[0]; h01.y = h[1];
    __nv_bfloat162 h23; h23.x = h[2]; h23.y = h[3];
    __nv_bfloat162 l01; l01.x = lv[0]; l01.y = lv[1];
    __nv_bfloat162 l23; l23.x = lv[2]; l23.y = lv[3];
    *(__nv_bfloat162*)(hi + i)     = h01;
    *(__nv_bfloat162*)(hi + i + 2) = h23;
    *(__nv_bfloat162*)(lo + i)     = l01;
    *(__nv_bfloat162*)(lo + i + 2) = l23;
}

// transpose + split: out[c][r] = in[r][c]; in [R,C] fp32 -> out [C,R] bf16 hi/lo
__global__ void __launch_bounds__(256) splitT_kernel(
    const float* __restrict__ in, long sIn,
    __nv_bfloat16* __restrict__ hi, __nv_bfloat16* __restrict__ lo, long sOut,
    int R, int C)
{
    __shared__ float t[32][33];
    in += (long)blockIdx.z * sIn;
    hi += (long)blockIdx.z * sOut;
    lo += (long)blockIdx.z * sOut;
    const int c0 = blockIdx.x * 32;
    const int r0 = blockIdx.y * 32;
    const int tx = threadIdx.x, ty = threadIdx.y;
    for (int k = ty; k < 32; k += 8)
        t[k][tx] = in[(long)(r0 + k) * C + c0 + tx];
    __syncthreads();
    for (int k = ty; k < 32; k += 8) {
        float vv = t[tx][k];                       // in[r0+tx][c0+k]
        __nv_bfloat16 h = __float2bfloat16_rn(vv);
        long o = (long)(c0 + k) * R + r0 + tx;
        hi[o] = h;
        lo[o] = __float2bfloat16_rn(vv - __bfloat162float(h));
    }
}

// M_{b,h}[i][j] = scale * sum_s K[b,s,h*64+i] * V[b,s,h*64+j]
__global__ void __launch_bounds__(256) kvM_kernel(
    const float* __restrict__ Kg, const float* __restrict__ Vg,
    float* __restrict__ Mout)
{
    const int h = blockIdx.x;
    const int b = blockIdx.y;
    const float* Kp = Kg + (long)b * Ssz * Dd + h * HD;
    const float* Vp = Vg + (long)b * Ssz * Dd + h * HD;

    __shared__ float Kt[32][64];
    __shared__ float Vt[32][64];

    const int tid = threadIdx.x;
    const int ti = tid & 15;
    const int tj = tid >> 4;
    const int lr = tid >> 3;
    const int lc = (tid & 7) * 8;

    float acc[4][4];
    #pragma unroll
    for (int a = 0; a < 4; a++)
        #pragma unroll
        for (int c = 0; c < 4; c++) acc[a][c] = 0.f;

    for (int s0 = 0; s0 < Ssz; s0 += 32) {
        const float* kp = Kp + (long)(s0 + lr) * Dd + lc;
        const float* vp = Vp + (long)(s0 + lr) * Dd + lc;
        float4 k0 = *(const float4*)kp;
        float4 k1 = *(const float4*)(kp + 4);
        float4 v0 = *(const float4*)vp;
        float4 v1 = *(const float4*)(vp + 4);
        __syncthreads();
        *(float4*)&Kt[lr][lc]     = k0;
        *(float4*)&Kt[lr][lc + 4] = k1;
        *(float4*)&Vt[lr][lc]     = v0;
        *(float4*)&Vt[lr][lc + 4] = v1;
        __syncthreads();

        #pragma unroll 8
        for (int ss = 0; ss < 32; ss++) {
            float4 ka = *(const float4*)&Kt[ss][ti * 4];
            float4 va = *(const float4*)&Vt[ss][tj * 4];
            float rk[4] = {ka.x, ka.y, ka.z, ka.w};
            float rv[4] = {va.x, va.y, va.z, va.w};
            #pragma unroll
            for (int a = 0; a < 4; a++)
                #pragma unroll
                for (int c = 0; c < 4; c++)
                    acc[a][c] += rk[a] * rv[c];
        }
    }

    const float scale = 0.125f;
    float* Mp = Mout + ((long)(b * Hh + h)) * HD * HD;
    #pragma unroll
    for (int a = 0; a < 4; a++) {
        float4 vo = make_float4(acc[a][0] * scale, acc[a][1] * scale,
                                acc[a][2] * scale, acc[a][3] * scale);
        *(float4*)&Mp[(ti * 4 + a) * HD + tj * 4] = vo;
    }
}

// P_b rows [h*64..h*64+63] = M_{b,h} @ Wo[h*64:h*64+64, :]
__global__ void __launch_bounds__(256) P_kernel(
    const float* __restrict__ Mmat, const float* __restrict__ Wo,
    float* __restrict__ P)
{
    const int nb = blockIdx.x;
    const int h  = blockIdx.y;
    const int b  = blockIdx.z;

    __shared__ float Ms[64][64];
    const float* Mp = Mmat + ((long)(b * Hh + h)) * HD * HD;
    for (int i = threadIdx.x; i < HD * HD; i += 256)
        Ms[i >> 6][i & 63] = Mp[i];
    __syncthreads();

    const int tid  = threadIdx.x;
    const int col  = nb * 128 + (tid & 31) * 4;
    const int row0 = (tid >> 5) * 8;

    float acc[8][4];
    #pragma unroll
    for (int i = 0; i < 8; i++)
        #pragma unroll
        for (int c = 0; c < 4; c++) acc[i][c] = 0.f;

    const float* Wp = Wo + (long)(h * HD) * Dd + col;
    #pragma unroll 4
    for (int j = 0; j < HD; j++) {
        float4 w = *(const float4*)(Wp + (long)j * Dd);
        #pragma unroll
        for (int i = 0; i < 8; i++) {
            float m = Ms[row0 + i][j];
            acc[i][0] += m * w.x;
            acc[i][1] += m * w.y;
            acc[i][2] += m * w.z;
            acc[i][3] += m * w.w;
        }
    }

    float* Pp = P + (long)b * Dd * Dd + (long)(h * HD) * Dd;
    #pragma unroll
    for (int i = 0; i < 8; i++) {
        float4 vo = make_float4(acc[i][0], acc[i][1], acc[i][2], acc[i][3]);
        *(float4*)(Pp + (long)(row0 + i) * Dd + col) = vo;
    }
}

// bbig_b[n] = sum_r bq[r] * P_b[r][n] + bo[n]
__global__ void __launch_bounds__(256) bbig_kernel(
    const float* __restrict__ P, const float* __restrict__ bq,
    const float* __restrict__ bo, float* __restrict__ bbig)
{
    const int b = blockIdx.y;
    const int n = blockIdx.x * 256 + threadIdx.x;
    const float* Pp = P + (long)b * Dd * Dd;
    float acc = bo[n];
    for (int r = 0; r < Dd; r++)
        acc += bq[r] * Pp[(long)r * Dd + n];
    bbig[b * Dd + n] = acc;
}

// ===========================================================================
extern "C" void kernel_launch(void* const* d_in, const int* in_sizes, int n_in,
                              void* d_out, int out_size)
{
    const float* query = (const float*)d_in[0];
    const float* key   = (const float*)d_in[1];
    const float* value = (const float*)d_in[2];
    const float* Wq    = (const float*)d_in[3];
    const float* bq    = (const float*)d_in[4];
    const float* Wk    = (const float*)d_in[5];
    const float* bk    = (const float*)d_in[6];
    const float* Wv    = (const float*)d_in[7];
    const float* bv    = (const float*)d_in[8];
    const float* Wo    = (const float*)d_in[9];
    const float* bo    = (const float*)d_in[10];
    float* out = (float*)d_out;

    float *pK, *pV, *pM, *pP, *pB;
    cudaGetSymbolAddress((void**)&pK, g_K);
    cudaGetSymbolAddress((void**)&pV, g_V);
    cudaGetSymbolAddress((void**)&pM, g_M);
    cudaGetSymbolAddress((void**)&pP, g_P);
    cudaGetSymbolAddress((void**)&pB, g_b);
    __nv_bfloat16 *qh, *ql, *kh, *kl, *vh, *vl, *wqh, *wql;
    __nv_bfloat16 *wkth, *wktl, *wvth, *wvtl, *pth, *ptl, *wbth, *wbtl;
    cudaGetSymbolAddress((void**)&qh, g_q_hi);   cudaGetSymbolAddress((void**)&ql, g_q_lo);
    cudaGetSymbolAddress((void**)&kh, g_k_hi);   cudaGetSymbolAddress((void**)&kl, g_k_lo);
    cudaGetSymbolAddress((void**)&vh, g_v_hi);   cudaGetSymbolAddress((void**)&vl, g_v_lo);
    cudaGetSymbolAddress((void**)&wqh, g_wq_hi); cudaGetSymbolAddress((void**)&wql, g_wq_lo);
    cudaGetSymbolAddress((void**)&wkth, g_wkT_hi); cudaGetSymbolAddress((void**)&wktl, g_wkT_lo);
    cudaGetSymbolAddress((void**)&wvth, g_wvT_hi); cudaGetSymbolAddress((void**)&wvtl, g_wvT_lo);
    cudaGetSymbolAddress((void**)&pth, g_pT_hi); cudaGetSymbolAddress((void**)&ptl, g_pT_lo);
    cudaGetSymbolAddress((void**)&wbth, g_wbT_hi); cudaGetSymbolAddress((void**)&wbtl, g_wbT_lo);

    cudaFuncSetAttribute(gemm_tc, cudaFuncAttributeMaxDynamicSharedMemorySize, GEMM_SMEM);

    // 1) splits
    split_kernel<<<GME / 1024, 256>>>(query, qh, ql, GME);
    split_kernel<<<GME / 1024, 256>>>(key,   kh, kl, GME);
    split_kernel<<<GME / 1024, 256>>>(value, vh, vl, GME);
    split_kernel<<<(Dd * Dd) / 1024, 256>>>(Wq, wqh, wql, Dd * Dd);
    splitT_kernel<<<dim3(32, 32, 1), dim3(32, 8)>>>(Wk, 0, wkth, wktl, 0, Dd, Dd);
    splitT_kernel<<<dim3(32, 32, 1), dim3(32, 8)>>>(Wv, 0, wvth, wvtl, 0, Dd, Dd);

    // 2) K = key@Wk + bk ; V = value@Wv + bv  (fp32 out)
    gemm_tc<<<dim3(Dd / 128, (Bn * Ssz) / 128, 1), 256, GEMM_SMEM>>>(
        kh, kl, 0, wkth, wktl, 0, bk, 0, pK, nullptr, nullptr, 0, Dd, Dd);
    gemm_tc<<<dim3(Dd / 128, (Bn * Ssz) / 128, 1), 256, GEMM_SMEM>>>(
        vh, vl, 0, wvth, wvtl, 0, bv, 0, pV, nullptr, nullptr, 0, Dd, Dd);

    // 3) M, P, P^T, bbig
    kvM_kernel<<<dim3(Hh, Bn), 256>>>(pK, pV, pM);
    P_kernel<<<dim3(Dd / 128, Hh, Bn), 256>>>(pM, Wo, pP);
    splitT_kernel<<<dim3(32, 32, Bn), dim3(32, 8)>>>(
        pP, (long)Dd * Dd, pth, ptl, (long)Dd * Dd, Dd, Dd);
    bbig_kernel<<<dim3(Dd / 256, Bn), 256>>>(pP, bq, bo, pB);

    // 4) WbigT_b = P_b^T @ Wq^T  (bf16 hi/lo out)
    gemm_tc<<<dim3(Dd / 128, Dd / 128, Bn), 256, GEMM_SMEM>>>(
        pth, ptl, (long)Dd * Dd, wqh, wql, 0, nullptr, 0,
        nullptr, wbth, wbtl, (long)Dd * Dd, Dd, Dd);

    // 5) out_b = query_b @ Wbig_b + bbig_b  (fp32 out)
    gemm_tc<<<dim3(Dd / 128, Ssz / 128, Bn), 256, GEMM_SMEM>>>(
        qh, ql, (long)Ssz * Dd, wbth, wbtl, (long)Dd * Dd, pB, Dd,
        out, nullptr, nullptr, (long)Ssz * Dd, Dd, Dd);
}

// round 4
// speedup vs baseline: 1.9909x; 1.1445x over previous
#include <cuda_runtime.h>
#include <cuda_bf16.h>
#include <cstdint>

// ===========================================================================
// MHA WITHOUT softmax == linear operator, fully re-associated:
//   G_b  = key_b^T @ value_b                         (mma.sync bf16-split)
//   T1_b = G_b @ Wv                                  (mma.sync bf16-split)
//   M_{b,h} = scale*( diag64(Wk^T T1)_h
//             + (Wk^T ksum)_h (x) bv_h + bk_h (x) (Wv^T vsum)_h
//             + S * bk_h (x) bv_h )                  (SIMT, tiny)
//   P_b = stack_h(M_{b,h} @ Wo_h)                    (SIMT, tiny)
//   WbigT_b = P_b^T @ Wq^T                           (mma.sync bf16-split)
//   bbig_b = (sum_i bq.M)^T @ Wo + bo                (SIMT, tiny)
//   out_b = query_b @ Wbig_b + bbig_b                (mma.sync bf16-split)
// fp32 accuracy via bf16 hi/lo split: A*B ~= Ah*Bh + Ah*Bl + Al*Bh
// (tcgen05 unavailable: harness emits .target sm_100, no 'a' suffix)
// ===========================================================================

namespace {
constexpr int Bn  = 4;
constexpr int Ssz = 2048;
constexpr int Dd  = 1024;
constexpr int Hh  = 16;
constexpr int HD  = 64;
constexpr int GME = Bn * Ssz * Dd;   // 8M elements
constexpr int DD  = Dd * Dd;         // 1M
}

// ------------------------- scratch (device globals) ------------------------
__device__ float g_T1[(size_t)Bn * DD];     // 16 MB: G @ Wv (fp32)
__device__ float g_M[Bn * Hh * HD * HD];
__device__ float g_P[(size_t)Bn * DD];
__device__ float g_bbig[Bn * Dd];
__device__ float g_tv[Bn * Dd];
__device__ float g_ksum[Bn * Dd], g_vsum[Bn * Dd];
__device__ float g_kpart[Bn * 8 * Dd], g_vpart[Bn * 8 * Dd];
__device__ float g_cka[Bn * Dd], g_cvb[Bn * Dd];

__device__ __nv_bfloat16 g_q_hi[GME],  g_q_lo[GME];
__device__ __nv_bfloat16 g_kT_hi[GME], g_kT_lo[GME];   // key^T per batch [D,S]
__device__ __nv_bfloat16 g_vT_hi[GME], g_vT_lo[GME];   // value^T per batch
__device__ __nv_bfloat16 g_wq_hi[DD],  g_wq_lo[DD];
__device__ __nv_bfloat16 g_wvT_hi[DD], g_wvT_lo[DD];
__device__ __nv_bfloat16 g_G_hi[(size_t)Bn * DD], g_G_lo[(size_t)Bn * DD];
__device__ __nv_bfloat16 g_pT_hi[(size_t)Bn * DD], g_pT_lo[(size_t)Bn * DD];
__device__ __nv_bfloat16 g_wbT_hi[(size_t)Bn * DD], g_wbT_lo[(size_t)Bn * DD];

// ------------------------------ PTX helpers --------------------------------
__device__ __forceinline__ uint32_t smem_u32(const void* p) {
    uint32_t a;
    asm("{ .reg .u64 t; cvta.to.shared.u64 t, %1; cvt.u32.u64 %0, t; }"
        : "=r"(a) : "l"(p));
    return a;
}

#define LDSM4(r, addr)                                                        \
    asm volatile("ldmatrix.sync.aligned.m8n8.x4.shared.b16 "                  \
                 "{%0,%1,%2,%3}, [%4];"                                       \
                 : "=r"((r)[0]), "=r"((r)[1]), "=r"((r)[2]), "=r"((r)[3])     \
                 : "r"(addr))

#define MMA_BF16(d, a, b)                                                     \
    asm volatile("mma.sync.aligned.m16n8k16.row.col.f32.bf16.bf16.f32 "       \
                 "{%0,%1,%2,%3}, {%4,%5,%6,%7}, {%8,%9}, {%0,%1,%2,%3};"      \
                 : "+f"((d)[0]), "+f"((d)[1]), "+f"((d)[2]), "+f"((d)[3])     \
                 : "r"((a)[0]), "r"((a)[1]), "r"((a)[2]), "r"((a)[3]),        \
                   "r"((b)[0]), "r"((b)[1]))

#define CP_ASYNC16(dst, src)                                                  \
    asm volatile("cp.async.cg.shared.global [%0], [%1], 16;"                  \
                 :: "r"(dst), "l"(src))
#define CP_COMMIT()  asm volatile("cp.async.commit_group;")
#define CP_WAIT1()   asm volatile("cp.async.wait_group 1;")
#define CP_WAIT0()   asm volatile("cp.async.wait_group 0;")

// ===========================================================================
// Tensor-core GEMM: C[M,N] = A[M,K] @ Bt[N,K]^T (+ bias[n]).
// fp32-accurate via bf16 hi/lo split (3 MMA terms).
// 128x128 CTA tile, K-chunk 32 (bf16), 3-stage cp.async pipeline.
// ===========================================================================
namespace {
constexpr int TILE_B      = 128 * 32 * 2;          // 8 KB per bf16 tile
constexpr int STAGE_BYTES = 4 * TILE_B;            // Ahi, Alo, Bhi, Blo
constexpr int STAGES      = 3;
constexpr int GEMM_SMEM   = STAGES * STAGE_BYTES;  // 96 KB
}

__global__ void __launch_bounds__(256) gemm_tc(
    const __nv_bfloat16* __restrict__ Ahi, const __nv_bfloat16* __restrict__ Alo, long sA,
    const __nv_bfloat16* __restrict__ Bhi, const __nv_bfloat16* __restrict__ Blo, long sB,
    const float* __restrict__ bias, long sBias,
    float* __restrict__ Cf,
    __nv_bfloat16* __restrict__ Chi, __nv_bfloat16* __restrict__ Clo,
    long sC, int Ndim, int Kdim)
{
    extern __shared__ char smem[];
    const uint32_t sb = smem_u32(smem);
    const int tid = threadIdx.x;
    const int wid = tid >> 5;
    const int l   = tid & 31;
    const int zb  = blockIdx.z;

    Ahi += (long)zb * sA;  Alo += (long)zb * sA;
    Bhi += (long)zb * sB;  Blo += (long)zb * sB;
    if (bias) bias += (long)zb * sBias;

    const int m0 = blockIdx.y * 128;
    const int n0 = blockIdx.x * 128;
    const int NC = Kdim >> 5;          // chunks of 32 bf16-K

    const int r0i = (tid * 2) >> 2, c40 = (tid * 2) & 3;
    const int r1i = (tid * 2 + 1) >> 2, c41 = (tid * 2 + 1) & 3;
    const __nv_bfloat16* gsrc[4] = {
        Ahi + (long)m0 * Kdim, Alo + (long)m0 * Kdim,
        Bhi + (long)n0 * Kdim, Blo + (long)n0 * Kdim };

    const uint32_t so0 = r0i * 64 + ((c40 ^ ((r0i >> 1) & 3)) << 4);
    const uint32_t so1 = r1i * 64 + ((c41 ^ ((r1i >> 1) & 3)) << 4);

    auto issue_stage = [&](int s, int c) {
        const uint32_t base = sb + s * STAGE_BYTES;
        #pragma unroll
        for (int t = 0; t < 4; t++) {
            CP_ASYNC16(base + t * TILE_B + so0,
                       gsrc[t] + (long)r0i * Kdim + c * 32 + c40 * 8);
            CP_ASYNC16(base + t * TILE_B + so1,
                       gsrc[t] + (long)r1i * Kdim + c * 32 + c41 * 8);
        }
    };

    issue_stage(0, 0); CP_COMMIT();
    issue_stage(1, 1); CP_COMMIT();

    const int wm = wid & 3;
    const int wn = wid >> 2;

    float acc[2][8][4];
    #pragma unroll
    for (int i = 0; i < 2; i++)
        #pragma unroll
        for (int j = 0; j < 8; j++)
            #pragma unroll
            for (int q = 0; q < 4; q++) acc[i][j][q] = 0.f;

    uint32_t aoff[2][2], boff[2][4];
    #pragma unroll
    for (int ks = 0; ks < 2; ks++) {
        #pragma unroll
        for (int i = 0; i < 2; i++) {
            int row = wm * 32 + i * 16 + (l & 15);
            int c4  = ks * 2 + (l >> 4);
            aoff[ks][i] = row * 64 + ((c4 ^ ((row >> 1) & 3)) << 4);
        }
        #pragma unroll
        for (int p = 0; p < 4; p++) {
            int row = wn * 64 + p * 16 + (l & 7) + ((l & 16) >> 1);
            int c4  = ks * 2 + ((l >> 3) & 1);
            boff[ks][p] = row * 64 + ((c4 ^ ((row >> 1) & 3)) << 4);
        }
    }

    for (int c = 0; c < NC; c++) {
        if (c + 1 < NC) { CP_WAIT1(); } else { CP_WAIT0(); }
        __syncthreads();
        if (c + 2 < NC) { issue_stage((c + 2) % STAGES, c + 2); CP_COMMIT(); }

        const uint32_t base = sb + (c % STAGES) * STAGE_BYTES;
        #pragma unroll
        for (int ks = 0; ks < 2; ks++) {
            uint32_t ah[2][4], al[2][4];
            #pragma unroll
            for (int i = 0; i < 2; i++) {
                LDSM4(ah[i], base + aoff[ks][i]);
                LDSM4(al[i], base + TILE_B + aoff[ks][i]);
            }
            uint32_t bh[8][2], bl[8][2];
            #pragma unroll
            for (int p = 0; p < 4; p++) {
                uint32_t rh[4], rl[4];
                LDSM4(rh, base + 2 * TILE_B + boff[ks][p]);
                LDSM4(rl, base + 3 * TILE_B + boff[ks][p]);
                bh[2*p][0] = rh[0]; bh[2*p][1] = rh[1];
                bh[2*p+1][0] = rh[2]; bh[2*p+1][1] = rh[3];
                bl[2*p][0] = rl[0]; bl[2*p][1] = rl[1];
                bl[2*p+1][0] = rl[2]; bl[2*p+1][1] = rl[3];
            }
            #pragma unroll
            for (int i = 0; i < 2; i++)
                #pragma unroll
                for (int j = 0; j < 8; j++) {
                    MMA_BF16(acc[i][j], ah[i], bh[j]);
                    MMA_BF16(acc[i][j], ah[i], bl[j]);
                    MMA_BF16(acc[i][j], al[i], bh[j]);
                }
        }
        __syncthreads();
    }

    const int mr = m0 + wm * 32 + (l >> 2);
    const int nc = n0 + wn * 64 + (l & 3) * 2;
    #pragma unroll
    for (int i = 0; i < 2; i++) {
        #pragma unroll
        for (int j = 0; j < 8; j++) {
            const int rr = mr + i * 16;
            const int cc = nc + j * 8;
            if (Cf) {
                float b0 = bias ? bias[cc] : 0.f;
                float b1 = bias ? bias[cc + 1] : 0.f;
                float2* p0 = (float2*)(Cf + (long)zb * sC + (long)rr * Ndim + cc);
                float2* p1 = (float2*)(Cf + (long)zb * sC + (long)(rr + 8) * Ndim + cc);
                *p0 = make_float2(acc[i][j][0] + b0, acc[i][j][1] + b1);
                *p1 = make_float2(acc[i][j][2] + b0, acc[i][j][3] + b1);
            } else {
                #pragma unroll
                for (int q = 0; q < 4; q++) {
                    float v = acc[i][j][q];
                    int row = rr + (q >> 1) * 8;
                    int col = cc + (q & 1);
                    __nv_bfloat16 h = __float2bfloat16_rn(v);
                    long o = (long)zb * sC + (long)row * Ndim + col;
                    Chi[o] = h;
                    Clo[o] = __float2bfloat16_rn(v - __bfloat162float(h));
                }
            }
        }
    }
}

// ===========================================================================
// small kernels
// ===========================================================================

__global__ void __launch_bounds__(256) split_kernel(
    const float* __restrict__ in, __nv_bfloat16* __restrict__ hi,
    __nv_bfloat16* __restrict__ lo, int n)
{
    int i = (blockIdx.x * 256 + threadIdx.x) * 4;
    if (i >= n) return;
    float4 x = *(const float4*)(in + i);
    float xs[4] = {x.x, x.y, x.z, x.w};
    __nv_bfloat16 h[4], lv[4];
    #pragma unroll
    for (int k = 0; k < 4; k++) {
        h[k] = __float2bfloat16_rn(xs[k]);
        lv[k] = __float2bfloat16_rn(xs[k] - __bfloat162float(h[k]));
    }
    __nv_bfloat162 h01; h01.x = h[0]; h01.y = h[1];
    __nv_bfloat162 h23; h23.x = h[2]; h23.y = h[3];
    __nv_bfloat162 l01; l01.x = lv[0]; l01.y = lv[1];
    __nv_bfloat162 l23; l23.x = lv[2]; l23.y = lv[3];
    *(__nv_bfloat162*)(hi + i)     = h01;
    *(__nv_bfloat162*)(hi + i + 2) = h23;
    *(__nv_bfloat162*)(lo + i)     = l01;
    *(__nv_bfloat162*)(lo + i + 2) = l23;
}

// transpose + split: in [R,C] fp32 -> out [C,R] bf16 hi/lo
__global__ void __launch_bounds__(256) splitT_kernel(
    const float* __restrict__ in, long sIn,
    __nv_bfloat16* __restrict__ hi, __nv_bfloat16* __restrict__ lo, long sOut,
    int R, int C)
{
    __shared__ float t[32][33];
    in += (long)blockIdx.z * sIn;
    hi += (long)blockIdx.z * sOut;
    lo += (long)blockIdx.z * sOut;
    const int c0 = blockIdx.x * 32;
    const int r0 = blockIdx.y * 32;
    const int tx = threadIdx.x, ty = threadIdx.y;
    for (int k = ty; k < 32; k += 8)
        t[k][tx] = in[(long)(r0 + k) * C + c0 + tx];
    __syncthreads();
    for (int k = ty; k < 32; k += 8) {
        float vv = t[tx][k];
        __nv_bfloat16 h = __float2bfloat16_rn(vv);
        long o = (long)(c0 + k) * R + r0 + tx;
        hi[o] = h;
        lo[o] = __float2bfloat16_rn(vv - __bfloat162float(h));
    }
}

// stage 1 column sum: part[b][sl][d] = sum over 256 s-rows of in[b,s,d]
__global__ void __launch_bounds__(256) colsum1_kernel(
    const float* __restrict__ in, float* __restrict__ part)
{
    const int b = blockIdx.z, sl = blockIdx.y;
    const int t = threadIdx.x;
    const int d = blockIdx.x * 128 + (t & 127);
    const int half = t >> 7;
    const float* p = in + (long)b * Ssz * Dd + (long)(sl * 256 + half * 128) * Dd + d;
    float s = 0.f;
    #pragma unroll 8
    for (int r = 0; r < 128; r++) s += p[(long)r * Dd];
    __shared__ float sm[256];
    sm[t] = s; __syncthreads();
    if (t < 128) part[((long)b * 8 + sl) * Dd + d] = sm[t] + sm[t + 128];
}

// stage 2: out[b][d] = sum of 8 partials
__global__ void __launch_bounds__(256) colsum2_kernel(
    const float* __restrict__ part, float* __restrict__ out)
{
    const int b = blockIdx.y;
    const int d = blockIdx.x * 256 + threadIdx.x;
    float s = 0.f;
    #pragma unroll
    for (int k = 0; k < 8; k++) s += part[((long)b * 8 + k) * Dd + d];
    out[b * Dd + d] = s;
}

// cka[b][i] = sum_d Wk[d][i]*ksum[b][d] ; cvb likewise (z selects)
__global__ void __launch_bounds__(256) corr_kernel(
    const float* __restrict__ Wk, const float* __restrict__ Wv,
    const float* __restrict__ ksum, const float* __restrict__ vsum,
    float* __restrict__ cka, float* __restrict__ cvb)
{
    const int b = blockIdx.y;
    const float* W = blockIdx.z ? Wv : Wk;
    const float* s = (blockIdx.z ? vsum : ksum) + b * Dd;
    float* o = (blockIdx.z ? cvb : cka) + b * Dd;
    const int t = threadIdx.x;
    const int i = blockIdx.x * 128 + (t & 127);
    const int half = t >> 7;
    float acc = 0.f;
    #pragma unroll 8
    for (int d = half * 512; d < half * 512 + 512; d++)
        acc += W[(long)d * Dd + i] * s[d];
    __shared__ float sm[256];
    sm[t] = acc; __syncthreads();
    if (t < 128) o[i] = sm[t] + sm[t + 128];
}

// M_{b,h}[i][j] = scale*( sum_d Wk[d,h64+i]*T1[b][d][h64+j] + corrections )
__global__ void __launch_bounds__(256) Mdiag_kernel(
    const float* __restrict__ Wk, const float* __restrict__ T1,
    const float* __restrict__ bk, const float* __restrict__ bv,
    const float* __restrict__ cka, const float* __restrict__ cvb,
    float* __restrict__ Mout)
{
    const int h = blockIdx.x;
    const int b = blockIdx.y;
    const float* Kp = Wk + h * HD;
    const float* Tp = T1 + (long)b * DD + h * HD;

    __shared__ float Kt[32][64];
    __shared__ float Vt[32][64];

    const int tid = threadIdx.x;
    const int ti = tid & 15;
    const int tj = tid >> 4;
    const int lr = tid >> 3;
    const int lc = (tid & 7) * 8;

    float acc[4][4];
    #pragma unroll
    for (int a = 0; a < 4; a++)
        #pragma unroll
        for (int c = 0; c < 4; c++) acc[a][c] = 0.f;

    for (int d0 = 0; d0 < Dd; d0 += 32) {
        const float* kp = Kp + (long)(d0 + lr) * Dd + lc;
        const float* vp = Tp + (long)(d0 + lr) * Dd + lc;
        float4 k0 = *(const float4*)kp;
        float4 k1 = *(const float4*)(kp + 4);
        float4 v0 = *(const float4*)vp;
        float4 v1 = *(const float4*)(vp + 4);
        __syncthreads();
        *(float4*)&Kt[lr][lc]     = k0;
        *(float4*)&Kt[lr][lc + 4] = k1;
        *(float4*)&Vt[lr][lc]     = v0;
        *(float4*)&Vt[lr][lc + 4] = v1;
        __syncthreads();

        #pragma unroll 8
        for (int ss = 0; ss < 32; ss++) {
            float4 ka = *(const float4*)&Kt[ss][ti * 4];
            float4 va = *(const float4*)&Vt[ss][tj * 4];
            float rk[4] = {ka.x, ka.y, ka.z, ka.w};
            float rv[4] = {va.x, va.y, va.z, va.w};
            #pragma unroll
            for (int a = 0; a < 4; a++)
                #pragma unroll
                for (int c = 0; c < 4; c++)
                    acc[a][c] += rk[a] * rv[c];
        }
    }

    const float scale = 0.125f;
    float* Mp = Mout + ((long)(b * Hh + h)) * HD * HD;
    #pragma unroll
    for (int a = 0; a < 4; a++) {
        const int i = ti * 4 + a;
        const float bki  = bk[h * HD + i];
        const float ckai = cka[b * Dd + h * HD + i];
        float4 vo;
        float* vp = &vo.x;
        #pragma unroll
        for (int c = 0; c < 4; c++) {
            const int j = tj * 4 + c;
            float corr = ckai * bv[h * HD + j]
                       + bki * cvb[b * Dd + h * HD + j]
                       + (float)Ssz * bki * bv[h * HD + j];
            vp[c] = scale * (acc[a][c] + corr);
        }
        *(float4*)&Mp[i * HD + tj * 4] = vo;
    }
}

// P_b rows [h*64..h*64+63] = M_{b,h} @ Wo[h*64:h*64+64, :]
__global__ void __launch_bounds__(256) P_kernel(
    const float* __restrict__ Mmat, const float* __restrict__ Wo,
    float* __restrict__ P)
{
    const int nb = blockIdx.x;
    const int h  = blockIdx.y;
    const int b  = blockIdx.z;

    __shared__ float Ms[64][64];
    const float* Mp = Mmat + ((long)(b * Hh + h)) * HD * HD;
    for (int i = threadIdx.x; i < HD * HD; i += 256)
        Ms[i >> 6][i & 63] = Mp[i];
    __syncthreads();

    const int tid  = threadIdx.x;
    const int col  = nb * 128 + (tid & 31) * 4;
    const int row0 = (tid >> 5) * 8;

    float acc[8][4];
    #pragma unroll
    for (int i = 0; i < 8; i++)
        #pragma unroll
        for (int c = 0; c < 4; c++) acc[i][c] = 0.f;

    const float* Wp = Wo + (long)(h * HD) * Dd + col;
    #pragma unroll 8
    for (int j = 0; j < HD; j++) {
        float4 w = *(const float4*)(Wp + (long)j * Dd);
        #pragma unroll
        for (int i = 0; i < 8; i++) {
            float m = Ms[row0 + i][j];
            acc[i][0] += m * w.x;
            acc[i][1] += m * w.y;
            acc[i][2] += m * w.z;
            acc[i][3] += m * w.w;
        }
    }

    float* Pp = P + (long)b * DD + (long)(h * HD) * Dd;
    #pragma unroll
    for (int i = 0; i < 8; i++) {
        float4 vo = make_float4(acc[i][0], acc[i][1], acc[i][2], acc[i][3]);
        *(float4*)(Pp + (long)(row0 + i) * Dd + col) = vo;
    }
}

// tv[b][h*64+j] = sum_i bq[h*64+i] * M[b,h,i,j]
__global__ void __launch_bounds__(64) tvec_kernel(
    const float* __restrict__ M, const float* __restrict__ bq,
    float* __restrict__ tv)
{
    const int h = blockIdx.x, b = blockIdx.y;
    const int j = threadIdx.x;
    const float* Mp = M + ((long)(b * Hh + h)) * HD * HD;
    float acc = 0.f;
    #pragma unroll 8
    for (int i = 0; i < HD; i++) acc += bq[h * HD + i] * Mp[i * HD + j];
    tv[b * Dd + h * HD + j] = acc;
}

// bbig[b][n] = sum_r tv[b][r]*Wo[r][n] + bo[n]
__global__ void __launch_bounds__(256) bbig2_kernel(
    const float* __restrict__ tv, const float* __restrict__ Wo,
    const float* __restrict__ bo, float* __restrict__ bbig)
{
    const int b = blockIdx.y;
    const int t = threadIdx.x;
    const int n = blockIdx.x * 64 + (t & 63);
    const int rs = t >> 6;
    float acc = 0.f;
    #pragma unroll 8
    for (int r = rs * 256; r < rs * 256 + 256; r++)
        acc += tv[b * Dd + r] * Wo[(long)r * Dd + n];
    __shared__ float sm[256];
    sm[t] = acc; __syncthreads();
    if (t < 64)
        bbig[b * Dd + n] = sm[t] + sm[t + 64] + sm[t + 128] + sm[t + 192] + bo[n];
}

// ===========================================================================
extern "C" void kernel_launch(void* const* d_in, const int* in_sizes, int n_in,
                              void* d_out, int out_size)
{
    const float* query = (const float*)d_in[0];
    const float* key   = (const float*)d_in[1];
    const float* value = (const float*)d_in[2];
    const float* Wq    = (const float*)d_in[3];
    const float* bq    = (const float*)d_in[4];
    const float* Wk    = (const float*)d_in[5];
    const float* bk    = (const float*)d_in[6];
    const float* Wv    = (const float*)d_in[7];
    const float* bv    = (const float*)d_in[8];
    const float* Wo    = (const float*)d_in[9];
    const float* bo    = (const float*)d_in[10];
    float* out = (float*)d_out;

    float *pT1, *pM, *pP, *pB, *pTv, *pKs, *pVs, *pKp, *pVp, *pCka, *pCvb;
    cudaGetSymbolAddress((void**)&pT1, g_T1);
    cudaGetSymbolAddress((void**)&pM,  g_M);
    cudaGetSymbolAddress((void**)&pP,  g_P);
    cudaGetSymbolAddress((void**)&pB,  g_bbig);
    cudaGetSymbolAddress((void**)&pTv, g_tv);
    cudaGetSymbolAddress((void**)&pKs, g_ksum);
    cudaGetSymbolAddress((void**)&pVs, g_vsum);
    cudaGetSymbolAddress((void**)&pKp, g_kpart);
    cudaGetSymbolAddress((void**)&pVp, g_vpart);
    cudaGetSymbolAddress((void**)&pCka, g_cka);
    cudaGetSymbolAddress((void**)&pCvb, g_cvb);
    __nv_bfloat16 *qh, *ql, *kth, *ktl, *vth, *vtl, *wqh, *wql, *wvth, *wvtl;
    __nv_bfloat16 *gh, *gl, *pth, *ptl, *wbth, *wbtl;
    cudaGetSymbolAddress((void**)&qh,  g_q_hi);  cudaGetSymbolAddress((void**)&ql,  g_q_lo);
    cudaGetSymbolAddress((void**)&kth, g_kT_hi); cudaGetSymbolAddress((void**)&ktl, g_kT_lo);
    cudaGetSymbolAddress((void**)&vth, g_vT_hi); cudaGetSymbolAddress((void**)&vtl, g_vT_lo);
    cudaGetSymbolAddress((void**)&wqh, g_wq_hi); cudaGetSymbolAddress((void**)&wql, g_wq_lo);
    cudaGetSymbolAddress((void**)&wvth, g_wvT_hi); cudaGetSymbolAddress((void**)&wvtl, g_wvT_lo);
    cudaGetSymbolAddress((void**)&gh,  g_G_hi);  cudaGetSymbolAddress((void**)&gl,  g_G_lo);
    cudaGetSymbolAddress((void**)&pth, g_pT_hi); cudaGetSymbolAddress((void**)&ptl, g_pT_lo);
    cudaGetSymbolAddress((void**)&wbth, g_wbT_hi); cudaGetSymbolAddress((void**)&wbtl, g_wbT_lo);

    cudaFuncSetAttribute(gemm_tc, cudaFuncAttributeMaxDynamicSharedMemorySize, GEMM_SMEM);

    const long sBatch = (long)Ssz * Dd;   // 2M elements per batch

    // 1-3) transposed splits of key/value (batched), query split
    split_kernel<<<GME / 1024, 256>>>(query, qh, ql, GME);
    splitT_kernel<<<dim3(Dd / 32, Ssz / 32, Bn), dim3(32, 8)>>>(
        key, sBatch, kth, ktl, sBatch, Ssz, Dd);
    splitT_kernel<<<dim3(Dd / 32, Ssz / 32, Bn), dim3(32, 8)>>>(
        value, sBatch, vth, vtl, sBatch, Ssz, Dd);

    // 4) G_b = key_b^T @ value_b  [1024,1024], K=2048  (bf16 hi/lo out)
    //    (4th launch -> gets the ncu profile)
    gemm_tc<<<dim3(Dd / 128, Dd / 128, Bn), 256, GEMM_SMEM>>>(
        kth, ktl, sBatch, vth, vtl, sBatch, nullptr, 0,
        nullptr, gh, gl, (long)DD, Dd, Ssz);

    // 5-6) weight splits
    split_kernel<<<DD / 1024, 256>>>(Wq, wqh, wql, DD);
    splitT_kernel<<<dim3(32, 32, 1), dim3(32, 8)>>>(Wv, 0, wvth, wvtl, 0, Dd, Dd);

    // 7-11) column sums + bias-correction matvecs
    colsum1_kernel<<<dim3(Dd / 128, 8, Bn), 256>>>(key, pKp);
    colsum1_kernel<<<dim3(Dd / 128, 8, Bn), 256>>>(value, pVp);
    colsum2_kernel<<<dim3(Dd / 256, Bn), 256>>>(pKp, pKs);
    colsum2_kernel<<<dim3(Dd / 256, Bn), 256>>>(pVp, pVs);
    corr_kernel<<<dim3(Dd / 128, Bn, 2), 256>>>(Wk, Wv, pKs, pVs, pCka, pCvb);

    // 12) T1_b = G_b @ Wv  (fp32 out)
    gemm_tc<<<dim3(Dd / 128, Dd / 128, Bn), 256, GEMM_SMEM>>>(
        gh, gl, (long)DD, wvth, wvtl, 0, nullptr, 0,
        pT1, nullptr, nullptr, (long)DD, Dd, Dd);

    // 13) M diag blocks + bias corrections
    Mdiag_kernel<<<dim3(Hh, Bn), 256>>>(Wk, pT1, bk, bv, pCka, pCvb, pM);

    // 14-16) P, t-vector, bbig
    P_kernel<<<dim3(Dd / 128, Hh, Bn), 256>>>(pM, Wo, pP);
    tvec_kernel<<<dim3(Hh, Bn), 64>>>(pM, bq, pTv);
    bbig2_kernel<<<dim3(Dd / 64, Bn), 256>>>(pTv, Wo, bo, pB);

    // 17) P^T split
    splitT_kernel<<<dim3(32, 32, Bn), dim3(32, 8)>>>(
        pP, (long)DD, pth, ptl, (long)DD, Dd, Dd);

    // 18) WbigT_b = P_b^T @ Wq^T  (bf16 hi/lo out)
    gemm_tc<<<dim3(Dd / 128, Dd / 128, Bn), 256, GEMM_SMEM>>>(
        pth, ptl, (long)DD, wqh, wql, 0, nullptr, 0,
        nullptr, wbth, wbtl, (long)DD, Dd, Dd);

    // 19) out_b = query_b @ Wbig_b + bbig_b  (fp32 out)
    gemm_tc<<<dim3(Dd / 128, Ssz / 128, Bn), 256, GEMM_SMEM>>>(
        qh, ql, sBatch, wbth, wbtl, (long)DD, pB, Dd,
        out, nullptr, nullptr, sBatch, Dd, Dd);
}

// round 5
// speedup vs baseline: 2.1855x; 1.0978x over previous
#include <cuda_runtime.h>
#include <cuda_bf16.h>
#include <cstdint>

// ===========================================================================
// MHA WITHOUT softmax == linear operator, fully re-associated:
//   G_b  = key_b^T @ value_b                         (mma.sync bf16-split)
//   T1_b = G_b @ Wv                                  (mma.sync bf16-split)
//   M_{b,h} = scale*( diag64(Wk^T T1)_h + rank-1 bias corrections )
//   P_b = stack_h(M_{b,h} @ Wo_h)                    (SIMT, tiny)
//   WbigT_b = P_b^T @ Wq^T                           (mma.sync bf16-split)
//   bbig_b = (bq.M)^T @ Wo + bo                      (SIMT, tiny)
//   out_b = query_b @ Wbig_b + bbig_b                (mma.sync bf16-split)
// fp32 accuracy via bf16 hi/lo split: A*B ~= Ah*Bh + Ah*Bl + Al*Bh
// R5: __launch_bounds__(256,2) + short-lived B fragments -> 2 CTAs/SM.
// ===========================================================================

namespace {
constexpr int Bn  = 4;
constexpr int Ssz = 2048;
constexpr int Dd  = 1024;
constexpr int Hh  = 16;
constexpr int HD  = 64;
constexpr int GME = Bn * Ssz * Dd;   // 8M elements
constexpr int DD  = Dd * Dd;         // 1M
}

// ------------------------- scratch (device globals) ------------------------
__device__ float g_T1[(size_t)Bn * DD];
__device__ float g_M[Bn * Hh * HD * HD];
__device__ float g_P[(size_t)Bn * DD];
__device__ float g_bbig[Bn * Dd];
__device__ float g_tv[Bn * Dd];
__device__ float g_ksum[Bn * Dd], g_vsum[Bn * Dd];
__device__ float g_kpart[Bn * 8 * Dd], g_vpart[Bn * 8 * Dd];
__device__ float g_cka[Bn * Dd], g_cvb[Bn * Dd];

__device__ __nv_bfloat16 g_q_hi[GME],  g_q_lo[GME];
__device__ __nv_bfloat16 g_kT_hi[GME], g_kT_lo[GME];
__device__ __nv_bfloat16 g_vT_hi[GME], g_vT_lo[GME];
__device__ __nv_bfloat16 g_wq_hi[DD],  g_wq_lo[DD];
__device__ __nv_bfloat16 g_wvT_hi[DD], g_wvT_lo[DD];
__device__ __nv_bfloat16 g_G_hi[(size_t)Bn * DD], g_G_lo[(size_t)Bn * DD];
__device__ __nv_bfloat16 g_pT_hi[(size_t)Bn * DD], g_pT_lo[(size_t)Bn * DD];
__device__ __nv_bfloat16 g_wbT_hi[(size_t)Bn * DD], g_wbT_lo[(size_t)Bn * DD];

// ------------------------------ PTX helpers --------------------------------
__device__ __forceinline__ uint32_t smem_u32(const void* p) {
    uint32_t a;
    asm("{ .reg .u64 t; cvta.to.shared.u64 t, %1; cvt.u32.u64 %0, t; }"
        : "=r"(a) : "l"(p));
    return a;
}

#define LDSM4(r, addr)                                                        \
    asm volatile("ldmatrix.sync.aligned.m8n8.x4.shared.b16 "                  \
                 "{%0,%1,%2,%3}, [%4];"                                       \
                 : "=r"((r)[0]), "=r"((r)[1]), "=r"((r)[2]), "=r"((r)[3])     \
                 : "r"(addr))

#define MMA_BF16(d, a, b)                                                     \
    asm volatile("mma.sync.aligned.m16n8k16.row.col.f32.bf16.bf16.f32 "       \
                 "{%0,%1,%2,%3}, {%4,%5,%6,%7}, {%8,%9}, {%0,%1,%2,%3};"      \
                 : "+f"((d)[0]), "+f"((d)[1]), "+f"((d)[2]), "+f"((d)[3])     \
                 : "r"((a)[0]), "r"((a)[1]), "r"((a)[2]), "r"((a)[3]),        \
                   "r"((b)[0]), "r"((b)[1]))

#define CP_ASYNC16(dst, src)                                                  \
    asm volatile("cp.async.cg.shared.global [%0], [%1], 16;"                  \
                 :: "r"(dst), "l"(src))
#define CP_COMMIT()  asm volatile("cp.async.commit_group;")
#define CP_WAIT1()   asm volatile("cp.async.wait_group 1;")
#define CP_WAIT0()   asm volatile("cp.async.wait_group 0;")

// ===========================================================================
// Tensor-core GEMM: C[M,N] = A[M,K] @ Bt[N,K]^T (+ bias[n]).
// fp32-accurate via bf16 hi/lo split (3 MMA terms).
// 128x128 CTA tile, K-chunk 32 (bf16), 3-stage cp.async pipeline.
// R5: 2 CTAs/SM (reg-capped), B fragments consumed immediately after LDSM.
// ===========================================================================
namespace {
constexpr int TILE_B      = 128 * 32 * 2;          // 8 KB per bf16 tile
constexpr int STAGE_BYTES = 4 * TILE_B;            // Ahi, Alo, Bhi, Blo
constexpr int STAGES      = 3;
constexpr int GEMM_SMEM   = STAGES * STAGE_BYTES;  // 96 KB
}

__global__ void __launch_bounds__(256, 2) gemm_tc(
    const __nv_bfloat16* __restrict__ Ahi, const __nv_bfloat16* __restrict__ Alo, long sA,
    const __nv_bfloat16* __restrict__ Bhi, const __nv_bfloat16* __restrict__ Blo, long sB,
    const float* __restrict__ bias, long sBias,
    float* __restrict__ Cf,
    __nv_bfloat16* __restrict__ Chi, __nv_bfloat16* __restrict__ Clo,
    long sC, int Ndim, int Kdim)
{
    extern __shared__ char smem[];
    const uint32_t sb = smem_u32(smem);
    const int tid = threadIdx.x;
    const int wid = tid >> 5;
    const int l   = tid & 31;
    const int zb  = blockIdx.z;

    Ahi += (long)zb * sA;  Alo += (long)zb * sA;
    Bhi += (long)zb * sB;  Blo += (long)zb * sB;
    if (bias) bias += (long)zb * sBias;

    const int m0 = blockIdx.y * 128;
    const int n0 = blockIdx.x * 128;
    const int NC = Kdim >> 5;          // chunks of 32 bf16-K

    const int r0i = (tid * 2) >> 2, c40 = (tid * 2) & 3;
    const int r1i = (tid * 2 + 1) >> 2, c41 = (tid * 2 + 1) & 3;
    const __nv_bfloat16* gsrc[4] = {
        Ahi + (long)m0 * Kdim, Alo + (long)m0 * Kdim,
        Bhi + (long)n0 * Kdim, Blo + (long)n0 * Kdim };

    const uint32_t so0 = r0i * 64 + ((c40 ^ ((r0i >> 1) & 3)) << 4);
    const uint32_t so1 = r1i * 64 + ((c41 ^ ((r1i >> 1) & 3)) << 4);

    auto issue_stage = [&](int s, int c) {
        const uint32_t base = sb + s * STAGE_BYTES;
        #pragma unroll
        for (int t = 0; t < 4; t++) {
            CP_ASYNC16(base + t * TILE_B + so0,
                       gsrc[t] + (long)r0i * Kdim + c * 32 + c40 * 8);
            CP_ASYNC16(base + t * TILE_B + so1,
                       gsrc[t] + (long)r1i * Kdim + c * 32 + c41 * 8);
        }
    };

    issue_stage(0, 0); CP_COMMIT();
    issue_stage(1, 1); CP_COMMIT();

    const int wm = wid & 3;
    const int wn = wid >> 2;

    float acc[2][8][4];
    #pragma unroll
    for (int i = 0; i < 2; i++)
        #pragma unroll
        for (int j = 0; j < 8; j++)
            #pragma unroll
            for (int q = 0; q < 4; q++) acc[i][j][q] = 0.f;

    uint32_t aoff[2][2], boff[2][4];
    #pragma unroll
    for (int ks = 0; ks < 2; ks++) {
        #pragma unroll
        for (int i = 0; i < 2; i++) {
            int row = wm * 32 + i * 16 + (l & 15);
            int c4  = ks * 2 + (l >> 4);
            aoff[ks][i] = row * 64 + ((c4 ^ ((row >> 1) & 3)) << 4);
        }
        #pragma unroll
        for (int p = 0; p < 4; p++) {
            int row = wn * 64 + p * 16 + (l & 7) + ((l & 16) >> 1);
            int c4  = ks * 2 + ((l >> 3) & 1);
            boff[ks][p] = row * 64 + ((c4 ^ ((row >> 1) & 3)) << 4);
        }
    }

    for (int c = 0; c < NC; c++) {
        if (c + 1 < NC) { CP_WAIT1(); } else { CP_WAIT0(); }
        __syncthreads();
        if (c + 2 < NC) { issue_stage((c + 2) % STAGES, c + 2); CP_COMMIT(); }

        const uint32_t base = sb + (c % STAGES) * STAGE_BYTES;
        #pragma unroll
        for (int ks = 0; ks < 2; ks++) {
            uint32_t ah[2][4], al[2][4];
            #pragma unroll
            for (int i = 0; i < 2; i++) {
                LDSM4(ah[i], base + aoff[ks][i]);
                LDSM4(al[i], base + TILE_B + aoff[ks][i]);
            }
            // B fragments: load one 16-col group, consume immediately (short
            // live range -> fits 128 regs -> 2 CTAs/SM)
            #pragma unroll
            for (int p = 0; p < 4; p++) {
                uint32_t rh[4], rl[4];
                LDSM4(rh, base + 2 * TILE_B + boff[ks][p]);
                LDSM4(rl, base + 3 * TILE_B + boff[ks][p]);
                #pragma unroll
                for (int i = 0; i < 2; i++) {
                    MMA_BF16(acc[i][2*p],     ah[i], rh);
                    MMA_BF16(acc[i][2*p],     ah[i], rl);
                    MMA_BF16(acc[i][2*p],     al[i], rh);
                    MMA_BF16(acc[i][2*p + 1], ah[i], rh + 2);
                    MMA_BF16(acc[i][2*p + 1], ah[i], rl + 2);
                    MMA_BF16(acc[i][2*p + 1], al[i], rh + 2);
                }
            }
        }
        __syncthreads();
    }

    const int mr = m0 + wm * 32 + (l >> 2);
    const int nc = n0 + wn * 64 + (l & 3) * 2;
    #pragma unroll
    for (int i = 0; i < 2; i++) {
        #pragma unroll
        for (int j = 0; j < 8; j++) {
            const int rr = mr + i * 16;
            const int cc = nc + j * 8;
            if (Cf) {
                float b0 = bias ? bias[cc] : 0.f;
                float b1 = bias ? bias[cc + 1] : 0.f;
                float2* p0 = (float2*)(Cf + (long)zb * sC + (long)rr * Ndim + cc);
                float2* p1 = (float2*)(Cf + (long)zb * sC + (long)(rr + 8) * Ndim + cc);
                *p0 = make_float2(acc[i][j][0] + b0, acc[i][j][1] + b1);
                *p1 = make_float2(acc[i][j][2] + b0, acc[i][j][3] + b1);
            } else {
                #pragma unroll
                for (int q = 0; q < 4; q++) {
                    float v = acc[i][j][q];
                    int row = rr + (q >> 1) * 8;
                    int col = cc + (q & 1);
                    __nv_bfloat16 h = __float2bfloat16_rn(v);
                    long o = (long)zb * sC + (long)row * Ndim + col;
                    Chi[o] = h;
                    Clo[o] = __float2bfloat16_rn(v - __bfloat162float(h));
                }
            }
        }
    }
}

// ===========================================================================
// small kernels
// ===========================================================================

__global__ void __launch_bounds__(256) split_kernel(
    const float* __restrict__ in, __nv_bfloat16* __restrict__ hi,
    __nv_bfloat16* __restrict__ lo, int n)
{
    int i = (blockIdx.x * 256 + threadIdx.x) * 4;
    if (i >= n) return;
    float4 x = *(const float4*)(in + i);
    float xs[4] = {x.x, x.y, x.z, x.w};
    __nv_bfloat16 h[4], lv[4];
    #pragma unroll
    for (int k = 0; k < 4; k++) {
        h[k] = __float2bfloat16_rn(xs[k]);
        lv[k] = __float2bfloat16_rn(xs[k] - __bfloat162float(h[k]));
    }
    __nv_bfloat162 h01; h01.x = h[0]; h01.y = h[1];
    __nv_bfloat162 h23; h23.x = h[2]; h23.y = h[3];
    __nv_bfloat162 l01; l01.x = lv[0]; l01.y = lv[1];
    __nv_bfloat162 l23; l23.x = lv[2]; l23.y = lv[3];
    *(__nv_bfloat162*)(hi + i)     = h01;
    *(__nv_bfloat162*)(hi + i + 2) = h23;
    *(__nv_bfloat162*)(lo + i)     = l01;
    *(__nv_bfloat162*)(lo + i + 2) = l23;
}

// transpose + split: in [R,C] fp32 -> out [C,R] bf16 hi/lo
__global__ void __launch_bounds__(256) splitT_kernel(
    const float* __restrict__ in, long sIn,
    __nv_bfloat16* __restrict__ hi, __nv_bfloat16* __restrict__ lo, long sOut,
    int R, int C)
{
    __shared__ float t[32][33];
    in += (long)blockIdx.z * sIn;
    hi += (long)blockIdx.z * sOut;
    lo += (long)blockIdx.z * sOut;
    const int c0 = blockIdx.x * 32;
    const int r0 = blockIdx.y * 32;
    const int tx = threadIdx.x, ty = threadIdx.y;
    for (int k = ty; k < 32; k += 8)
        t[k][tx] = in[(long)(r0 + k) * C + c0 + tx];
    __syncthreads();
    for (int k = ty; k < 32; k += 8) {
        float vv = t[tx][k];
        __nv_bfloat16 h = __float2bfloat16_rn(vv);
        long o = (long)(c0 + k) * R + r0 + tx;
        hi[o] = h;
        lo[o] = __float2bfloat16_rn(vv - __bfloat162float(h));
    }
}

// stage 1 column sum: part[b][sl][d] = sum over 256 s-rows of in[b,s,d]
__global__ void __launch_bounds__(256) colsum1_kernel(
    const float* __restrict__ in, float* __restrict__ part)
{
    const int b = blockIdx.z, sl = blockIdx.y;
    const int t = threadIdx.x;
    const int d = blockIdx.x * 128 + (t & 127);
    const int half = t >> 7;
    const float* p = in + (long)b * Ssz * Dd + (long)(sl * 256 + half * 128) * Dd + d;
    float s = 0.f;
    #pragma unroll 8
    for (int r = 0; r < 128; r++) s += p[(long)r * Dd];
    __shared__ float sm[256];
    sm[t] = s; __syncthreads();
    if (t < 128) part[((long)b * 8 + sl) * Dd + d] = sm[t] + sm[t + 128];
}

__global__ void __launch_bounds__(256) colsum2_kernel(
    const float* __restrict__ part, float* __restrict__ out)
{
    const int b = blockIdx.y;
    const int d = blockIdx.x * 256 + threadIdx.x;
    float s = 0.f;
    #pragma unroll
    for (int k = 0; k < 8; k++) s += part[((long)b * 8 + k) * Dd + d];
    out[b * Dd + d] = s;
}

// cka[b][i] = sum_d Wk[d][i]*ksum[b][d] ; cvb likewise (z selects)
__global__ void __launch_bounds__(256) corr_kernel(
    const float* __restrict__ Wk, const float* __restrict__ Wv,
    const float* __restrict__ ksum, const float* __restrict__ vsum,
    float* __restrict__ cka, float* __restrict__ cvb)
{
    const int b = blockIdx.y;
    const float* W = blockIdx.z ? Wv : Wk;
    const float* s = (blockIdx.z ? vsum : ksum) + b * Dd;
    float* o = (blockIdx.z ? cvb : cka) + b * Dd;
    const int t = threadIdx.x;
    const int i = blockIdx.x * 128 + (t & 127);
    const int half = t >> 7;
    float acc = 0.f;
    #pragma unroll 8
    for (int d = half * 512; d < half * 512 + 512; d++)
        acc += W[(long)d * Dd + i] * s[d];
    __shared__ float sm[256];
    sm[t] = acc; __syncthreads();
    if (t < 128) o[i] = sm[t] + sm[t + 128];
}

// M_{b,h}[i][j] = scale*( sum_d Wk[d,h64+i]*T1[b][d][h64+j] + corrections )
__global__ void __launch_bounds__(256) Mdiag_kernel(
    const float* __restrict__ Wk, const float* __restrict__ T1,
    const float* __restrict__ bk, const float* __restrict__ bv,
    const float* __restrict__ cka, const float* __restrict__ cvb,
    float* __restrict__ Mout)
{
    const int h = blockIdx.x;
    const int b = blockIdx.y;
    const float* Kp = Wk + h * HD;
    const float* Tp = T1 + (long)b * DD + h * HD;

    __shared__ float Kt[32][64];
    __shared__ float Vt[32][64];

    const int tid = threadIdx.x;
    const int ti = tid & 15;
    const int tj = tid >> 4;
    const int lr = tid >> 3;
    const int lc = (tid & 7) * 8;

    float acc[4][4];
    #pragma unroll
    for (int a = 0; a < 4; a++)
        #pragma unroll
        for (int c = 0; c < 4; c++) acc[a][c] = 0.f;

    for (int d0 = 0; d0 < Dd; d0 += 32) {
        const float* kp = Kp + (long)(d0 + lr) * Dd + lc;
        const float* vp = Tp + (long)(d0 + lr) * Dd + lc;
        float4 k0 = *(const float4*)kp;
        float4 k1 = *(const float4*)(kp + 4);
        float4 v0 = *(const float4*)vp;
        float4 v1 = *(const float4*)(vp + 4);
        __syncthreads();
        *(float4*)&Kt[lr][lc]     = k0;
        *(float4*)&Kt[lr][lc + 4] = k1;
        *(float4*)&Vt[lr][lc]     = v0;
        *(float4*)&Vt[lr][lc + 4] = v1;
        __syncthreads();

        #pragma unroll 8
        for (int ss = 0; ss < 32; ss++) {
            float4 ka = *(const float4*)&Kt[ss][ti * 4];
            float4 va = *(const float4*)&Vt[ss][tj * 4];
            float rk[4] = {ka.x, ka.y, ka.z, ka.w};
            float rv[4] = {va.x, va.y, va.z, va.w};
            #pragma unroll
            for (int a = 0; a < 4; a++)
                #pragma unroll
                for (int c = 0; c < 4; c++)
                    acc[a][c] += rk[a] * rv[c];
        }
    }

    const float scale = 0.125f;
    float* Mp = Mout + ((long)(b * Hh + h)) * HD * HD;
    #pragma unroll
    for (int a = 0; a < 4; a++) {
        const int i = ti * 4 + a;
        const float bki  = bk[h * HD + i];
        const float ckai = cka[b * Dd + h * HD + i];
        float4 vo;
        float* vp = &vo.x;
        #pragma unroll
        for (int c = 0; c < 4; c++) {
            const int j = tj * 4 + c;
            float corr = ckai * bv[h * HD + j]
                       + bki * cvb[b * Dd + h * HD + j]
                       + (float)Ssz * bki * bv[h * HD + j];
            vp[c] = scale * (acc[a][c] + corr);
        }
        *(float4*)&Mp[i * HD + tj * 4] = vo;
    }
}

// P_b rows [h*64..h*64+63] = M_{b,h} @ Wo[h*64:h*64+64, :]
__global__ void __launch_bounds__(256) P_kernel(
    const float* __restrict__ Mmat, const float* __restrict__ Wo,
    float* __restrict__ P)
{
    const int nb = blockIdx.x;
    const int h  = blockIdx.y;
    const int b  = blockIdx.z;

    __shared__ float Ms[64][64];
    const float* Mp = Mmat + ((long)(b * Hh + h)) * HD * HD;
    for (int i = threadIdx.x; i < HD * HD; i += 256)
        Ms[i >> 6][i & 63] = Mp[i];
    __syncthreads();

    const int tid  = threadIdx.x;
    const int col  = nb * 128 + (tid & 31) * 4;
    const int row0 = (tid >> 5) * 8;

    float acc[8][4];
    #pragma unroll
    for (int i = 0; i < 8; i++)
        #pragma unroll
        for (int c = 0; c < 4; c++) acc[i][c] = 0.f;

    const float* Wp = Wo + (long)(h * HD) * Dd + col;
    #pragma unroll 8
    for (int j = 0; j < HD; j++) {
        float4 w = *(const float4*)(Wp + (long)j * Dd);
        #pragma unroll
        for (int i = 0; i < 8; i++) {
            float m = Ms[row0 + i][j];
            acc[i][0] += m * w.x;
            acc[i][1] += m * w.y;
            acc[i][2] += m * w.z;
            acc[i][3] += m * w.w;
        }
    }

    float* Pp = P + (long)b * DD + (long)(h * HD) * Dd;
    #pragma unroll
    for (int i = 0; i < 8; i++) {
        float4 vo = make_float4(acc[i][0], acc[i][1], acc[i][2], acc[i][3]);
        *(float4*)(Pp + (long)(row0 + i) * Dd + col) = vo;
    }
}

// tv[b][h*64+j] = sum_i bq[h*64+i] * M[b,h,i,j]
__global__ void __launch_bounds__(64) tvec_kernel(
    const float* __restrict__ M, const float* __restrict__ bq,
    float* __restrict__ tv)
{
    const int h = blockIdx.x, b = blockIdx.y;
    const int j = threadIdx.x;
    const float* Mp = M + ((long)(b * Hh + h)) * HD * HD;
    float acc = 0.f;
    #pragma unroll 8
    for (int i = 0; i < HD; i++) acc += bq[h * HD + i] * Mp[i * HD + j];
    tv[b * Dd + h * HD + j] = acc;
}

// bbig[b][n] = sum_r tv[b][r]*Wo[r][n] + bo[n]
__global__ void __launch_bounds__(256) bbig2_kernel(
    const float* __restrict__ tv, const float* __restrict__ Wo,
    const float* __restrict__ bo, float* __restrict__ bbig)
{
    const int b = blockIdx.y;
    const int t = threadIdx.x;
    const int n = blockIdx.x * 64 + (t & 63);
    const int rs = t >> 6;
    float acc = 0.f;
    #pragma unroll 8
    for (int r = rs * 256; r < rs * 256 + 256; r++)
        acc += tv[b * Dd + r] * Wo[(long)r * Dd + n];
    __shared__ float sm[256];
    sm[t] = acc; __syncthreads();
    if (t < 64)
        bbig[b * Dd + n] = sm[t] + sm[t + 64] + sm[t + 128] + sm[t + 192] + bo[n];
}

// ===========================================================================
extern "C" void kernel_launch(void* const* d_in, const int* in_sizes, int n_in,
                              void* d_out, int out_size)
{
    const float* query = (const float*)d_in[0];
    const float* key   = (const float*)d_in[1];
    const float* value = (const float*)d_in[2];
    const float* Wq    = (const float*)d_in[3];
    const float* bq    = (const float*)d_in[4];
    const float* Wk    = (const float*)d_in[5];
    const float* bk    = (const float*)d_in[6];
    const float* Wv    = (const float*)d_in[7];
    const float* bv    = (const float*)d_in[8];
    const float* Wo    = (const float*)d_in[9];
    const float* bo    = (const float*)d_in[10];
    float* out = (float*)d_out;

    float *pT1, *pM, *pP, *pB, *pTv, *pKs, *pVs, *pKp, *pVp, *pCka, *pCvb;
    cudaGetSymbolAddress((void**)&pT1, g_T1);
    cudaGetSymbolAddress((void**)&pM,  g_M);
    cudaGetSymbolAddress((void**)&pP,  g_P);
    cudaGetSymbolAddress((void**)&pB,  g_bbig);
    cudaGetSymbolAddress((void**)&pTv, g_tv);
    cudaGetSymbolAddress((void**)&pKs, g_ksum);
    cudaGetSymbolAddress((void**)&pVs, g_vsum);
    cudaGetSymbolAddress((void**)&pKp, g_kpart);
    cudaGetSymbolAddress((void**)&pVp, g_vpart);
    cudaGetSymbolAddress((void**)&pCka, g_cka);
    cudaGetSymbolAddress((void**)&pCvb, g_cvb);
    __nv_bfloat16 *qh, *ql, *kth, *ktl, *vth, *vtl, *wqh, *wql, *wvth, *wvtl;
    __nv_bfloat16 *gh, *gl, *pth, *ptl, *wbth, *wbtl;
    cudaGetSymbolAddress((void**)&qh,  g_q_hi);  cudaGetSymbolAddress((void**)&ql,  g_q_lo);
    cudaGetSymbolAddress((void**)&kth, g_kT_hi); cudaGetSymbolAddress((void**)&ktl, g_kT_lo);
    cudaGetSymbolAddress((void**)&vth, g_vT_hi); cudaGetSymbolAddress((void**)&vtl, g_vT_lo);
    cudaGetSymbolAddress((void**)&wqh, g_wq_hi); cudaGetSymbolAddress((void**)&wql, g_wq_lo);
    cudaGetSymbolAddress((void**)&wvth, g_wvT_hi); cudaGetSymbolAddress((void**)&wvtl, g_wvT_lo);
    cudaGetSymbolAddress((void**)&gh,  g_G_hi);  cudaGetSymbolAddress((void**)&gl,  g_G_lo);
    cudaGetSymbolAddress((void**)&pth, g_pT_hi); cudaGetSymbolAddress((void**)&ptl, g_pT_lo);
    cudaGetSymbolAddress((void**)&wbth, g_wbT_hi); cudaGetSymbolAddress((void**)&wbtl, g_wbT_lo);

    cudaFuncSetAttribute(gemm_tc, cudaFuncAttributeMaxDynamicSharedMemorySize, GEMM_SMEM);

    const long sBatch = (long)Ssz * Dd;

    // 1-3) transposed splits of key/value (batched), query split
    split_kernel<<<GME / 1024, 256>>>(query, qh, ql, GME);
    splitT_kernel<<<dim3(Dd / 32, Ssz / 32, Bn), dim3(32, 8)>>>(
        key, sBatch, kth, ktl, sBatch, Ssz, Dd);
    splitT_kernel<<<dim3(Dd / 32, Ssz / 32, Bn), dim3(32, 8)>>>(
        value, sBatch, vth, vtl, sBatch, Ssz, Dd);

    // 4) G_b = key_b^T @ value_b  (4th launch -> ncu profile)
    gemm_tc<<<dim3(Dd / 128, Dd / 128, Bn), 256, GEMM_SMEM>>>(
        kth, ktl, sBatch, vth, vtl, sBatch, nullptr, 0,
        nullptr, gh, gl, (long)DD, Dd, Ssz);

    // 5-6) weight splits
    split_kernel<<<DD / 1024, 256>>>(Wq, wqh, wql, DD);
    splitT_kernel<<<dim3(32, 32, 1), dim3(32, 8)>>>(Wv, 0, wvth, wvtl, 0, Dd, Dd);

    // 7-11) column sums + bias-correction matvecs
    colsum1_kernel<<<dim3(Dd / 128, 8, Bn), 256>>>(key, pKp);
    colsum1_kernel<<<dim3(Dd / 128, 8, Bn), 256>>>(value, pVp);
    colsum2_kernel<<<dim3(Dd / 256, Bn), 256>>>(pKp, pKs);
    colsum2_kernel<<<dim3(Dd / 256, Bn), 256>>>(pVp, pVs);
    corr_kernel<<<dim3(Dd / 128, Bn, 2), 256>>>(Wk, Wv, pKs, pVs, pCka, pCvb);

    // 12) T1_b = G_b @ Wv
    gemm_tc<<<dim3(Dd / 128, Dd / 128, Bn), 256, GEMM_SMEM>>>(
        gh, gl, (long)DD, wvth, wvtl, 0, nullptr, 0,
        pT1, nullptr, nullptr, (long)DD, Dd, Dd);

    // 13) M diag blocks + bias corrections
    Mdiag_kernel<<<dim3(Hh, Bn), 256>>>(Wk, pT1, bk, bv, pCka, pCvb, pM);

    // 14-16) P, t-vector, bbig
    P_kernel<<<dim3(Dd / 128, Hh, Bn), 256>>>(pM, Wo, pP);
    tvec_kernel<<<dim3(Hh, Bn), 64>>>(pM, bq, pTv);
    bbig2_kernel<<<dim3(Dd / 64, Bn), 256>>>(pTv, Wo, bo, pB);

    // 17) P^T split
    splitT_kernel<<<dim3(32, 32, Bn), dim3(32, 8)>>>(
        pP, (long)DD, pth, ptl, (long)DD, Dd, Dd);

    // 18) WbigT_b = P_b^T @ Wq^T
    gemm_tc<<<dim3(Dd / 128, Dd / 128, Bn), 256, GEMM_SMEM>>>(
        pth, ptl, (long)DD, wqh, wql, 0, nullptr, 0,
        nullptr, wbth, wbtl, (long)DD, Dd, Dd);

    // 19) out_b = query_b @ Wbig_b + bbig_b
    gemm_tc<<<dim3(Dd / 128, Ssz / 128, Bn), 256, GEMM_SMEM>>>(
        qh, ql, sBatch, wbth, wbtl, (long)DD, pB, Dd,
        out, nullptr, nullptr, sBatch, Dd, Dd);
}

// round 6
// speedup vs baseline: 2.3651x; 1.0822x over previous
#include <cuda_runtime.h>
#include <cuda_bf16.h>
#include <cstdint>

// ===========================================================================
// MHA WITHOUT softmax == linear operator, fully re-associated:
//   G_b  = key_b^T @ value_b                         (mma.sync bf16-split)
//   T1_b = G_b @ Wv                                  (mma.sync bf16-split)
//   M_{b,h} = scale*( diag64(Wk^T T1)_h + rank-1 bias corrections )
//   PT_b = (stack_h(M_{b,h} @ Wo_h))^T               (SIMT, tiny, fused split)
//   WbigT_b = P_b^T @ Wq^T                           (mma.sync bf16-split)
//   bbig_b = (bq.M)^T @ Wo + bo                      (SIMT, tiny)
//   out_b = query_b @ Wbig_b + bbig_b                (mma.sync bf16-split)
// R6: B-fragment double buffering, single sync/chunk, colsum fused into
//     splitT, P transpose+split fused into P_kernel.
// ===========================================================================

namespace {
constexpr int Bn  = 4;
constexpr int Ssz = 2048;
constexpr int Dd  = 1024;
constexpr int Hh  = 16;
constexpr int HD  = 64;
constexpr int GME = Bn * Ssz * Dd;
constexpr int DD  = Dd * Dd;
}

// ------------------------- scratch (device globals) ------------------------
__device__ float g_T1[(size_t)Bn * DD];
__device__ float g_M[Bn * Hh * HD * HD];
__device__ float g_bbig[Bn * Dd];
__device__ float g_tv[Bn * Dd];
__device__ float g_ksum[Bn * Dd], g_vsum[Bn * Dd];
__device__ float g_kpart[(size_t)Bn * 64 * Dd], g_vpart[(size_t)Bn * 64 * Dd];
__device__ float g_cka[Bn * Dd], g_cvb[Bn * Dd];

__device__ __nv_bfloat16 g_q_hi[GME],  g_q_lo[GME];
__device__ __nv_bfloat16 g_kT_hi[GME], g_kT_lo[GME];
__device__ __nv_bfloat16 g_vT_hi[GME], g_vT_lo[GME];
__device__ __nv_bfloat16 g_wq_hi[DD],  g_wq_lo[DD];
__device__ __nv_bfloat16 g_wvT_hi[DD], g_wvT_lo[DD];
__device__ __nv_bfloat16 g_G_hi[(size_t)Bn * DD], g_G_lo[(size_t)Bn * DD];
__device__ __nv_bfloat16 g_pT_hi[(size_t)Bn * DD], g_pT_lo[(size_t)Bn * DD];
__device__ __nv_bfloat16 g_wbT_hi[(size_t)Bn * DD], g_wbT_lo[(size_t)Bn * DD];

// ------------------------------ PTX helpers --------------------------------
__device__ __forceinline__ uint32_t smem_u32(const void* p) {
    uint32_t a;
    asm("{ .reg .u64 t; cvta.to.shared.u64 t, %1; cvt.u32.u64 %0, t; }"
        : "=r"(a) : "l"(p));
    return a;
}

#define LDSM4(r, addr)                                                        \
    asm volatile("ldmatrix.sync.aligned.m8n8.x4.shared.b16 "                  \
                 "{%0,%1,%2,%3}, [%4];"                                       \
                 : "=r"((r)[0]), "=r"((r)[1]), "=r"((r)[2]), "=r"((r)[3])     \
                 : "r"(addr))

#define MMA_BF16(d, a, b)                                                     \
    asm volatile("mma.sync.aligned.m16n8k16.row.col.f32.bf16.bf16.f32 "       \
                 "{%0,%1,%2,%3}, {%4,%5,%6,%7}, {%8,%9}, {%0,%1,%2,%3};"      \
                 : "+f"((d)[0]), "+f"((d)[1]), "+f"((d)[2]), "+f"((d)[3])     \
                 : "r"((a)[0]), "r"((a)[1]), "r"((a)[2]), "r"((a)[3]),        \
                   "r"((b)[0]), "r"((b)[1]))

#define CP_ASYNC16(dst, src)                                                  \
    asm volatile("cp.async.cg.shared.global [%0], [%1], 16;"                  \
                 :: "r"(dst), "l"(src))
#define CP_COMMIT()  asm volatile("cp.async.commit_group;")
#define CP_WAIT1()   asm volatile("cp.async.wait_group 1;")
#define CP_WAIT0()   asm volatile("cp.async.wait_group 0;")

__device__ __forceinline__ uint32_t pack_bf2(float a, float b) {
    __nv_bfloat162 t;
    t.x = __float2bfloat16_rn(a);
    t.y = __float2bfloat16_rn(b);
    return *(uint32_t*)&t;
}

// ===========================================================================
// Tensor-core GEMM: C[M,N] = A[M,K] @ Bt[N,K]^T (+ bias[n]).
// bf16 hi/lo split (3 MMA terms). 128x128 tile, K-chunk 32, 3-stage cp.async.
// R6: single sync/chunk, B-fragment double buffer.
// ===========================================================================
namespace {
constexpr int TILE_B      = 128 * 32 * 2;
constexpr int STAGE_BYTES = 4 * TILE_B;
constexpr int STAGES      = 3;
constexpr int GEMM_SMEM   = STAGES * STAGE_BYTES;   // 96 KB
}

__global__ void __launch_bounds__(256, 2) gemm_tc(
    const __nv_bfloat16* __restrict__ Ahi, const __nv_bfloat16* __restrict__ Alo, long sA,
    const __nv_bfloat16* __restrict__ Bhi, const __nv_bfloat16* __restrict__ Blo, long sB,
    const float* __restrict__ bias, long sBias,
    float* __restrict__ Cf,
    __nv_bfloat16* __restrict__ Chi, __nv_bfloat16* __restrict__ Clo,
    long sC, int Ndim, int Kdim)
{
    extern __shared__ char smem[];
    const uint32_t sb = smem_u32(smem);
    const int tid = threadIdx.x;
    const int wid = tid >> 5;
    const int l   = tid & 31;
    const int zb  = blockIdx.z;

    Ahi += (long)zb * sA;  Alo += (long)zb * sA;
    Bhi += (long)zb * sB;  Blo += (long)zb * sB;
    if (bias) bias += (long)zb * sBias;

    const int m0 = blockIdx.y * 128;
    const int n0 = blockIdx.x * 128;
    const int NC = Kdim >> 5;

    const int r0i = (tid * 2) >> 2, c40 = (tid * 2) & 3;
    const int r1i = (tid * 2 + 1) >> 2, c41 = (tid * 2 + 1) & 3;
    const __nv_bfloat16* gsrc[4] = {
        Ahi + (long)m0 * Kdim, Alo + (long)m0 * Kdim,
        Bhi + (long)n0 * Kdim, Blo + (long)n0 * Kdim };

    const uint32_t so0 = r0i * 64 + ((c40 ^ ((r0i >> 1) & 3)) << 4);
    const uint32_t so1 = r1i * 64 + ((c41 ^ ((r1i >> 1) & 3)) << 4);

    auto issue_stage = [&](int s, int c) {
        const uint32_t base = sb + s * STAGE_BYTES;
        #pragma unroll
        for (int t = 0; t < 4; t++) {
            CP_ASYNC16(base + t * TILE_B + so0,
                       gsrc[t] + (long)r0i * Kdim + c * 32 + c40 * 8);
            CP_ASYNC16(base + t * TILE_B + so1,
                       gsrc[t] + (long)r1i * Kdim + c * 32 + c41 * 8);
        }
    };

    issue_stage(0, 0); CP_COMMIT();
    issue_stage(1, 1); CP_COMMIT();

    const int wm = wid & 3;
    const int wn = wid >> 2;

    float acc[2][8][4];
    #pragma unroll
    for (int i = 0; i < 2; i++)
        #pragma unroll
        for (int j = 0; j < 8; j++)
            #pragma unroll
            for (int q = 0; q < 4; q++) acc[i][j][q] = 0.f;

    uint32_t aoff[2][2], boff[2][4];
    #pragma unroll
    for (int ks = 0; ks < 2; ks++) {
        #pragma unroll
        for (int i = 0; i < 2; i++) {
            int row = wm * 32 + i * 16 + (l & 15);
            int c4  = ks * 2 + (l >> 4);
            aoff[ks][i] = row * 64 + ((c4 ^ ((row >> 1) & 3)) << 4);
        }
        #pragma unroll
        for (int p = 0; p < 4; p++) {
            int row = wn * 64 + p * 16 + (l & 7) + ((l & 16) >> 1);
            int c4  = ks * 2 + ((l >> 3) & 1);
            boff[ks][p] = row * 64 + ((c4 ^ ((row >> 1) & 3)) << 4);
        }
    }

    for (int c = 0; c < NC; c++) {
        if (c + 1 < NC) { CP_WAIT1(); } else { CP_WAIT0(); }
        __syncthreads();       // single sync: orders compute(c-1) before the
                               // issue below overwrites stage (c+2)%3
        if (c + 2 < NC) { issue_stage((c + 2) % STAGES, c + 2); CP_COMMIT(); }

        const uint32_t base = sb + (c % STAGES) * STAGE_BYTES;
        #pragma unroll
        for (int ks = 0; ks < 2; ks++) {
            uint32_t ah[2][4], al[2][4];
            #pragma unroll
            for (int i = 0; i < 2; i++) {
                LDSM4(ah[i], base + aoff[ks][i]);
                LDSM4(al[i], base + TILE_B + aoff[ks][i]);
            }
            // B double buffer: LDSM for p+1 issued before MMAs of p consume
            uint32_t rh[2][4], rl[2][4];
            LDSM4(rh[0], base + 2 * TILE_B + boff[ks][0]);
            LDSM4(rl[0], base + 3 * TILE_B + boff[ks][0]);
            #pragma unroll
            for (int p = 0; p < 4; p++) {
                const int cur = p & 1, nxt = cur ^ 1;
                if (p < 3) {
                    LDSM4(rh[nxt], base + 2 * TILE_B + boff[ks][p + 1]);
                    LDSM4(rl[nxt], base + 3 * TILE_B + boff[ks][p + 1]);
                }
                #pragma unroll
                for (int i = 0; i < 2; i++) {
                    MMA_BF16(acc[i][2*p],     ah[i], rh[cur]);
                    MMA_BF16(acc[i][2*p],     ah[i], rl[cur]);
                    MMA_BF16(acc[i][2*p],     al[i], rh[cur]);
                    MMA_BF16(acc[i][2*p + 1], ah[i], rh[cur] + 2);
                    MMA_BF16(acc[i][2*p + 1], ah[i], rl[cur] + 2);
                    MMA_BF16(acc[i][2*p + 1], al[i], rh[cur] + 2);
                }
            }
        }
    }

    const int mr = m0 + wm * 32 + (l >> 2);
    const int nc = n0 + wn * 64 + (l & 3) * 2;
    #pragma unroll
    for (int i = 0; i < 2; i++) {
        #pragma unroll
        for (int j = 0; j < 8; j++) {
            const int rr = mr + i * 16;
            const int cc = nc + j * 8;
            if (Cf) {
                float b0 = bias ? bias[cc] : 0.f;
                float b1 = bias ? bias[cc + 1] : 0.f;
                float2* p0 = (float2*)(Cf + (long)zb * sC + (long)rr * Ndim + cc);
                float2* p1 = (float2*)(Cf + (long)zb * sC + (long)(rr + 8) * Ndim + cc);
                *p0 = make_float2(acc[i][j][0] + b0, acc[i][j][1] + b1);
                *p1 = make_float2(acc[i][j][2] + b0, acc[i][j][3] + b1);
            } else {
                // bf16x2-packed split stores (cols cc, cc+1)
                float v0 = acc[i][j][0], v1 = acc[i][j][1];
                float v2 = acc[i][j][2], v3 = acc[i][j][3];
                __nv_bfloat16 h0 = __float2bfloat16_rn(v0);
                __nv_bfloat16 h1 = __float2bfloat16_rn(v1);
                __nv_bfloat16 h2 = __float2bfloat16_rn(v2);
                __nv_bfloat16 h3 = __float2bfloat16_rn(v3);
                long o0 = (long)zb * sC + (long)rr * Ndim + cc;
                long o1 = (long)zb * sC + (long)(rr + 8) * Ndim + cc;
                __nv_bfloat162 hp, lp;
                hp.x = h0; hp.y = h1;
                lp.x = __float2bfloat16_rn(v0 - __bfloat162float(h0));
                lp.y = __float2bfloat16_rn(v1 - __bfloat162float(h1));
                *(__nv_bfloat162*)(Chi + o0) = hp;
                *(__nv_bfloat162*)(Clo + o0) = lp;
                hp.x = h2; hp.y = h3;
                lp.x = __float2bfloat16_rn(v2 - __bfloat162float(h2));
                lp.y = __float2bfloat16_rn(v3 - __bfloat162float(h3));
                *(__nv_bfloat162*)(Chi + o1) = hp;
                *(__nv_bfloat162*)(Clo + o1) = lp;
            }
        }
    }
}

// ===========================================================================
// small kernels
// ===========================================================================

__global__ void __launch_bounds__(256) split_kernel(
    const float* __restrict__ in, __nv_bfloat16* __restrict__ hi,
    __nv_bfloat16* __restrict__ lo, int n)
{
    int i = (blockIdx.x * 256 + threadIdx.x) * 4;
    if (i >= n) return;
    float4 x = *(const float4*)(in + i);
    float xs[4] = {x.x, x.y, x.z, x.w};
    __nv_bfloat16 h[4], lv[4];
    #pragma unroll
    for (int k = 0; k < 4; k++) {
        h[k] = __float2bfloat16_rn(xs[k]);
        lv[k] = __float2bfloat16_rn(xs[k] - __bfloat162float(h[k]));
    }
    __nv_bfloat162 h01; h01.x = h[0]; h01.y = h[1];
    __nv_bfloat162 h23; h23.x = h[2]; h23.y = h[3];
    __nv_bfloat162 l01; l01.x = lv[0]; l01.y = lv[1];
    __nv_bfloat162 l23; l23.x = lv[2]; l23.y = lv[3];
    *(__nv_bfloat162*)(hi + i)     = h01;
    *(__nv_bfloat162*)(hi + i + 2) = h23;
    *(__nv_bfloat162*)(lo + i)     = l01;
    *(__nv_bfloat162*)(lo + i + 2) = l23;
}

// transpose + split (+ optional per-block column partial sums)
// in [R,C] fp32 -> out [C,R] bf16 hi/lo; part[(z*gridDim.y+y)*C + col] if set
__global__ void __launch_bounds__(256) splitT_kernel(
    const float* __restrict__ in, long sIn,
    __nv_bfloat16* __restrict__ hi, __nv_bfloat16* __restrict__ lo, long sOut,
    int R, int C, float* __restrict__ part)
{
    __shared__ float t[32][33];
    __shared__ float ps[8][32];
    in += (long)blockIdx.z * sIn;
    hi += (long)blockIdx.z * sOut;
    lo += (long)blockIdx.z * sOut;
    const int c0 = blockIdx.x * 32;
    const int r0 = blockIdx.y * 32;
    const int tx = threadIdx.x, ty = threadIdx.y;
    float acc = 0.f;
    for (int k = ty; k < 32; k += 8) {
        float v = in[(long)(r0 + k) * C + c0 + tx];
        t[k][tx] = v;
        acc += v;
    }
    if (part) ps[ty][tx] = acc;
    __syncthreads();
    if (part && ty == 0) {
        float s = ps[0][tx] + ps[1][tx] + ps[2][tx] + ps[3][tx]
                + ps[4][tx] + ps[5][tx] + ps[6][tx] + ps[7][tx];
        part[((long)blockIdx.z * gridDim.y + blockIdx.y) * C + c0 + tx] = s;
    }
    for (int k = ty; k < 32; k += 8) {
        float vv = t[tx][k];
        __nv_bfloat16 h = __float2bfloat16_rn(vv);
        long o = (long)(c0 + k) * R + r0 + tx;
        hi[o] = h;
        lo[o] = __float2bfloat16_rn(vv - __bfloat162float(h));
    }
}

// reduce 64 partials -> colsum
__global__ void __launch_bounds__(256) colsum2_kernel(
    const float* __restrict__ part, float* __restrict__ out)
{
    const int b = blockIdx.y;
    const int d = blockIdx.x * 256 + threadIdx.x;
    float s = 0.f;
    #pragma unroll 8
    for (int k = 0; k < 64; k++) s += part[((long)b * 64 + k) * Dd + d];
    out[b * Dd + d] = s;
}

// cka[b][i] = sum_d Wk[d][i]*ksum[b][d] ; cvb likewise (z selects)
__global__ void __launch_bounds__(256) corr_kernel(
    const float* __restrict__ Wk, const float* __restrict__ Wv,
    const float* __restrict__ ksum, const float* __restrict__ vsum,
    float* __restrict__ cka, float* __restrict__ cvb)
{
    const int b = blockIdx.y;
    const float* W = blockIdx.z ? Wv : Wk;
    const float* s = (blockIdx.z ? vsum : ksum) + b * Dd;
    float* o = (blockIdx.z ? cvb : cka) + b * Dd;
    const int t = threadIdx.x;
    const int i = blockIdx.x * 128 + (t & 127);
    const int half = t >> 7;
    float acc = 0.f;
    #pragma unroll 8
    for (int d = half * 512; d < half * 512 + 512; d++)
        acc += W[(long)d * Dd + i] * s[d];
    __shared__ float sm[256];
    sm[t] = acc; __syncthreads();
    if (t < 128) o[i] = sm[t] + sm[t + 128];
}

// M_{b,h}[i][j] = scale*( sum_d Wk[d,h64+i]*T1[b][d][h64+j] + corrections )
__global__ void __launch_bounds__(256) Mdiag_kernel(
    const float* __restrict__ Wk, const float* __restrict__ T1,
    const float* __restrict__ bk, const float* __restrict__ bv,
    const float* __restrict__ cka, const float* __restrict__ cvb,
    float* __restrict__ Mout)
{
    const int h = blockIdx.x;
    const int b = blockIdx.y;
    const float* Kp = Wk + h * HD;
    const float* Tp = T1 + (long)b * DD + h * HD;

    __shared__ float Kt[32][64];
    __shared__ float Vt[32][64];

    const int tid = threadIdx.x;
    const int ti = tid & 15;
    const int tj = tid >> 4;
    const int lr = tid >> 3;
    const int lc = (tid & 7) * 8;

    float acc[4][4];
    #pragma unroll
    for (int a = 0; a < 4; a++)
        #pragma unroll
        for (int c = 0; c < 4; c++) acc[a][c] = 0.f;

    for (int d0 = 0; d0 < Dd; d0 += 32) {
        const float* kp = Kp + (long)(d0 + lr) * Dd + lc;
        const float* vp = Tp + (long)(d0 + lr) * Dd + lc;
        float4 k0 = *(const float4*)kp;
        float4 k1 = *(const float4*)(kp + 4);
        float4 v0 = *(const float4*)vp;
        float4 v1 = *(const float4*)(vp + 4);
        __syncthreads();
        *(float4*)&Kt[lr][lc]     = k0;
        *(float4*)&Kt[lr][lc + 4] = k1;
        *(float4*)&Vt[lr][lc]     = v0;
        *(float4*)&Vt[lr][lc + 4] = v1;
        __syncthreads();

        #pragma unroll 8
        for (int ss = 0; ss < 32; ss++) {
            float4 ka = *(const float4*)&Kt[ss][ti * 4];
            float4 va = *(const float4*)&Vt[ss][tj * 4];
            float rk[4] = {ka.x, ka.y, ka.z, ka.w};
            float rv[4] = {va.x, va.y, va.z, va.w};
            #pragma unroll
            for (int a = 0; a < 4; a++)
                #pragma unroll
                for (int c = 0; c < 4; c++)
                    acc[a][c] += rk[a] * rv[c];
        }
    }

    const float scale = 0.125f;
    float* Mp = Mout + ((long)(b * Hh + h)) * HD * HD;
    #pragma unroll
    for (int a = 0; a < 4; a++) {
        const int i = ti * 4 + a;
        const float bki  = bk[h * HD + i];
        const float ckai = cka[b * Dd + h * HD + i];
        float4 vo;
        float* vp = &vo.x;
        #pragma unroll
        for (int c = 0; c < 4; c++) {
            const int j = tj * 4 + c;
            float corr = ckai * bv[h * HD + j]
                       + bki * cvb[b * Dd + h * HD + j]
                       + (float)Ssz * bki * bv[h * HD + j];
            vp[c] = scale * (acc[a][c] + corr);
        }
        *(float4*)&Mp[i * HD + tj * 4] = vo;
    }
}

// P^T hi/lo directly: for rows r = h*64+row0+i, cols cc -> pT[cc][r]
__global__ void __launch_bounds__(256) P_kernel(
    const float* __restrict__ Mmat, const float* __restrict__ Wo,
    __nv_bfloat16* __restrict__ pth, __nv_bfloat16* __restrict__ ptl)
{
    const int nb = blockIdx.x;
    const int h  = blockIdx.y;
    const int b  = blockIdx.z;

    __shared__ float Ms[64][64];
    const float* Mp = Mmat + ((long)(b * Hh + h)) * HD * HD;
    for (int i = threadIdx.x; i < HD * HD; i += 256)
        Ms[i >> 6][i & 63] = Mp[i];
    __syncthreads();

    const int tid  = threadIdx.x;
    const int col  = nb * 128 + (tid & 31) * 4;
    const int row0 = (tid >> 5) * 8;

    float acc[8][4];
    #pragma unroll
    for (int i = 0; i < 8; i++)
        #pragma unroll
        for (int c = 0; c < 4; c++) acc[i][c] = 0.f;

    const float* Wp = Wo + (long)(h * HD) * Dd + col;
    #pragma unroll 8
    for (int j = 0; j < HD; j++) {
        float4 w = *(const float4*)(Wp + (long)j * Dd);
        #pragma unroll
        for (int i = 0; i < 8; i++) {
            float m = Ms[row0 + i][j];
            acc[i][0] += m * w.x;
            acc[i][1] += m * w.y;
            acc[i][2] += m * w.z;
            acc[i][3] += m * w.w;
        }
    }

    // write transposed split: o = (col+c)*Dd + h*64 + row0 + i (8 contig bf16)
    #pragma unroll
    for (int c = 0; c < 4; c++) {
        uint32_t hbuf[4], lbuf[4];
        #pragma unroll
        for (int i = 0; i < 8; i += 2) {
            float v0 = acc[i][c], v1 = acc[i + 1][c];
            __nv_bfloat16 h0 = __float2bfloat16_rn(v0);
            __nv_bfloat16 h1 = __float2bfloat16_rn(v1);
            __nv_bfloat162 hp; hp.x = h0; hp.y = h1;
            __nv_bfloat162 lp;
            lp.x = __float2bfloat16_rn(v0 - __bfloat162float(h0));
            lp.y = __float2bfloat16_rn(v1 - __bfloat162float(h1));
            hbuf[i >> 1] = *(uint32_t*)&hp;
            lbuf[i >> 1] = *(uint32_t*)&lp;
        }
        long o = (long)b * DD + (long)(col + c) * Dd + h * HD + row0;
        *(uint4*)(pth + o) = make_uint4(hbuf[0], hbuf[1], hbuf[2], hbuf[3]);
        *(uint4*)(ptl + o) = make_uint4(lbuf[0], lbuf[1], lbuf[2], lbuf[3]);
    }
}

// tv[b][h*64+j] = sum_i bq[h*64+i] * M[b,h,i,j]
__global__ void __launch_bounds__(64) tvec_kernel(
    const float* __restrict__ M, const float* __restrict__ bq,
    float* __restrict__ tv)
{
    const int h = blockIdx.x, b = blockIdx.y;
    const int j = threadIdx.x;
    const float* Mp = M + ((long)(b * Hh + h)) * HD * HD;
    float acc = 0.f;
    #pragma unroll 8
    for (int i = 0; i < HD; i++) acc += bq[h * HD + i] * Mp[i * HD + j];
    tv[b * Dd + h * HD + j] = acc;
}

// bbig[b][n] = sum_r tv[b][r]*Wo[r][n] + bo[n]
__global__ void __launch_bounds__(256) bbig2_kernel(
    const float* __restrict__ tv, const float* __restrict__ Wo,
    const float* __restrict__ bo, float* __restrict__ bbig)
{
    const int b = blockIdx.y;
    const int t = threadIdx.x;
    const int n = blockIdx.x * 64 + (t & 63);
    const int rs = t >> 6;
    float acc = 0.f;
    #pragma unroll 8
    for (int r = rs * 256; r < rs * 256 + 256; r++)
        acc += tv[b * Dd + r] * Wo[(long)r * Dd + n];
    __shared__ float sm[256];
    sm[t] = acc; __syncthreads();
    if (t < 64)
        bbig[b * Dd + n] = sm[t] + sm[t + 64] + sm[t + 128] + sm[t + 192] + bo[n];
}

// ===========================================================================
extern "C" void kernel_launch(void* const* d_in, const int* in_sizes, int n_in,
                              void* d_out, int out_size)
{
    const float* query = (const float*)d_in[0];
    const float* key   = (const float*)d_in[1];
    const float* value = (const float*)d_in[2];
    const float* Wq    = (const float*)d_in[3];
    const float* bq    = (const float*)d_in[4];
    const float* Wk    = (const float*)d_in[5];
    const float* bk    = (const float*)d_in[6];
    const float* Wv    = (const float*)d_in[7];
    const float* bv    = (const float*)d_in[8];
    const float* Wo    = (const float*)d_in[9];
    const float* bo    = (const float*)d_in[10];
    float* out = (float*)d_out;

    float *pT1, *pM, *pB, *pTv, *pKs, *pVs, *pKp, *pVp, *pCka, *pCvb;
    cudaGetSymbolAddress((void**)&pT1, g_T1);
    cudaGetSymbolAddress((void**)&pM,  g_M);
    cudaGetSymbolAddress((void**)&pB,  g_bbig);
    cudaGetSymbolAddress((void**)&pTv, g_tv);
    cudaGetSymbolAddress((void**)&pKs, g_ksum);
    cudaGetSymbolAddress((void**)&pVs, g_vsum);
    cudaGetSymbolAddress((void**)&pKp, g_kpart);
    cudaGetSymbolAddress((void**)&pVp, g_vpart);
    cudaGetSymbolAddress((void**)&pCka, g_cka);
    cudaGetSymbolAddress((void**)&pCvb, g_cvb);
    __nv_bfloat16 *qh, *ql, *kth, *ktl, *vth, *vtl, *wqh, *wql, *wvth, *wvtl;
    __nv_bfloat16 *gh, *gl, *pth, *ptl, *wbth, *wbtl;
    cudaGetSymbolAddress((void**)&qh,  g_q_hi);  cudaGetSymbolAddress((void**)&ql,  g_q_lo);
    cudaGetSymbolAddress((void**)&kth, g_kT_hi); cudaGetSymbolAddress((void**)&ktl, g_kT_lo);
    cudaGetSymbolAddress((void**)&vth, g_vT_hi); cudaGetSymbolAddress((void**)&vtl, g_vT_lo);
    cudaGetSymbolAddress((void**)&wqh, g_wq_hi); cudaGetSymbolAddress((void**)&wql, g_wq_lo);
    cudaGetSymbolAddress((void**)&wvth, g_wvT_hi); cudaGetSymbolAddress((void**)&wvtl, g_wvT_lo);
    cudaGetSymbolAddress((void**)&gh,  g_G_hi);  cudaGetSymbolAddress((void**)&gl,  g_G_lo);
    cudaGetSymbolAddress((void**)&pth, g_pT_hi); cudaGetSymbolAddress((void**)&ptl, g_pT_lo);
    cudaGetSymbolAddress((void**)&wbth, g_wbT_hi); cudaGetSymbolAddress((void**)&wbtl, g_wbT_lo);

    cudaFuncSetAttribute(gemm_tc, cudaFuncAttributeMaxDynamicSharedMemorySize, GEMM_SMEM);

    const long sBatch = (long)Ssz * Dd;

    // 1-3) query split; key/value transpose-splits WITH fused column partials
    split_kernel<<<GME / 1024, 256>>>(query, qh, ql, GME);
    splitT_kernel<<<dim3(Dd / 32, Ssz / 32, Bn), dim3(32, 8)>>>(
        key, sBatch, kth, ktl, sBatch, Ssz, Dd, pKp);
    splitT_kernel<<<dim3(Dd / 32, Ssz / 32, Bn), dim3(32, 8)>>>(
        value, sBatch, vth, vtl, sBatch, Ssz, Dd, pVp);

    // 4) G_b = key_b^T @ value_b  (4th launch -> ncu profile)
    gemm_tc<<<dim3(Dd / 128, Dd / 128, Bn), 256, GEMM_SMEM>>>(
        kth, ktl, sBatch, vth, vtl, sBatch, nullptr, 0,
        nullptr, gh, gl, (long)DD, Dd, Ssz);

    // 5-6) weight splits
    split_kernel<<<DD / 1024, 256>>>(Wq, wqh, wql, DD);
    splitT_kernel<<<dim3(32, 32, 1), dim3(32, 8)>>>(
        Wv, 0, wvth, wvtl, 0, Dd, Dd, nullptr);

    // 7-9) colsum reduce + bias-correction matvecs
    colsum2_kernel<<<dim3(Dd / 256, Bn), 256>>>(pKp, pKs);
    colsum2_kernel<<<dim3(Dd / 256, Bn), 256>>>(pVp, pVs);
    corr_kernel<<<dim3(Dd / 128, Bn, 2), 256>>>(Wk, Wv, pKs, pVs, pCka, pCvb);

    // 10) T1_b = G_b @ Wv
    gemm_tc<<<dim3(Dd / 128, Dd / 128, Bn), 256, GEMM_SMEM>>>(
        gh, gl, (long)DD, wvth, wvtl, 0, nullptr, 0,
        pT1, nullptr, nullptr, (long)DD, Dd, Dd);

    // 11) M diag blocks + bias corrections
    Mdiag_kernel<<<dim3(Hh, Bn), 256>>>(Wk, pT1, bk, bv, pCka, pCvb, pM);

    // 12-14) P (writes P^T hi/lo directly), t-vector, bbig
    P_kernel<<<dim3(Dd / 128, Hh, Bn), 256>>>(pM, Wo, pth, ptl);
    tvec_kernel<<<dim3(Hh, Bn), 64>>>(pM, bq, pTv);
    bbig2_kernel<<<dim3(Dd / 64, Bn), 256>>>(pTv, Wo, bo, pB);

    // 15) WbigT_b = P_b^T @ Wq^T
    gemm_tc<<<dim3(Dd / 128, Dd / 128, Bn), 256, GEMM_SMEM>>>(
        pth, ptl, (long)DD, wqh, wql, 0, nullptr, 0,
        nullptr, wbth, wbtl, (long)DD, Dd, Dd);

    // 16) out_b = query_b @ Wbig_b + bbig_b
    gemm_tc<<<dim3(Dd / 128, Ssz / 128, Bn), 256, GEMM_SMEM>>>(
        qh, ql, sBatch, wbth, wbtl, (long)DD, pB, Dd,
        out, nullptr, nullptr, sBatch, Dd, Dd);
}

// round 9
// speedup vs baseline: 3.0241x; 1.2786x over previous
#include <cuda_runtime.h>
#include <cuda_fp16.h>
#include <cstdint>

// ===========================================================================
// MHA WITHOUT softmax == linear operator, fully re-associated:
//   G_b  = key_b^T @ value_b                         (mma.sync fp16 2-term)
//   T1_b = G_b @ Wv                                  (mma.sync fp16 2-term)
//   M_{b,h} = scale*( diag64(Wk^T T1)_h + rank-1 bias corrections )
//   PT_b = (stack_h(M_{b,h} @ Wo_h))^T               (SIMT, tiny, fused split)
//   WbigT_b = P_b^T @ Wq^T                           (mma.sync fp16 2-term)
//   bbig_b = (bq.M)^T @ Wo + bo                      (SIMT, tiny)
//   out_b = query_b @ Wbig_b + bbig_b                (mma.sync fp16 2-term)
// R9: fp16 asymmetric split (A=Ah+Al fp16, B=rounded fp16; drops A*Blo
//     ~2^-12/GEMM) grafted onto the UNCHANGED R6 3-stage pipeline skeleton
//     (the last configuration the broker demonstrably ran).
// ===========================================================================

namespace {
constexpr int Bn  = 4;
constexpr int Ssz = 2048;
constexpr int Dd  = 1024;
constexpr int Hh  = 16;
constexpr int HD  = 64;
constexpr int GME = Bn * Ssz * Dd;
constexpr int DD  = Dd * Dd;
}

// ------------------------- scratch (device globals) ------------------------
__device__ float g_T1[(size_t)Bn * DD];
__device__ float g_M[Bn * Hh * HD * HD];
__device__ float g_bbig[Bn * Dd];
__device__ float g_tv[Bn * Dd];
__device__ float g_ksum[Bn * Dd], g_vsum[Bn * Dd];
__device__ float g_kpart[(size_t)Bn * 64 * Dd], g_vpart[(size_t)Bn * 64 * Dd];
__device__ float g_cka[Bn * Dd], g_cvb[Bn * Dd];

__device__ __half g_q_hi[GME],  g_q_lo[GME];
__device__ __half g_kT_hi[GME], g_kT_lo[GME];
__device__ __half g_vT_hi[GME];                       // B operand: hi only
__device__ __half g_wq_hi[DD];                        // B operand: hi only
__device__ __half g_wvT_hi[DD];                       // B operand: hi only
__device__ __half g_G_hi[(size_t)Bn * DD], g_G_lo[(size_t)Bn * DD];
__device__ __half g_pT_hi[(size_t)Bn * DD], g_pT_lo[(size_t)Bn * DD];
__device__ __half g_wbT_hi[(size_t)Bn * DD];          // B operand: hi only

// ------------------------------ PTX helpers --------------------------------
__device__ __forceinline__ uint32_t smem_u32(const void* p) {
    uint32_t a;
    asm("{ .reg .u64 t; cvta.to.shared.u64 t, %1; cvt.u32.u64 %0, t; }"
        : "=r"(a) : "l"(p));
    return a;
}

#define LDSM4(r, addr)                                                        \
    asm volatile("ldmatrix.sync.aligned.m8n8.x4.shared.b16 "                  \
                 "{%0,%1,%2,%3}, [%4];"                                       \
                 : "=r"((r)[0]), "=r"((r)[1]), "=r"((r)[2]), "=r"((r)[3])     \
                 : "r"(addr))

#define MMA_F16(d, a, b)                                                      \
    asm volatile("mma.sync.aligned.m16n8k16.row.col.f32.f16.f16.f32 "         \
                 "{%0,%1,%2,%3}, {%4,%5,%6,%7}, {%8,%9}, {%0,%1,%2,%3};"      \
                 : "+f"((d)[0]), "+f"((d)[1]), "+f"((d)[2]), "+f"((d)[3])     \
                 : "r"((a)[0]), "r"((a)[1]), "r"((a)[2]), "r"((a)[3]),        \
                   "r"((b)[0]), "r"((b)[1]))

#define CP_ASYNC16(dst, src)                                                  \
    asm volatile("cp.async.cg.shared.global [%0], [%1], 16;"                  \
                 :: "r"(dst), "l"(src))
#define CP_COMMIT()  asm volatile("cp.async.commit_group;")
#define CP_WAIT1()   asm volatile("cp.async.wait_group 1;")
#define CP_WAIT0()   asm volatile("cp.async.wait_group 0;")

// ===========================================================================
// Tensor-core GEMM: C[M,N] = A[M,K] @ Bt[N,K]^T (+ bias[n]).
// fp16 asymmetric split (A hi/lo, B hi). 128x128 tile, K-chunk 32,
// 3-stage cp.async pipeline (R6 skeleton), single __syncthreads per chunk.
// Output: Cf (fp32 + bias) OR Chi (+ optional Clo) fp16 split.
// ===========================================================================
namespace {
constexpr int TILE_B      = 128 * 32 * 2;          // 8 KB per fp16 tile
constexpr int STAGE_BYTES = 3 * TILE_B;            // Ahi, Alo, Bh = 24 KB
constexpr int STAGES      = 3;
constexpr int GEMM_SMEM   = STAGES * STAGE_BYTES;  // 72 KB
}

__global__ void __launch_bounds__(256, 2) gemm_tc(
    const __half* __restrict__ Ahi, const __half* __restrict__ Alo, long sA,
    const __half* __restrict__ Bh, long sB,
    const float* __restrict__ bias, long sBias,
    float* __restrict__ Cf,
    __half* __restrict__ Chi, __half* __restrict__ Clo,
    long sC, int Ndim, int Kdim)
{
    extern __shared__ char smem[];
    const uint32_t sb = smem_u32(smem);
    const int tid = threadIdx.x;
    const int wid = tid >> 5;
    const int l   = tid & 31;
    const int zb  = blockIdx.z;

    Ahi += (long)zb * sA;  Alo += (long)zb * sA;
    Bh  += (long)zb * sB;
    if (bias) bias += (long)zb * sBias;

    const int m0 = blockIdx.y * 128;
    const int n0 = blockIdx.x * 128;
    const int NC = Kdim >> 5;

    const int r0i = (tid * 2) >> 2, c40 = (tid * 2) & 3;
    const int r1i = (tid * 2 + 1) >> 2, c41 = (tid * 2 + 1) & 3;
    const __half* gsrc[3] = {
        Ahi + (long)m0 * Kdim, Alo + (long)m0 * Kdim, Bh + (long)n0 * Kdim };

    const uint32_t so0 = r0i * 64 + ((c40 ^ ((r0i >> 1) & 3)) << 4);
    const uint32_t so1 = r1i * 64 + ((c41 ^ ((r1i >> 1) & 3)) << 4);

    auto issue_stage = [&](int s, int c) {
        const uint32_t base = sb + s * STAGE_BYTES;
        #pragma unroll
        for (int t = 0; t < 3; t++) {
            CP_ASYNC16(base + t * TILE_B + so0,
                       gsrc[t] + (long)r0i * Kdim + c * 32 + c40 * 8);
            CP_ASYNC16(base + t * TILE_B + so1,
                       gsrc[t] + (long)r1i * Kdim + c * 32 + c41 * 8);
        }
    };

    issue_stage(0, 0); CP_COMMIT();
    issue_stage(1, 1); CP_COMMIT();

    const int wm = wid & 3;
    const int wn = wid >> 2;

    float acc[2][8][4];
    #pragma unroll
    for (int i = 0; i < 2; i++)
        #pragma unroll
        for (int j = 0; j < 8; j++)
            #pragma unroll
            for (int q = 0; q < 4; q++) acc[i][j][q] = 0.f;

    uint32_t aoff[2][2], boff[2][4];
    #pragma unroll
    for (int ks = 0; ks < 2; ks++) {
        #pragma unroll
        for (int i = 0; i < 2; i++) {
            int row = wm * 32 + i * 16 + (l & 15);
            int c4  = ks * 2 + (l >> 4);
            aoff[ks][i] = row * 64 + ((c4 ^ ((row >> 1) & 3)) << 4);
        }
        #pragma unroll
        for (int p = 0; p < 4; p++) {
            int row = wn * 64 + p * 16 + (l & 7) + ((l & 16) >> 1);
            int c4  = ks * 2 + ((l >> 3) & 1);
            boff[ks][p] = row * 64 + ((c4 ^ ((row >> 1) & 3)) << 4);
        }
    }

    for (int c = 0; c < NC; c++) {
        if (c + 1 < NC) { CP_WAIT1(); } else { CP_WAIT0(); }
        __syncthreads();     // single sync: orders compute(c-1) before the
                             // issue below overwrites stage (c+2)%3
        if (c + 2 < NC) { issue_stage((c + 2) % STAGES, c + 2); CP_COMMIT(); }

        const uint32_t base = sb + (c % STAGES) * STAGE_BYTES;
        #pragma unroll
        for (int ks = 0; ks < 2; ks++) {
            uint32_t ah[2][4], al[2][4];
            #pragma unroll
            for (int i = 0; i < 2; i++) {
                LDSM4(ah[i], base + aoff[ks][i]);
                LDSM4(al[i], base + TILE_B + aoff[ks][i]);
            }
            // B double buffer: LDSM for p+1 issued before MMAs of p consume
            uint32_t rh[2][4];
            LDSM4(rh[0], base + 2 * TILE_B + boff[ks][0]);
            #pragma unroll
            for (int p = 0; p < 4; p++) {
                const int cur = p & 1, nxt = cur ^ 1;
                if (p < 3) LDSM4(rh[nxt], base + 2 * TILE_B + boff[ks][p + 1]);
                #pragma unroll
                for (int i = 0; i < 2; i++) {
                    MMA_F16(acc[i][2*p],     ah[i], rh[cur]);
                    MMA_F16(acc[i][2*p],     al[i], rh[cur]);
                    MMA_F16(acc[i][2*p + 1], ah[i], rh[cur] + 2);
                    MMA_F16(acc[i][2*p + 1], al[i], rh[cur] + 2);
                }
            }
        }
    }

    const int mr = m0 + wm * 32 + (l >> 2);
    const int nc = n0 + wn * 64 + (l & 3) * 2;
    #pragma unroll
    for (int i = 0; i < 2; i++) {
        #pragma unroll
        for (int j = 0; j < 8; j++) {
            const int rr = mr + i * 16;
            const int cc = nc + j * 8;
            if (Cf) {
                float b0 = bias ? bias[cc] : 0.f;
                float b1 = bias ? bias[cc + 1] : 0.f;
                float2* p0 = (float2*)(Cf + (long)zb * sC + (long)rr * Ndim + cc);
                float2* p1 = (float2*)(Cf + (long)zb * sC + (long)(rr + 8) * Ndim + cc);
                *p0 = make_float2(acc[i][j][0] + b0, acc[i][j][1] + b1);
                *p1 = make_float2(acc[i][j][2] + b0, acc[i][j][3] + b1);
            } else {
                float v0 = acc[i][j][0], v1 = acc[i][j][1];
                float v2 = acc[i][j][2], v3 = acc[i][j][3];
                __half h0 = __float2half_rn(v0), h1 = __float2half_rn(v1);
                __half h2 = __float2half_rn(v2), h3 = __float2half_rn(v3);
                long o0 = (long)zb * sC + (long)rr * Ndim + cc;
                long o1 = (long)zb * sC + (long)(rr + 8) * Ndim + cc;
                __half2 hp;
                hp.x = h0; hp.y = h1;
                *(__half2*)(Chi + o0) = hp;
                hp.x = h2; hp.y = h3;
                *(__half2*)(Chi + o1) = hp;
                if (Clo) {
                    __half2 lp;
                    lp.x = __float2half_rn(v0 - __half2float(h0));
                    lp.y = __float2half_rn(v1 - __half2float(h1));
                    *(__half2*)(Clo + o0) = lp;
                    lp.x = __float2half_rn(v2 - __half2float(h2));
                    lp.y = __float2half_rn(v3 - __half2float(h3));
                    *(__half2*)(Clo + o1) = lp;
                }
            }
        }
    }
}

// ===========================================================================
// small kernels
// ===========================================================================

// elementwise fp32 -> fp16 hi (+ optional lo)
__global__ void __launch_bounds__(256) split_kernel(
    const float* __restrict__ in, __half* __restrict__ hi,
    __half* __restrict__ lo, int n)
{
    int i = (blockIdx.x * 256 + threadIdx.x) * 4;
    if (i >= n) return;
    float4 x = *(const float4*)(in + i);
    float xs[4] = {x.x, x.y, x.z, x.w};
    __half h[4];
    #pragma unroll
    for (int k = 0; k < 4; k++) h[k] = __float2half_rn(xs[k]);
    __half2 h01; h01.x = h[0]; h01.y = h[1];
    __half2 h23; h23.x = h[2]; h23.y = h[3];
    *(__half2*)(hi + i)     = h01;
    *(__half2*)(hi + i + 2) = h23;
    if (lo) {
        __half2 l01, l23;
        l01.x = __float2half_rn(xs[0] - __half2float(h[0]));
        l01.y = __float2half_rn(xs[1] - __half2float(h[1]));
        l23.x = __float2half_rn(xs[2] - __half2float(h[2]));
        l23.y = __float2half_rn(xs[3] - __half2float(h[3]));
        *(__half2*)(lo + i)     = l01;
        *(__half2*)(lo + i + 2) = l23;
    }
}

// transpose + split (+ optional lo, optional per-block column partial sums)
__global__ void __launch_bounds__(256) splitT_kernel(
    const float* __restrict__ in, long sIn,
    __half* __restrict__ hi, __half* __restrict__ lo, long sOut,
    int R, int C, float* __restrict__ part)
{
    __shared__ float t[32][33];
    __shared__ float ps[8][32];
    in += (long)blockIdx.z * sIn;
    hi += (long)blockIdx.z * sOut;
    if (lo) lo += (long)blockIdx.z * sOut;
    const int c0 = blockIdx.x * 32;
    const int r0 = blockIdx.y * 32;
    const int tx = threadIdx.x, ty = threadIdx.y;
    float acc = 0.f;
    for (int k = ty; k < 32; k += 8) {
        float v = in[(long)(r0 + k) * C + c0 + tx];
        t[k][tx] = v;
        acc += v;
    }
    if (part) ps[ty][tx] = acc;
    __syncthreads();
    if (part && ty == 0) {
        float s = ps[0][tx] + ps[1][tx] + ps[2][tx] + ps[3][tx]
                + ps[4][tx] + ps[5][tx] + ps[6][tx] + ps[7][tx];
        part[((long)blockIdx.z * gridDim.y + blockIdx.y) * C + c0 + tx] = s;
    }
    for (int k = ty; k < 32; k += 8) {
        float vv = t[tx][k];
        __half h = __float2half_rn(vv);
        long o = (long)(c0 + k) * R + r0 + tx;
        hi[o] = h;
        if (lo) lo[o] = __float2half_rn(vv - __half2float(h));
    }
}

// reduce 64 partials -> colsum
__global__ void __launch_bounds__(256) colsum2_kernel(
    const float* __restrict__ part, float* __restrict__ out)
{
    const int b = blockIdx.y;
    const int d = blockIdx.x * 256 + threadIdx.x;
    float s = 0.f;
    #pragma unroll 8
    for (int k = 0; k < 64; k++) s += part[((long)b * 64 + k) * Dd + d];
    out[b * Dd + d] = s;
}

// cka[b][i] = sum_d Wk[d][i]*ksum[b][d] ; cvb likewise (z selects)
__global__ void __launch_bounds__(256) corr_kernel(
    const float* __restrict__ Wk, const float* __restrict__ Wv,
    const float* __restrict__ ksum, const float* __restrict__ vsum,
    float* __restrict__ cka, float* __restrict__ cvb)
{
    const int b = blockIdx.y;
    const float* W = blockIdx.z ? Wv : Wk;
    const float* s = (blockIdx.z ? vsum : ksum) + b * Dd;
    float* o = (blockIdx.z ? cvb : cka) + b * Dd;
    const int t = threadIdx.x;
    const int i = blockIdx.x * 128 + (t & 127);
    const int half = t >> 7;
    float acc = 0.f;
    #pragma unroll 8
    for (int d = half * 512; d < half * 512 + 512; d++)
        acc += W[(long)d * Dd + i] * s[d];
    __shared__ float sm[256];
    sm[t] = acc; __syncthreads();
    if (t < 128) o[i] = sm[t] + sm[t + 128];
}

// M_{b,h}[i][j] = scale*( sum_d Wk[d,h64+i]*T1[b][d][h64+j] + corrections )
__global__ void __launch_bounds__(256) Mdiag_kernel(
    const float* __restrict__ Wk, const float* __restrict__ T1,
    const float* __restrict__ bk, const float* __restrict__ bv,
    const float* __restrict__ cka, const float* __restrict__ cvb,
    float* __restrict__ Mout)
{
    const int h = blockIdx.x;
    const int b = blockIdx.y;
    const float* Kp = Wk + h * HD;
    const float* Tp = T1 + (long)b * DD + h * HD;

    __shared__ float Kt[32][64];
    __shared__ float Vt[32][64];

    const int tid = threadIdx.x;
    const int ti = tid & 15;
    const int tj = tid >> 4;
    const int lr = tid >> 3;
    const int lc = (tid & 7) * 8;

    float acc[4][4];
    #pragma unroll
    for (int a = 0; a < 4; a++)
        #pragma unroll
        for (int c = 0; c < 4; c++) acc[a][c] = 0.f;

    for (int d0 = 0; d0 < Dd; d0 += 32) {
        const float* kp = Kp + (long)(d0 + lr) * Dd + lc;
        const float* vp = Tp + (long)(d0 + lr) * Dd + lc;
        float4 k0 = *(const float4*)kp;
        float4 k1 = *(const float4*)(kp + 4);
        float4 v0 = *(const float4*)vp;
        float4 v1 = *(const float4*)(vp + 4);
        __syncthreads();
        *(float4*)&Kt[lr][lc]     = k0;
        *(float4*)&Kt[lr][lc + 4] = k1;
        *(float4*)&Vt[lr][lc]     = v0;
        *(float4*)&Vt[lr][lc + 4] = v1;
        __syncthreads();

        #pragma unroll 8
        for (int ss = 0; ss < 32; ss++) {
            float4 ka = *(const float4*)&Kt[ss][ti * 4];
            float4 va = *(const float4*)&Vt[ss][tj * 4];
            float rk[4] = {ka.x, ka.y, ka.z, ka.w};
            float rv[4] = {va.x, va.y, va.z, va.w};
            #pragma unroll
            for (int a = 0; a < 4; a++)
                #pragma unroll
                for (int c = 0; c < 4; c++)
                    acc[a][c] += rk[a] * rv[c];
        }
    }

    const float scale = 0.125f;
    float* Mp = Mout + ((long)(b * Hh + h)) * HD * HD;
    #pragma unroll
    for (int a = 0; a < 4; a++) {
        const int i = ti * 4 + a;
        const float bki  = bk[h * HD + i];
        const float ckai = cka[b * Dd + h * HD + i];
        float4 vo;
        float* vp = &vo.x;
        #pragma unroll
        for (int c = 0; c < 4; c++) {
            const int j = tj * 4 + c;
            float corr = ckai * bv[h * HD + j]
                       + bki * cvb[b * Dd + h * HD + j]
                       + (float)Ssz * bki * bv[h * HD + j];
            vp[c] = scale * (acc[a][c] + corr);
        }
        *(float4*)&Mp[i * HD + tj * 4] = vo;
    }
}

// P^T hi/lo fp16 directly: rows r = h*64+row0+i, cols cc -> pT[cc][r]
__global__ void __launch_bounds__(256) P_kernel(
    const float* __restrict__ Mmat, const float* __restrict__ Wo,
    __half* __restrict__ pth, __half* __restrict__ ptl)
{
    const int nb = blockIdx.x;
    const int h  = blockIdx.y;
    const int b  = blockIdx.z;

    __shared__ float Ms[64][64];
    const float* Mp = Mmat + ((long)(b * Hh + h)) * HD * HD;
    for (int i = threadIdx.x; i < HD * HD; i += 256)
        Ms[i >> 6][i & 63] = Mp[i];
    __syncthreads();

    const int tid  = threadIdx.x;
    const int col  = nb * 128 + (tid & 31) * 4;
    const int row0 = (tid >> 5) * 8;

    float acc[8][4];
    #pragma unroll
    for (int i = 0; i < 8; i++)
        #pragma unroll
        for (int c = 0; c < 4; c++) acc[i][c] = 0.f;

    const float* Wp = Wo + (long)(h * HD) * Dd + col;
    #pragma unroll 8
    for (int j = 0; j < HD; j++) {
        float4 w = *(const float4*)(Wp + (long)j * Dd);
        #pragma unroll
        for (int i = 0; i < 8; i++) {
            float m = Ms[row0 + i][j];
            acc[i][0] += m * w.x;
            acc[i][1] += m * w.y;
            acc[i][2] += m * w.z;
            acc[i][3] += m * w.w;
        }
    }

    #pragma unroll
    for (int c = 0; c < 4; c++) {
        uint32_t hbuf[4], lbuf[4];
        #pragma unroll
        for (int i = 0; i < 8; i += 2) {
            float v0 = acc[i][c], v1 = acc[i + 1][c];
            __half h0 = __float2half_rn(v0);
            __half h1 = __float2half_rn(v1);
            __half2 hp; hp.x = h0; hp.y = h1;
            __half2 lp;
            lp.x = __float2half_rn(v0 - __half2float(h0));
            lp.y = __float2half_rn(v1 - __half2float(h1));
            hbuf[i >> 1] = *(uint32_t*)&hp;
            lbuf[i >> 1] = *(uint32_t*)&lp;
        }
        long o = (long)b * DD + (long)(col + c) * Dd + h * HD + row0;
        *(uint4*)(pth + o) = make_uint4(hbuf[0], hbuf[1], hbuf[2], hbuf[3]);
        *(uint4*)(ptl + o) = make_uint4(lbuf[0], lbuf[1], lbuf[2], lbuf[3]);
    }
}

// tv[b][h*64+j] = sum_i bq[h*64+i] * M[b,h,i,j]
__global__ void __launch_bounds__(64) tvec_kernel(
    const float* __restrict__ M, const float* __restrict__ bq,
    float* __restrict__ tv)
{
    const int h = blockIdx.x, b = blockIdx.y;
    const int j = threadIdx.x;
    const float* Mp = M + ((long)(b * Hh + h)) * HD * HD;
    float acc = 0.f;
    #pragma unroll 8
    for (int i = 0; i < HD; i++) acc += bq[h * HD + i] * Mp[i * HD + j];
    tv[b * Dd + h * HD + j] = acc;
}

// bbig[b][n] = sum_r tv[b][r]*Wo[r][n] + bo[n]
__global__ void __launch_bounds__(256) bbig2_kernel(
    const float* __restrict__ tv, const float* __restrict__ Wo,
    const float* __restrict__ bo, float* __restrict__ bbig)
{
    const int b = blockIdx.y;
    const int t = threadIdx.x;
    const int n = blockIdx.x * 64 + (t & 63);
    const int rs = t >> 6;
    float acc = 0.f;
    #pragma unroll 8
    for (int r = rs * 256; r < rs * 256 + 256; r++)
        acc += tv[b * Dd + r] * Wo[(long)r * Dd + n];
    __shared__ float sm[256];
    sm[t] = acc; __syncthreads();
    if (t < 64)
        bbig[b * Dd + n] = sm[t] + sm[t + 64] + sm[t + 128] + sm[t + 192] + bo[n];
}

// ===========================================================================
extern "C" void kernel_launch(void* const* d_in, const int* in_sizes, int n_in,
                              void* d_out, int out_size)
{
    const float* query = (const float*)d_in[0];
    const float* key   = (const float*)d_in[1];
    const float* value = (const float*)d_in[2];
    const float* Wq    = (const float*)d_in[3];
    const float* bq    = (const float*)d_in[4];
    const float* Wk    = (const float*)d_in[5];
    const float* bk    = (const float*)d_in[6];
    const float* Wv    = (const float*)d_in[7];
    const float* bv    = (const float*)d_in[8];
    const float* Wo    = (const float*)d_in[9];
    const float* bo    = (const float*)d_in[10];
    float* out = (float*)d_out;

    float *pT1, *pM, *pB, *pTv, *pKs, *pVs, *pKp, *pVp, *pCka, *pCvb;
    cudaGetSymbolAddress((void**)&pT1, g_T1);
    cudaGetSymbolAddress((void**)&pM,  g_M);
    cudaGetSymbolAddress((void**)&pB,  g_bbig);
    cudaGetSymbolAddress((void**)&pTv, g_tv);
    cudaGetSymbolAddress((void**)&pKs, g_ksum);
    cudaGetSymbolAddress((void**)&pVs, g_vsum);
    cudaGetSymbolAddress((void**)&pKp, g_kpart);
    cudaGetSymbolAddress((void**)&pVp, g_vpart);
    cudaGetSymbolAddress((void**)&pCka, g_cka);
    cudaGetSymbolAddress((void**)&pCvb, g_cvb);
    __half *qh, *ql, *kth, *ktl, *vth, *wqh, *wvth;
    __half *gh, *gl, *pth, *ptl, *wbth;
    cudaGetSymbolAddress((void**)&qh,  g_q_hi);  cudaGetSymbolAddress((void**)&ql,  g_q_lo);
    cudaGetSymbolAddress((void**)&kth, g_kT_hi); cudaGetSymbolAddress((void**)&ktl, g_kT_lo);
    cudaGetSymbolAddress((void**)&vth, g_vT_hi);
    cudaGetSymbolAddress((void**)&wqh, g_wq_hi);
    cudaGetSymbolAddress((void**)&wvth, g_wvT_hi);
    cudaGetSymbolAddress((void**)&gh,  g_G_hi);  cudaGetSymbolAddress((void**)&gl,  g_G_lo);
    cudaGetSymbolAddress((void**)&pth, g_pT_hi); cudaGetSymbolAddress((void**)&ptl, g_pT_lo);
    cudaGetSymbolAddress((void**)&wbth, g_wbT_hi);

    cudaFuncSetAttribute(gemm_tc, cudaFuncAttributeMaxDynamicSharedMemorySize, GEMM_SMEM);

    const long sBatch = (long)Ssz * Dd;

    // 1-3) query split (hi+lo); key (hi+lo+colsum); value (hi+colsum)
    split_kernel<<<GME / 1024, 256>>>(query, qh, ql, GME);
    splitT_kernel<<<dim3(Dd / 32, Ssz / 32, Bn), dim3(32, 8)>>>(
        key, sBatch, kth, ktl, sBatch, Ssz, Dd, pKp);
    splitT_kernel<<<dim3(Dd / 32, Ssz / 32, Bn), dim3(32, 8)>>>(
        value, sBatch, vth, nullptr, sBatch, Ssz, Dd, pVp);

    // 4) G_b = key_b^T @ value_b  (4th launch -> ncu profile); G hi/lo out
    gemm_tc<<<dim3(Dd / 128, Dd / 128, Bn), 256, GEMM_SMEM>>>(
        kth, ktl, sBatch, vth, sBatch, nullptr, 0,
        nullptr, gh, gl, (long)DD, Dd, Ssz);

    // 5-6) weight splits (hi only; they are B operands)
    split_kernel<<<DD / 1024, 256>>>(Wq, wqh, nullptr, DD);
    splitT_kernel<<<dim3(32, 32, 1), dim3(32, 8)>>>(
        Wv, 0, wvth, nullptr, 0, Dd, Dd, nullptr);

    // 7-9) colsum reduce + bias-correction matvecs
    colsum2_kernel<<<dim3(Dd / 256, Bn), 256>>>(pKp, pKs);
    colsum2_kernel<<<dim3(Dd / 256, Bn), 256>>>(pVp, pVs);
    corr_kernel<<<dim3(Dd / 128, Bn, 2), 256>>>(Wk, Wv, pKs, pVs, pCka, pCvb);

    // 10) T1_b = G_b @ Wv  (fp32 out)
    gemm_tc<<<dim3(Dd / 128, Dd / 128, Bn), 256, GEMM_SMEM>>>(
        gh, gl, (long)DD, wvth, 0, nullptr, 0,
        pT1, nullptr, nullptr, (long)DD, Dd, Dd);

    // 11) M diag blocks + bias corrections
    Mdiag_kernel<<<dim3(Hh, Bn), 256>>>(Wk, pT1, bk, bv, pCka, pCvb, pM);

    // 12-14) P (writes P^T hi/lo directly), t-vector, bbig
    P_kernel<<<dim3(Dd / 128, Hh, Bn), 256>>>(pM, Wo, pth, ptl);
    tvec_kernel<<<dim3(Hh, Bn), 64>>>(pM, bq, pTv);
    bbig2_kernel<<<dim3(Dd / 64, Bn), 256>>>(pTv, Wo, bo, pB);

    // 15) WbigT_b = P_b^T @ Wq^T  (hi-only out; it's the B of the out gemm)
    gemm_tc<<<dim3(Dd / 128, Dd / 128, Bn), 256, GEMM_SMEM>>>(
        pth, ptl, (long)DD, wqh, 0, nullptr, 0,
        nullptr, wbth, nullptr, (long)DD, Dd, Dd);

    // 16) out_b = query_b @ Wbig_b + bbig_b  (fp32 out)
    gemm_tc<<<dim3(Dd / 128, Ssz / 128, Bn), 256, GEMM_SMEM>>>(
        qh, ql, sBatch, wbth, (long)DD, pB, Dd,
        out, nullptr, nullptr, sBatch, Dd, Dd);
}

// round 11
// speedup vs baseline: 3.4023x; 1.1251x over previous
#include <cuda_runtime.h>
#include <cuda_fp16.h>
#include <cstdint>

// ===========================================================================
// MHA WITHOUT softmax == linear operator, fully re-associated:
//   G_b  = key_b^T @ value_b                         (mma.sync fp16 2-term)
//   T1_b = G_b @ Wv                                  (mma.sync fp16 2-term)
//   M_{b,h} = scale*( diag64(Wk^T T1)_h + rank-1 bias corrections )
//   PT_b = (stack_h(M_{b,h} @ Wo_h))^T               (SIMT, tiny, fused split)
//   WbigT_b = P_b^T @ Wq^T                           (mma.sync fp16 2-term)
//   bbig_b = (bq.M)^T @ Wo + bo                      (SIMT, tiny)
//   out_b = query_b @ Wbig_b + bbig_b                (mma.sync fp16 1-TERM)
// R11 == R10 resubmitted verbatim (R10 bench was a broker infra failure):
//      out-GEMM drops query-lo (HAS_LO=false template: 16 MMA/chunk);
//      Mdiag K-split x4 + deterministic reduce. Rest identical to R9.
// ===========================================================================

namespace {
constexpr int Bn  = 4;
constexpr int Ssz = 2048;
constexpr int Dd  = 1024;
constexpr int Hh  = 16;
constexpr int HD  = 64;
constexpr int GME = Bn * Ssz * Dd;
constexpr int DD  = Dd * Dd;
constexpr int MSEG = 4;              // Mdiag K-split factor
}

// ------------------------- scratch (device globals) ------------------------
__device__ float g_T1[(size_t)Bn * DD];
__device__ float g_M[Bn * Hh * HD * HD];
__device__ float g_Mpart[(size_t)MSEG * Bn * Hh * HD * HD];
__device__ float g_bbig[Bn * Dd];
__device__ float g_tv[Bn * Dd];
__device__ float g_ksum[Bn * Dd], g_vsum[Bn * Dd];
__device__ float g_kpart[(size_t)Bn * 64 * Dd], g_vpart[(size_t)Bn * 64 * Dd];
__device__ float g_cka[Bn * Dd], g_cvb[Bn * Dd];

__device__ __half g_q_hi[GME];                        // A of out-gemm: hi ONLY
__device__ __half g_kT_hi[GME], g_kT_lo[GME];
__device__ __half g_vT_hi[GME];                       // B operand: hi only
__device__ __half g_wq_hi[DD];                        // B operand: hi only
__device__ __half g_wvT_hi[DD];                       // B operand: hi only
__device__ __half g_G_hi[(size_t)Bn * DD], g_G_lo[(size_t)Bn * DD];
__device__ __half g_pT_hi[(size_t)Bn * DD], g_pT_lo[(size_t)Bn * DD];
__device__ __half g_wbT_hi[(size_t)Bn * DD];          // B operand: hi only

// ------------------------------ PTX helpers --------------------------------
__device__ __forceinline__ uint32_t smem_u32(const void* p) {
    uint32_t a;
    asm("{ .reg .u64 t; cvta.to.shared.u64 t, %1; cvt.u32.u64 %0, t; }"
        : "=r"(a) : "l"(p));
    return a;
}

#define LDSM4(r, addr)                                                        \
    asm volatile("ldmatrix.sync.aligned.m8n8.x4.shared.b16 "                  \
                 "{%0,%1,%2,%3}, [%4];"                                       \
                 : "=r"((r)[0]), "=r"((r)[1]), "=r"((r)[2]), "=r"((r)[3])     \
                 : "r"(addr))

#define MMA_F16(d, a, b)                                                      \
    asm volatile("mma.sync.aligned.m16n8k16.row.col.f32.f16.f16.f32 "         \
                 "{%0,%1,%2,%3}, {%4,%5,%6,%7}, {%8,%9}, {%0,%1,%2,%3};"      \
                 : "+f"((d)[0]), "+f"((d)[1]), "+f"((d)[2]), "+f"((d)[3])     \
                 : "r"((a)[0]), "r"((a)[1]), "r"((a)[2]), "r"((a)[3]),        \
                   "r"((b)[0]), "r"((b)[1]))

#define CP_ASYNC16(dst, src)                                                  \
    asm volatile("cp.async.cg.shared.global [%0], [%1], 16;"                  \
                 :: "r"(dst), "l"(src))
#define CP_COMMIT()  asm volatile("cp.async.commit_group;")
#define CP_WAIT1()   asm volatile("cp.async.wait_group 1;")
#define CP_WAIT0()   asm volatile("cp.async.wait_group 0;")

// ===========================================================================
// Tensor-core GEMM: C[M,N] = A[M,K] @ Bt[N,K]^T (+ bias[n]).
// fp16 asymmetric split (A hi[/lo], B hi). 128x128 tile, K-chunk 32,
// 3-stage cp.async pipeline, single __syncthreads per chunk.
// HAS_LO=false: single-term A (plain fp16 A), 16 MMAs/chunk.
// ===========================================================================
namespace {
constexpr int TILE_B      = 128 * 32 * 2;          // 8 KB per fp16 tile
constexpr int STAGE_BYTES = 3 * TILE_B;            // Ahi, Alo, Bh = 24 KB
constexpr int STAGES      = 3;
constexpr int GEMM_SMEM   = STAGES * STAGE_BYTES;  // 72 KB
}

template <bool HAS_LO>
__global__ void __launch_bounds__(256, 2) gemm_tc(
    const __half* __restrict__ Ahi, const __half* __restrict__ Alo, long sA,
    const __half* __restrict__ Bh, long sB,
    const float* __restrict__ bias, long sBias,
    float* __restrict__ Cf,
    __half* __restrict__ Chi, __half* __restrict__ Clo,
    long sC, int Ndim, int Kdim)
{
    extern __shared__ char smem[];
    const uint32_t sb = smem_u32(smem);
    const int tid = threadIdx.x;
    const int wid = tid >> 5;
    const int l   = tid & 31;
    const int zb  = blockIdx.z;

    Ahi += (long)zb * sA;
    if (HAS_LO) Alo += (long)zb * sA;
    Bh  += (long)zb * sB;
    if (bias) bias += (long)zb * sBias;

    const int m0 = blockIdx.y * 128;
    const int n0 = blockIdx.x * 128;
    const int NC = Kdim >> 5;

    const int r0i = (tid * 2) >> 2, c40 = (tid * 2) & 3;
    const int r1i = (tid * 2 + 1) >> 2, c41 = (tid * 2 + 1) & 3;
    const __half* gsrc[3] = {
        Ahi + (long)m0 * Kdim,
        HAS_LO ? (Alo + (long)m0 * Kdim) : nullptr,
        Bh + (long)n0 * Kdim };

    const uint32_t so0 = r0i * 64 + ((c40 ^ ((r0i >> 1) & 3)) << 4);
    const uint32_t so1 = r1i * 64 + ((c41 ^ ((r1i >> 1) & 3)) << 4);

    auto issue_stage = [&](int s, int c) {
        const uint32_t base = sb + s * STAGE_BYTES;
        #pragma unroll
        for (int t = 0; t < 3; t++) {
            if (!HAS_LO && t == 1) continue;
            CP_ASYNC16(base + t * TILE_B + so0,
                       gsrc[t] + (long)r0i * Kdim + c * 32 + c40 * 8);
            CP_ASYNC16(base + t * TILE_B + so1,
                       gsrc[t] + (long)r1i * Kdim + c * 32 + c41 * 8);
        }
    };

    issue_stage(0, 0); CP_COMMIT();
    issue_stage(1, 1); CP_COMMIT();

    const int wm = wid & 3;
    const int wn = wid >> 2;

    float acc[2][8][4];
    #pragma unroll
    for (int i = 0; i < 2; i++)
        #pragma unroll
        for (int j = 0; j < 8; j++)
            #pragma unroll
            for (int q = 0; q < 4; q++) acc[i][j][q] = 0.f;

    uint32_t aoff[2][2], boff[2][4];
    #pragma unroll
    for (int ks = 0; ks < 2; ks++) {
        #pragma unroll
        for (int i = 0; i < 2; i++) {
            int row = wm * 32 + i * 16 + (l & 15);
            int c4  = ks * 2 + (l >> 4);
            aoff[ks][i] = row * 64 + ((c4 ^ ((row >> 1) & 3)) << 4);
        }
        #pragma unroll
        for (int p = 0; p < 4; p++) {
            int row = wn * 64 + p * 16 + (l & 7) + ((l & 16) >> 1);
            int c4  = ks * 2 + ((l >> 3) & 1);
            boff[ks][p] = row * 64 + ((c4 ^ ((row >> 1) & 3)) << 4);
        }
    }

    for (int c = 0; c < NC; c++) {
        if (c + 1 < NC) { CP_WAIT1(); } else { CP_WAIT0(); }
        __syncthreads();     // single sync: orders compute(c-1) before the
                             // issue below overwrites stage (c+2)%3
        if (c + 2 < NC) { issue_stage((c + 2) % STAGES, c + 2); CP_COMMIT(); }

        const uint32_t base = sb + (c % STAGES) * STAGE_BYTES;
        #pragma unroll
        for (int ks = 0; ks < 2; ks++) {
            uint32_t ah[2][4], al[2][4];
            #pragma unroll
            for (int i = 0; i < 2; i++) {
                LDSM4(ah[i], base + aoff[ks][i]);
                if (HAS_LO) LDSM4(al[i], base + TILE_B + aoff[ks][i]);
            }
            // B double buffer: LDSM for p+1 issued before MMAs of p consume
            uint32_t rh[2][4];
            LDSM4(rh[0], base + 2 * TILE_B + boff[ks][0]);
            #pragma unroll
            for (int p = 0; p < 4; p++) {
                const int cur = p & 1, nxt = cur ^ 1;
                if (p < 3) LDSM4(rh[nxt], base + 2 * TILE_B + boff[ks][p + 1]);
                #pragma unroll
                for (int i = 0; i < 2; i++) {
                    MMA_F16(acc[i][2*p],     ah[i], rh[cur]);
                    if (HAS_LO) MMA_F16(acc[i][2*p], al[i], rh[cur]);
                    MMA_F16(acc[i][2*p + 1], ah[i], rh[cur] + 2);
                    if (HAS_LO) MMA_F16(acc[i][2*p + 1], al[i], rh[cur] + 2);
                }
            }
        }
    }

    const int mr = m0 + wm * 32 + (l >> 2);
    const int nc = n0 + wn * 64 + (l & 3) * 2;
    #pragma unroll
    for (int i = 0; i < 2; i++) {
        #pragma unroll
        for (int j = 0; j < 8; j++) {
            const int rr = mr + i * 16;
            const int cc = nc + j * 8;
            if (Cf) {
                float b0 = bias ? bias[cc] : 0.f;
                float b1 = bias ? bias[cc + 1] : 0.f;
                float2* p0 = (float2*)(Cf + (long)zb * sC + (long)rr * Ndim + cc);
                float2* p1 = (float2*)(Cf + (long)zb * sC + (long)(rr + 8) * Ndim + cc);
                *p0 = make_float2(acc[i][j][0] + b0, acc[i][j][1] + b1);
                *p1 = make_float2(acc[i][j][2] + b0, acc[i][j][3] + b1);
            } else {
                float v0 = acc[i][j][0], v1 = acc[i][j][1];
                float v2 = acc[i][j][2], v3 = acc[i][j][3];
                __half h0 = __float2half_rn(v0), h1 = __float2half_rn(v1);
                __half h2 = __float2half_rn(v2), h3 = __float2half_rn(v3);
                long o0 = (long)zb * sC + (long)rr * Ndim + cc;
                long o1 = (long)zb * sC + (long)(rr + 8) * Ndim + cc;
                __half2 hp;
                hp.x = h0; hp.y = h1;
                *(__half2*)(Chi + o0) = hp;
                hp.x = h2; hp.y = h3;
                *(__half2*)(Chi + o1) = hp;
                if (Clo) {
                    __half2 lp;
                    lp.x = __float2half_rn(v0 - __half2float(h0));
                    lp.y = __float2half_rn(v1 - __half2float(h1));
                    *(__half2*)(Clo + o0) = lp;
                    lp.x = __float2half_rn(v2 - __half2float(h2));
                    lp.y = __float2half_rn(v3 - __half2float(h3));
                    *(__half2*)(Clo + o1) = lp;
                }
            }
        }
    }
}

// ===========================================================================
// small kernels
// ===========================================================================

// elementwise fp32 -> fp16 hi (+ optional lo)
__global__ void __launch_bounds__(256) split_kernel(
    const float* __restrict__ in, __half* __restrict__ hi,
    __half* __restrict__ lo, int n)
{
    int i = (blockIdx.x * 256 + threadIdx.x) * 4;
    if (i >= n) return;
    float4 x = *(const float4*)(in + i);
    float xs[4] = {x.x, x.y, x.z, x.w};
    __half h[4];
    #pragma unroll
    for (int k = 0; k < 4; k++) h[k] = __float2half_rn(xs[k]);
    __half2 h01; h01.x = h[0]; h01.y = h[1];
    __half2 h23; h23.x = h[2]; h23.y = h[3];
    *(__half2*)(hi + i)     = h01;
    *(__half2*)(hi + i + 2) = h23;
    if (lo) {
        __half2 l01, l23;
        l01.x = __float2half_rn(xs[0] - __half2float(h[0]));
        l01.y = __float2half_rn(xs[1] - __half2float(h[1]));
        l23.x = __float2half_rn(xs[2] - __half2float(h[2]));
        l23.y = __float2half_rn(xs[3] - __half2float(h[3]));
        *(__half2*)(lo + i)     = l01;
        *(__half2*)(lo + i + 2) = l23;
    }
}

// transpose + split (+ optional lo, optional per-block column partial sums)
__global__ void __launch_bounds__(256) splitT_kernel(
    const float* __restrict__ in, long sIn,
    __half* __restrict__ hi, __half* __restrict__ lo, long sOut,
    int R, int C, float* __restrict__ part)
{
    __shared__ float t[32][33];
    __shared__ float ps[8][32];
    in += (long)blockIdx.z * sIn;
    hi += (long)blockIdx.z * sOut;
    if (lo) lo += (long)blockIdx.z * sOut;
    const int c0 = blockIdx.x * 32;
    const int r0 = blockIdx.y * 32;
    const int tx = threadIdx.x, ty = threadIdx.y;
    float acc = 0.f;
    for (int k = ty; k < 32; k += 8) {
        float v = in[(long)(r0 + k) * C + c0 + tx];
        t[k][tx] = v;
        acc += v;
    }
    if (part) ps[ty][tx] = acc;
    __syncthreads();
    if (part && ty == 0) {
        float s = ps[0][tx] + ps[1][tx] + ps[2][tx] + ps[3][tx]
                + ps[4][tx] + ps[5][tx] + ps[6][tx] + ps[7][tx];
        part[((long)blockIdx.z * gridDim.y + blockIdx.y) * C + c0 + tx] = s;
    }
    for (int k = ty; k < 32; k += 8) {
        float vv = t[tx][k];
        __half h = __float2half_rn(vv);
        long o = (long)(c0 + k) * R + r0 + tx;
        hi[o] = h;
        if (lo) lo[o] = __float2half_rn(vv - __half2float(h));
    }
}

// reduce 64 partials -> colsum
__global__ void __launch_bounds__(256) colsum2_kernel(
    const float* __restrict__ part, float* __restrict__ out)
{
    const int b = blockIdx.y;
    const int d = blockIdx.x * 256 + threadIdx.x;
    float s = 0.f;
    #pragma unroll 8
    for (int k = 0; k < 64; k++) s += part[((long)b * 64 + k) * Dd + d];
    out[b * Dd + d] = s;
}

// cka[b][i] = sum_d Wk[d][i]*ksum[b][d] ; cvb likewise (z selects)
__global__ void __launch_bounds__(256) corr_kernel(
    const float* __restrict__ Wk, const float* __restrict__ Wv,
    const float* __restrict__ ksum, const float* __restrict__ vsum,
    float* __restrict__ cka, float* __restrict__ cvb)
{
    const int b = blockIdx.y;
    const float* W = blockIdx.z ? Wv : Wk;
    const float* s = (blockIdx.z ? vsum : ksum) + b * Dd;
    float* o = (blockIdx.z ? cvb : cka) + b * Dd;
    const int t = threadIdx.x;
    const int i = blockIdx.x * 128 + (t & 127);
    const int half = t >> 7;
    float acc = 0.f;
    #pragma unroll 8
    for (int d = half * 512; d < half * 512 + 512; d++)
        acc += W[(long)d * Dd + i] * s[d];
    __shared__ float sm[256];
    sm[t] = acc; __syncthreads();
    if (t < 128) o[i] = sm[t] + sm[t + 128];
}

// Mdiag partial: Mpart[seg][b,h][i][j] = sum_{d in seg} Wk[d,h64+i]*T1[b][d][h64+j]
__global__ void __launch_bounds__(256) Mdiag_part_kernel(
    const float* __restrict__ Wk, const float* __restrict__ T1,
    float* __restrict__ Mpart)
{
    const int h = blockIdx.x;
    const int b = blockIdx.y;
    const int seg = blockIdx.z;
    const float* Kp = Wk + h * HD;
    const float* Tp = T1 + (long)b * DD + h * HD;
    const int d_begin = seg * (Dd / MSEG);
    const int d_end   = d_begin + (Dd / MSEG);

    __shared__ float Kt[32][64];
    __shared__ float Vt[32][64];

    const int tid = threadIdx.x;
    const int ti = tid & 15;
    const int tj = tid >> 4;
    const int lr = tid >> 3;
    const int lc = (tid & 7) * 8;

    float acc[4][4];
    #pragma unroll
    for (int a = 0; a < 4; a++)
        #pragma unroll
        for (int c = 0; c < 4; c++) acc[a][c] = 0.f;

    for (int d0 = d_begin; d0 < d_end; d0 += 32) {
        const float* kp = Kp + (long)(d0 + lr) * Dd + lc;
        const float* vp = Tp + (long)(d0 + lr) * Dd + lc;
        float4 k0 = *(const float4*)kp;
        float4 k1 = *(const float4*)(kp + 4);
        float4 v0 = *(const float4*)vp;
        float4 v1 = *(const float4*)(vp + 4);
        __syncthreads();
        *(float4*)&Kt[lr][lc]     = k0;
        *(float4*)&Kt[lr][lc + 4] = k1;
        *(float4*)&Vt[lr][lc]     = v0;
        *(float4*)&Vt[lr][lc + 4] = v1;
        __syncthreads();

        #pragma unroll 8
        for (int ss = 0; ss < 32; ss++) {
            float4 ka = *(const float4*)&Kt[ss][ti * 4];
            float4 va = *(const float4*)&Vt[ss][tj * 4];
            float rk[4] = {ka.x, ka.y, ka.z, ka.w};
            float rv[4] = {va.x, va.y, va.z, va.w};
            #pragma unroll
            for (int a = 0; a < 4; a++)
                #pragma unroll
                for (int c = 0; c < 4; c++)
                    acc[a][c] += rk[a] * rv[c];
        }
    }

    float* Mp = Mpart + ((long)seg * Bn * Hh + (long)(b * Hh + h)) * (HD * HD);
    #pragma unroll
    for (int a = 0; a < 4; a++) {
        float4 vo = make_float4(acc[a][0], acc[a][1], acc[a][2], acc[a][3]);
        *(float4*)&Mp[(ti * 4 + a) * HD + tj * 4] = vo;
    }
}

// Mdiag reduce (+ bias corrections + scale): deterministic fixed-order sum
__global__ void __launch_bounds__(256) Mdiag_red_kernel(
    const float* __restrict__ Mpart,
    const float* __restrict__ bk, const float* __restrict__ bv,
    const float* __restrict__ cka, const float* __restrict__ cvb,
    float* __restrict__ Mout)
{
    const int h = blockIdx.x;
    const int b = blockIdx.y;
    const int t = threadIdx.x;
    const long bh = (long)(b * Hh + h);
    const long blkSz = (long)HD * HD;

    const int i  = t >> 2;            // row 0..63
    const int j0 = (t & 3) * 16;      // 16 contiguous cols

    const float bki  = bk[h * HD + i];
    const float ckai = cka[b * Dd + h * HD + i];
    const float scale = 0.125f;

    #pragma unroll
    for (int q = 0; q < 4; q++) {
        const int j = j0 + q * 4;
        const long e = (long)i * HD + j;
        float4 s = *(const float4*)&Mpart[(0 * (long)Bn * Hh + bh) * blkSz + e];
        #pragma unroll
        for (int g = 1; g < MSEG; g++) {
            float4 p = *(const float4*)&Mpart[((long)g * Bn * Hh + bh) * blkSz + e];
            s.x += p.x; s.y += p.y; s.z += p.z; s.w += p.w;
        }
        float* sv = &s.x;
        float4 vo;
        float* vp = &vo.x;
        #pragma unroll
        for (int c = 0; c < 4; c++) {
            const int jj = j + c;
            float corr = ckai * bv[h * HD + jj]
                       + bki * cvb[b * Dd + h * HD + jj]
                       + (float)Ssz * bki * bv[h * HD + jj];
            vp[c] = scale * (sv[c] + corr);
        }
        *(float4*)&Mout[bh * blkSz + e] = vo;
    }
}

// P^T hi/lo fp16 directly: rows r = h*64+row0+i, cols cc -> pT[cc][r]
__global__ void __launch_bounds__(256) P_kernel(
    const float* __restrict__ Mmat, const float* __restrict__ Wo,
    __half* __restrict__ pth, __half* __restrict__ ptl)
{
    const int nb = blockIdx.x;
    const int h  = blockIdx.y;
    const int b  = blockIdx.z;

    __shared__ float Ms[64][64];
    const float* Mp = Mmat + ((long)(b * Hh + h)) * HD * HD;
    for (int i = threadIdx.x; i < HD * HD; i += 256)
        Ms[i >> 6][i & 63] = Mp[i];
    __syncthreads();

    const int tid  = threadIdx.x;
    const int col  = nb * 128 + (tid & 31) * 4;
    const int row0 = (tid >> 5) * 8;

    float acc[8][4];
    #pragma unroll
    for (int i = 0; i < 8; i++)
        #pragma unroll
        for (int c = 0; c < 4; c++) acc[i][c] = 0.f;

    const float* Wp = Wo + (long)(h * HD) * Dd + col;
    #pragma unroll 8
    for (int j = 0; j < HD; j++) {
        float4 w = *(const float4*)(Wp + (long)j * Dd);
        #pragma unroll
        for (int i = 0; i < 8; i++) {
            float m = Ms[row0 + i][j];
            acc[i][0] += m * w.x;
            acc[i][1] += m * w.y;
            acc[i][2] += m * w.z;
            acc[i][3] += m * w.w;
        }
    }

    #pragma unroll
    for (int c = 0; c < 4; c++) {
        uint32_t hbuf[4], lbuf[4];
        #pragma unroll
        for (int i = 0; i < 8; i += 2) {
            float v0 = acc[i][c], v1 = acc[i + 1][c];
            __half h0 = __float2half_rn(v0);
            __half h1 = __float2half_rn(v1);
            __half2 hp; hp.x = h0; hp.y = h1;
            __half2 lp;
            lp.x = __float2half_rn(v0 - __half2float(h0));
            lp.y = __float2half_rn(v1 - __half2float(h1));
            hbuf[i >> 1] = *(uint32_t*)&hp;
            lbuf[i >> 1] = *(uint32_t*)&lp;
        }
        long o = (long)b * DD + (long)(col + c) * Dd + h * HD + row0;
        *(uint4*)(pth + o) = make_uint4(hbuf[0], hbuf[1], hbuf[2], hbuf[3]);
        *(uint4*)(ptl + o) = make_uint4(lbuf[0], lbuf[1], lbuf[2], lbuf[3]);
    }
}

// tv[b][h*64+j] = sum_i bq[h*64+i] * M[b,h,i,j]
__global__ void __launch_bounds__(64) tvec_kernel(
    const float* __restrict__ M, const float* __restrict__ bq,
    float* __restrict__ tv)
{
    const int h = blockIdx.x, b = blockIdx.y;
    const int j = threadIdx.x;
    const float* Mp = M + ((long)(b * Hh + h)) * HD * HD;
    float acc = 0.f;
    #pragma unroll 8
    for (int i = 0; i < HD; i++) acc += bq[h * HD + i] * Mp[i * HD + j];
    tv[b * Dd + h * HD + j] = acc;
}

// bbig[b][n] = sum_r tv[b][r]*Wo[r][n] + bo[n]
__global__ void __launch_bounds__(256) bbig2_kernel(
    const float* __restrict__ tv, const float* __restrict__ Wo,
    const float* __restrict__ bo, float* __restrict__ bbig)
{
    const int b = blockIdx.y;
    const int t = threadIdx.x;
    const int n = blockIdx.x * 64 + (t & 63);
    const int rs = t >> 6;
    float acc = 0.f;
    #pragma unroll 8
    for (int r = rs * 256; r < rs * 256 + 256; r++)
        acc += tv[b * Dd + r] * Wo[(long)r * Dd + n];
    __shared__ float sm[256];
    sm[t] = acc; __syncthreads();
    if (t < 64)
        bbig[b * Dd + n] = sm[t] + sm[t + 64] + sm[t + 128] + sm[t + 192] + bo[n];
}

// ===========================================================================
extern "C" void kernel_launch(void* const* d_in, const int* in_sizes, int n_in,
                              void* d_out, int out_size)
{
    const float* query = (const float*)d_in[0];
    const float* key   = (const float*)d_in[1];
    const float* value = (const float*)d_in[2];
    const float* Wq    = (const float*)d_in[3];
    const float* bq    = (const float*)d_in[4];
    const float* Wk    = (const float*)d_in[5];
    const float* bk    = (const float*)d_in[6];
    const float* Wv    = (const float*)d_in[7];
    const float* bv    = (const float*)d_in[8];
    const float* Wo    = (const float*)d_in[9];
    const float* bo    = (const float*)d_in[10];
    float* out = (float*)d_out;

    float *pT1, *pM, *pMp, *pB, *pTv, *pKs, *pVs, *pKp, *pVp, *pCka, *pCvb;
    cudaGetSymbolAddress((void**)&pT1, g_T1);
    cudaGetSymbolAddress((void**)&pM,  g_M);
    cudaGetSymbolAddress((void**)&pMp, g_Mpart);
    cudaGetSymbolAddress((void**)&pB,  g_bbig);
    cudaGetSymbolAddress((void**)&pTv, g_tv);
    cudaGetSymbolAddress((void**)&pKs, g_ksum);
    cudaGetSymbolAddress((void**)&pVs, g_vsum);
    cudaGetSymbolAddress((void**)&pKp, g_kpart);
    cudaGetSymbolAddress((void**)&pVp, g_vpart);
    cudaGetSymbolAddress((void**)&pCka, g_cka);
    cudaGetSymbolAddress((void**)&pCvb, g_cvb);
    __half *qh, *kth, *ktl, *vth, *wqh, *wvth;
    __half *gh, *gl, *pth, *ptl, *wbth;
    cudaGetSymbolAddress((void**)&qh,  g_q_hi);
    cudaGetSymbolAddress((void**)&kth, g_kT_hi); cudaGetSymbolAddress((void**)&ktl, g_kT_lo);
    cudaGetSymbolAddress((void**)&vth, g_vT_hi);
    cudaGetSymbolAddress((void**)&wqh, g_wq_hi);
    cudaGetSymbolAddress((void**)&wvth, g_wvT_hi);
    cudaGetSymbolAddress((void**)&gh,  g_G_hi);  cudaGetSymbolAddress((void**)&gl,  g_G_lo);
    cudaGetSymbolAddress((void**)&pth, g_pT_hi); cudaGetSymbolAddress((void**)&ptl, g_pT_lo);
    cudaGetSymbolAddress((void**)&wbth, g_wbT_hi);

    cudaFuncSetAttribute(gemm_tc<true>,
                         cudaFuncAttributeMaxDynamicSharedMemorySize, GEMM_SMEM);
    cudaFuncSetAttribute(gemm_tc<false>,
                         cudaFuncAttributeMaxDynamicSharedMemorySize, GEMM_SMEM);

    const long sBatch = (long)Ssz * Dd;

    // 1-3) query split (hi only); key (hi+lo+colsum); value (hi+colsum)
    split_kernel<<<GME / 1024, 256>>>(query, qh, nullptr, GME);
    splitT_kernel<<<dim3(Dd / 32, Ssz / 32, Bn), dim3(32, 8)>>>(
        key, sBatch, kth, ktl, sBatch, Ssz, Dd, pKp);
    splitT_kernel<<<dim3(Dd / 32, Ssz / 32, Bn), dim3(32, 8)>>>(
        value, sBatch, vth, nullptr, sBatch, Ssz, Dd, pVp);

    // 4) G_b = key_b^T @ value_b  (4th launch -> ncu profile; control)
    gemm_tc<true><<<dim3(Dd / 128, Dd / 128, Bn), 256, GEMM_SMEM>>>(
        kth, ktl, sBatch, vth, sBatch, nullptr, 0,
        nullptr, gh, gl, (long)DD, Dd, Ssz);

    // 5-6) weight splits (hi only; they are B operands)
    split_kernel<<<DD / 1024, 256>>>(Wq, wqh, nullptr, DD);
    splitT_kernel<<<dim3(32, 32, 1), dim3(32, 8)>>>(
        Wv, 0, wvth, nullptr, 0, Dd, Dd, nullptr);

    // 7-9) colsum reduce + bias-correction matvecs
    colsum2_kernel<<<dim3(Dd / 256, Bn), 256>>>(pKp, pKs);
    colsum2_kernel<<<dim3(Dd / 256, Bn), 256>>>(pVp, pVs);
    corr_kernel<<<dim3(Dd / 128, Bn, 2), 256>>>(Wk, Wv, pKs, pVs, pCka, pCvb);

    // 10) T1_b = G_b @ Wv  (fp32 out)
    gemm_tc<true><<<dim3(Dd / 128, Dd / 128, Bn), 256, GEMM_SMEM>>>(
        gh, gl, (long)DD, wvth, 0, nullptr, 0,
        pT1, nullptr, nullptr, (long)DD, Dd, Dd);

    // 11) M diag blocks: K-split x4 partials + deterministic reduce w/ corr
    Mdiag_part_kernel<<<dim3(Hh, Bn, MSEG), 256>>>(Wk, pT1, pMp);
    Mdiag_red_kernel<<<dim3(Hh, Bn), 256>>>(pMp, bk, bv, pCka, pCvb, pM);

    // 12-14) P (writes P^T hi/lo directly), t-vector, bbig
    P_kernel<<<dim3(Dd / 128, Hh, Bn), 256>>>(pM, Wo, pth, ptl);
    tvec_kernel<<<dim3(Hh, Bn), 64>>>(pM, bq, pTv);
    bbig2_kernel<<<dim3(Dd / 64, Bn), 256>>>(pTv, Wo, bo, pB);

    // 15) WbigT_b = P_b^T @ Wq^T  (hi-only out; it's the B of the out gemm)
    gemm_tc<true><<<dim3(Dd / 128, Dd / 128, Bn), 256, GEMM_SMEM>>>(
        pth, ptl, (long)DD, wqh, 0, nullptr, 0,
        nullptr, wbth, nullptr, (long)DD, Dd, Dd);

    // 16) out_b = query_b @ Wbig_b + bbig_b  (fp32 out; SINGLE-term A)
    gemm_tc<false><<<dim3(Dd / 128, Ssz / 128, Bn), 256, GEMM_SMEM>>>(
        qh, nullptr, sBatch, wbth, (long)DD, pB, Dd,
        out, nullptr, nullptr, sBatch, Dd, Dd);
}

// round 14
// speedup vs baseline: 4.2319x; 1.2438x over previous
#include <cuda_runtime.h>
#include <cuda_fp16.h>
#include <cstdint>

// ===========================================================================
// MHA WITHOUT softmax == linear operator, fully re-associated:
//   G_b  = key_b^T @ value_b                         (mma.sync fp16 1-term)
//   T1_b = G_b @ Wv                                  (mma.sync fp16 1-term)
//   M_{b,h} = scale*( diag64(Wk^T T1)_h + rank-1 bias corrections )
//   PT_b = (stack_h(M_{b,h} @ Wo_h))^T               (SIMT, tiny, fused split)
//   WbigT_b = P_b^T @ Wq^T                           (mma.sync fp16 1-term)
//   bbig_b = (bq.M)^T @ Wo + bo                      (SIMT, tiny)
//   out_b = query_b @ Wbig_b + bbig_b                (mma.sync fp16 1-term)
// R14: same semantics as R12/R13 (all GEMMs single-term fp16; calibrated
//      error model 8 x 1.96e-4 quadrature ~ 5.5e-4) but using R11's exact
//      template<bool HAS_LO> gemm skeleton (the last broker-run binary
//      structure); all call sites use HAS_LO=false with nullptr lo planes.
// ===========================================================================

namespace {
constexpr int Bn  = 4;
constexpr int Ssz = 2048;
constexpr int Dd  = 1024;
constexpr int Hh  = 16;
constexpr int HD  = 64;
constexpr int GME = Bn * Ssz * Dd;
constexpr int DD  = Dd * Dd;
constexpr int MSEG = 4;              // Mdiag K-split factor
}

// ------------------------- scratch (device globals) ------------------------
__device__ float g_T1[(size_t)Bn * DD];
__device__ float g_M[Bn * Hh * HD * HD];
__device__ float g_Mpart[(size_t)MSEG * Bn * Hh * HD * HD];
__device__ float g_bbig[Bn * Dd];
__device__ float g_tv[Bn * Dd];
__device__ float g_ksum[Bn * Dd], g_vsum[Bn * Dd];
__device__ float g_kpart[(size_t)Bn * 64 * Dd], g_vpart[(size_t)Bn * 64 * Dd];
__device__ float g_cka[Bn * Dd], g_cvb[Bn * Dd];

__device__ __half g_q_hi[GME];
__device__ __half g_kT_hi[GME];
__device__ __half g_vT_hi[GME];
__device__ __half g_wq_hi[DD];
__device__ __half g_wvT_hi[DD];
__device__ __half g_G_hi[(size_t)Bn * DD];
__device__ __half g_pT_hi[(size_t)Bn * DD];
__device__ __half g_wbT_hi[(size_t)Bn * DD];

// ------------------------------ PTX helpers --------------------------------
__device__ __forceinline__ uint32_t smem_u32(const void* p) {
    uint32_t a;
    asm("{ .reg .u64 t; cvta.to.shared.u64 t, %1; cvt.u32.u64 %0, t; }"
        : "=r"(a) : "l"(p));
    return a;
}

#define LDSM4(r, addr)                                                        \
    asm volatile("ldmatrix.sync.aligned.m8n8.x4.shared.b16 "                  \
                 "{%0,%1,%2,%3}, [%4];"                                       \
                 : "=r"((r)[0]), "=r"((r)[1]), "=r"((r)[2]), "=r"((r)[3])     \
                 : "r"(addr))

#define MMA_F16(d, a, b)                                                      \
    asm volatile("mma.sync.aligned.m16n8k16.row.col.f32.f16.f16.f32 "         \
                 "{%0,%1,%2,%3}, {%4,%5,%6,%7}, {%8,%9}, {%0,%1,%2,%3};"      \
                 : "+f"((d)[0]), "+f"((d)[1]), "+f"((d)[2]), "+f"((d)[3])     \
                 : "r"((a)[0]), "r"((a)[1]), "r"((a)[2]), "r"((a)[3]),        \
                   "r"((b)[0]), "r"((b)[1]))

#define CP_ASYNC16(dst, src)                                                  \
    asm volatile("cp.async.cg.shared.global [%0], [%1], 16;"                  \
                 :: "r"(dst), "l"(src))
#define CP_COMMIT()  asm volatile("cp.async.commit_group;")
#define CP_WAIT1()   asm volatile("cp.async.wait_group 1;")
#define CP_WAIT0()   asm volatile("cp.async.wait_group 0;")

// ===========================================================================
// Tensor-core GEMM: C[M,N] = A[M,K] @ Bt[N,K]^T (+ bias[n]).
// fp16 asymmetric split (A hi[/lo], B hi). 128x128 tile, K-chunk 32,
// 3-stage cp.async pipeline, single __syncthreads per chunk.
// HAS_LO=false: single-term A (plain fp16 A), 16 MMAs/chunk.
// (Template skeleton identical to the R11 binary that the broker ran.)
// ===========================================================================
namespace {
constexpr int TILE_B      = 128 * 32 * 2;          // 8 KB per fp16 tile
constexpr int STAGE_BYTES = 3 * TILE_B;            // Ahi, Alo, Bh = 24 KB
constexpr int STAGES      = 3;
constexpr int GEMM_SMEM   = STAGES * STAGE_BYTES;  // 72 KB
}

template <bool HAS_LO>
__global__ void __launch_bounds__(256, 2) gemm_tc(
    const __half* __restrict__ Ahi, const __half* __restrict__ Alo, long sA,
    const __half* __restrict__ Bh, long sB,
    const float* __restrict__ bias, long sBias,
    float* __restrict__ Cf,
    __half* __restrict__ Chi, __half* __restrict__ Clo,
    long sC, int Ndim, int Kdim)
{
    extern __shared__ char smem[];
    const uint32_t sb = smem_u32(smem);
    const int tid = threadIdx.x;
    const int wid = tid >> 5;
    const int l   = tid & 31;
    const int zb  = blockIdx.z;

    Ahi += (long)zb * sA;
    if (HAS_LO) Alo += (long)zb * sA;
    Bh  += (long)zb * sB;
    if (bias) bias += (long)zb * sBias;

    const int m0 = blockIdx.y * 128;
    const int n0 = blockIdx.x * 128;
    const int NC = Kdim >> 5;

    const int r0i = (tid * 2) >> 2, c40 = (tid * 2) & 3;
    const int r1i = (tid * 2 + 1) >> 2, c41 = (tid * 2 + 1) & 3;
    const __half* gsrc[3] = {
        Ahi + (long)m0 * Kdim,
        HAS_LO ? (Alo + (long)m0 * Kdim) : nullptr,
        Bh + (long)n0 * Kdim };

    const uint32_t so0 = r0i * 64 + ((c40 ^ ((r0i >> 1) & 3)) << 4);
    const uint32_t so1 = r1i * 64 + ((c41 ^ ((r1i >> 1) & 3)) << 4);

    auto issue_stage = [&](int s, int c) {
        const uint32_t base = sb + s * STAGE_BYTES;
        #pragma unroll
        for (int t = 0; t < 3; t++) {
            if (!HAS_LO && t == 1) continue;
            CP_ASYNC16(base + t * TILE_B + so0,
                       gsrc[t] + (long)r0i * Kdim + c * 32 + c40 * 8);
            CP_ASYNC16(base + t * TILE_B + so1,
                       gsrc[t] + (long)r1i * Kdim + c * 32 + c41 * 8);
        }
    };

    issue_stage(0, 0); CP_COMMIT();
    issue_stage(1, 1); CP_COMMIT();

    const int wm = wid & 3;
    const int wn = wid >> 2;

    float acc[2][8][4];
    #pragma unroll
    for (int i = 0; i < 2; i++)
        #pragma unroll
        for (int j = 0; j < 8; j++)
            #pragma unroll
            for (int q = 0; q < 4; q++) acc[i][j][q] = 0.f;

    uint32_t aoff[2][2], boff[2][4];
    #pragma unroll
    for (int ks = 0; ks < 2; ks++) {
        #pragma unroll
        for (int i = 0; i < 2; i++) {
            int row = wm * 32 + i * 16 + (l & 15);
            int c4  = ks * 2 + (l >> 4);
            aoff[ks][i] = row * 64 + ((c4 ^ ((row >> 1) & 3)) << 4);
        }
        #pragma unroll
        for (int p = 0; p < 4; p++) {
            int row = wn * 64 + p * 16 + (l & 7) + ((l & 16) >> 1);
            int c4  = ks * 2 + ((l >> 3) & 1);
            boff[ks][p] = row * 64 + ((c4 ^ ((row >> 1) & 3)) << 4);
        }
    }

    for (int c = 0; c < NC; c++) {
        if (c + 1 < NC) { CP_WAIT1(); } else { CP_WAIT0(); }
        __syncthreads();     // single sync: orders compute(c-1) before the
                             // issue below overwrites stage (c+2)%3
        if (c + 2 < NC) { issue_stage((c + 2) % STAGES, c + 2); CP_COMMIT(); }

        const uint32_t base = sb + (c % STAGES) * STAGE_BYTES;
        #pragma unroll
        for (int ks = 0; ks < 2; ks++) {
            uint32_t ah[2][4], al[2][4];
            #pragma unroll
            for (int i = 0; i < 2; i++) {
                LDSM4(ah[i], base + aoff[ks][i]);
                if (HAS_LO) LDSM4(al[i], base + TILE_B + aoff[ks][i]);
            }
            // B double buffer: LDSM for p+1 issued before MMAs of p consume
            uint32_t rh[2][4];
            LDSM4(rh[0], base + 2 * TILE_B + boff[ks][0]);
            #pragma unroll
            for (int p = 0; p < 4; p++) {
                const int cur = p & 1, nxt = cur ^ 1;
                if (p < 3) LDSM4(rh[nxt], base + 2 * TILE_B + boff[ks][p + 1]);
                #pragma unroll
                for (int i = 0; i < 2; i++) {
                    MMA_F16(acc[i][2*p],     ah[i], rh[cur]);
                    if (HAS_LO) MMA_F16(acc[i][2*p], al[i], rh[cur]);
                    MMA_F16(acc[i][2*p + 1], ah[i], rh[cur] + 2);
                    if (HAS_LO) MMA_F16(acc[i][2*p + 1], al[i], rh[cur] + 2);
                }
            }
        }
    }

    const int mr = m0 + wm * 32 + (l >> 2);
    const int nc = n0 + wn * 64 + (l & 3) * 2;
    #pragma unroll
    for (int i = 0; i < 2; i++) {
        #pragma unroll
        for (int j = 0; j < 8; j++) {
            const int rr = mr + i * 16;
            const int cc = nc + j * 8;
            if (Cf) {
                float b0 = bias ? bias[cc] : 0.f;
                float b1 = bias ? bias[cc + 1] : 0.f;
                float2* p0 = (float2*)(Cf + (long)zb * sC + (long)rr * Ndim + cc);
                float2* p1 = (float2*)(Cf + (long)zb * sC + (long)(rr + 8) * Ndim + cc);
                *p0 = make_float2(acc[i][j][0] + b0, acc[i][j][1] + b1);
                *p1 = make_float2(acc[i][j][2] + b0, acc[i][j][3] + b1);
            } else {
                float v0 = acc[i][j][0], v1 = acc[i][j][1];
                float v2 = acc[i][j][2], v3 = acc[i][j][3];
                __half h0 = __float2half_rn(v0), h1 = __float2half_rn(v1);
                __half h2 = __float2half_rn(v2), h3 = __float2half_rn(v3);
                long o0 = (long)zb * sC + (long)rr * Ndim + cc;
                long o1 = (long)zb * sC + (long)(rr + 8) * Ndim + cc;
                __half2 hp;
                hp.x = h0; hp.y = h1;
                *(__half2*)(Chi + o0) = hp;
                hp.x = h2; hp.y = h3;
                *(__half2*)(Chi + o1) = hp;
                if (Clo) {
                    __half2 lp;
                    lp.x = __float2half_rn(v0 - __half2float(h0));
                    lp.y = __float2half_rn(v1 - __half2float(h1));
                    *(__half2*)(Clo + o0) = lp;
                    lp.x = __float2half_rn(v2 - __half2float(h2));
                    lp.y = __float2half_rn(v3 - __half2float(h3));
                    *(__half2*)(Clo + o1) = lp;
                }
            }
        }
    }
}

// ===========================================================================
// small kernels
// ===========================================================================

// elementwise fp32 -> fp16
__global__ void __launch_bounds__(256) split_kernel(
    const float* __restrict__ in, __half* __restrict__ hi, int n)
{
    int i = (blockIdx.x * 256 + threadIdx.x) * 4;
    if (i >= n) return;
    float4 x = *(const float4*)(in + i);
    __half2 h01; h01.x = __float2half_rn(x.x); h01.y = __float2half_rn(x.y);
    __half2 h23; h23.x = __float2half_rn(x.z); h23.y = __float2half_rn(x.w);
    *(__half2*)(hi + i)     = h01;
    *(__half2*)(hi + i + 2) = h23;
}

// transpose + fp16 convert (+ optional per-block column partial sums)
__global__ void __launch_bounds__(256) splitT_kernel(
    const float* __restrict__ in, long sIn,
    __half* __restrict__ hi, long sOut,
    int R, int C, float* __restrict__ part)
{
    __shared__ float t[32][33];
    __shared__ float ps[8][32];
    in += (long)blockIdx.z * sIn;
    hi += (long)blockIdx.z * sOut;
    const int c0 = blockIdx.x * 32;
    const int r0 = blockIdx.y * 32;
    const int tx = threadIdx.x, ty = threadIdx.y;
    float acc = 0.f;
    for (int k = ty; k < 32; k += 8) {
        float v = in[(long)(r0 + k) * C + c0 + tx];
        t[k][tx] = v;
        acc += v;
    }
    if (part) ps[ty][tx] = acc;
    __syncthreads();
    if (part && ty == 0) {
        float s = ps[0][tx] + ps[1][tx] + ps[2][tx] + ps[3][tx]
                + ps[4][tx] + ps[5][tx] + ps[6][tx] + ps[7][tx];
        part[((long)blockIdx.z * gridDim.y + blockIdx.y) * C + c0 + tx] = s;
    }
    for (int k = ty; k < 32; k += 8) {
        long o = (long)(c0 + k) * R + r0 + tx;
        hi[o] = __float2half_rn(t[tx][k]);
    }
}

// reduce 64 partials -> colsum
__global__ void __launch_bounds__(256) colsum2_kernel(
    const float* __restrict__ part, float* __restrict__ out)
{
    const int b = blockIdx.y;
    const int d = blockIdx.x * 256 + threadIdx.x;
    float s = 0.f;
    #pragma unroll 8
    for (int k = 0; k < 64; k++) s += part[((long)b * 64 + k) * Dd + d];
    out[b * Dd + d] = s;
}

// cka[b][i] = sum_d Wk[d][i]*ksum[b][d] ; cvb likewise (z selects)
__global__ void __launch_bounds__(256) corr_kernel(
    const float* __restrict__ Wk, const float* __restrict__ Wv,
    const float* __restrict__ ksum, const float* __restrict__ vsum,
    float* __restrict__ cka, float* __restrict__ cvb)
{
    const int b = blockIdx.y;
    const float* W = blockIdx.z ? Wv : Wk;
    const float* s = (blockIdx.z ? vsum : ksum) + b * Dd;
    float* o = (blockIdx.z ? cvb : cka) + b * Dd;
    const int t = threadIdx.x;
    const int i = blockIdx.x * 128 + (t & 127);
    const int half = t >> 7;
    float acc = 0.f;
    #pragma unroll 8
    for (int d = half * 512; d < half * 512 + 512; d++)
        acc += W[(long)d * Dd + i] * s[d];
    __shared__ float sm[256];
    sm[t] = acc; __syncthreads();
    if (t < 128) o[i] = sm[t] + sm[t + 128];
}

// Mdiag partial: Mpart[seg][b,h][i][j] = sum_{d in seg} Wk[d,h64+i]*T1[b][d][h64+j]
__global__ void __launch_bounds__(256) Mdiag_part_kernel(
    const float* __restrict__ Wk, const float* __restrict__ T1,
    float* __restrict__ Mpart)
{
    const int h = blockIdx.x;
    const int b = blockIdx.y;
    const int seg = blockIdx.z;
    const float* Kp = Wk + h * HD;
    const float* Tp = T1 + (long)b * DD + h * HD;
    const int d_begin = seg * (Dd / MSEG);
    const int d_end   = d_begin + (Dd / MSEG);

    __shared__ float Kt[32][64];
    __shared__ float Vt[32][64];

    const int tid = threadIdx.x;
    const int ti = tid & 15;
    const int tj = tid >> 4;
    const int lr = tid >> 3;
    const int lc = (tid & 7) * 8;

    float acc[4][4];
    #pragma unroll
    for (int a = 0; a < 4; a++)
        #pragma unroll
        for (int c = 0; c < 4; c++) acc[a][c] = 0.f;

    for (int d0 = d_begin; d0 < d_end; d0 += 32) {
        const float* kp = Kp + (long)(d0 + lr) * Dd + lc;
        const float* vp = Tp + (long)(d0 + lr) * Dd + lc;
        float4 k0 = *(const float4*)kp;
        float4 k1 = *(const float4*)(kp + 4);
        float4 v0 = *(const float4*)vp;
        float4 v1 = *(const float4*)(vp + 4);
        __syncthreads();
        *(float4*)&Kt[lr][lc]     = k0;
        *(float4*)&Kt[lr][lc + 4] = k1;
        *(float4*)&Vt[lr][lc]     = v0;
        *(float4*)&Vt[lr][lc + 4] = v1;
        __syncthreads();

        #pragma unroll 8
        for (int ss = 0; ss < 32; ss++) {
            float4 ka = *(const float4*)&Kt[ss][ti * 4];
            float4 va = *(const float4*)&Vt[ss][tj * 4];
            float rk[4] = {ka.x, ka.y, ka.z, ka.w};
            float rv[4] = {va.x, va.y, va.z, va.w};
            #pragma unroll
            for (int a = 0; a < 4; a++)
                #pragma unroll
                for (int c = 0; c < 4; c++)
                    acc[a][c] += rk[a] * rv[c];
        }
    }

    float* Mp = Mpart + ((long)seg * Bn * Hh + (long)(b * Hh + h)) * (HD * HD);
    #pragma unroll
    for (int a = 0; a < 4; a++) {
        float4 vo = make_float4(acc[a][0], acc[a][1], acc[a][2], acc[a][3]);
        *(float4*)&Mp[(ti * 4 + a) * HD + tj * 4] = vo;
    }
}

// Mdiag reduce (+ bias corrections + scale): deterministic fixed-order sum
__global__ void __launch_bounds__(256) Mdiag_red_kernel(
    const float* __restrict__ Mpart,
    const float* __restrict__ bk, const float* __restrict__ bv,
    const float* __restrict__ cka, const float* __restrict__ cvb,
    float* __restrict__ Mout)
{
    const int h = blockIdx.x;
    const int b = blockIdx.y;
    const int t = threadIdx.x;
    const long bh = (long)(b * Hh + h);
    const long blkSz = (long)HD * HD;

    const int i  = t >> 2;            // row 0..63
    const int j0 = (t & 3) * 16;      // 16 contiguous cols

    const float bki  = bk[h * HD + i];
    const float ckai = cka[b * Dd + h * HD + i];
    const float scale = 0.125f;

    #pragma unroll
    for (int q = 0; q < 4; q++) {
        const int j = j0 + q * 4;
        const long e = (long)i * HD + j;
        float4 s = *(const float4*)&Mpart[(0 * (long)Bn * Hh + bh) * blkSz + e];
        #pragma unroll
        for (int g = 1; g < MSEG; g++) {
            float4 p = *(const float4*)&Mpart[((long)g * Bn * Hh + bh) * blkSz + e];
            s.x += p.x; s.y += p.y; s.z += p.z; s.w += p.w;
        }
        float* sv = &s.x;
        float4 vo;
        float* vp = &vo.x;
        #pragma unroll
        for (int c = 0; c < 4; c++) {
            const int jj = j + c;
            float corr = ckai * bv[h * HD + jj]
                       + bki * cvb[b * Dd + h * HD + jj]
                       + (float)Ssz * bki * bv[h * HD + jj];
            vp[c] = scale * (sv[c] + corr);
        }
        *(float4*)&Mout[bh * blkSz + e] = vo;
    }
}

// P^T fp16 directly: rows r = h*64+row0+i, cols cc -> pT[cc][r]
__global__ void __launch_bounds__(256) P_kernel(
    const float* __restrict__ Mmat, const float* __restrict__ Wo,
    __half* __restrict__ pth)
{
    const int nb = blockIdx.x;
    const int h  = blockIdx.y;
    const int b  = blockIdx.z;

    __shared__ float Ms[64][64];
    const float* Mp = Mmat + ((long)(b * Hh + h)) * HD * HD;
    for (int i = threadIdx.x; i < HD * HD; i += 256)
        Ms[i >> 6][i & 63] = Mp[i];
    __syncthreads();

    const int tid  = threadIdx.x;
    const int col  = nb * 128 + (tid & 31) * 4;
    const int row0 = (tid >> 5) * 8;

    float acc[8][4];
    #pragma unroll
    for (int i = 0; i < 8; i++)
        #pragma unroll
        for (int c = 0; c < 4; c++) acc[i][c] = 0.f;

    const float* Wp = Wo + (long)(h * HD) * Dd + col;
    #pragma unroll 8
    for (int j = 0; j < HD; j++) {
        float4 w = *(const float4*)(Wp + (long)j * Dd);
        #pragma unroll
        for (int i = 0; i < 8; i++) {
            float m = Ms[row0 + i][j];
            acc[i][0] += m * w.x;
            acc[i][1] += m * w.y;
            acc[i][2] += m * w.z;
            acc[i][3] += m * w.w;
        }
    }

    #pragma unroll
    for (int c = 0; c < 4; c++) {
        uint32_t hbuf[4];
        #pragma unroll
        for (int i = 0; i < 8; i += 2) {
            __half2 hp;
            hp.x = __float2half_rn(acc[i][c]);
            hp.y = __float2half_rn(acc[i + 1][c]);
            hbuf[i >> 1] = *(uint32_t*)&hp;
        }
        long o = (long)b * DD + (long)(col + c) * Dd + h * HD + row0;
        *(uint4*)(pth + o) = make_uint4(hbuf[0], hbuf[1], hbuf[2], hbuf[3]);
    }
}

// tv[b][h*64+j] = sum_i bq[h*64+i] * M[b,h,i,j]
__global__ void __launch_bounds__(64) tvec_kernel(
    const float* __restrict__ M, const float* __restrict__ bq,
    float* __restrict__ tv)
{
    const int h = blockIdx.x, b = blockIdx.y;
    const int j = threadIdx.x;
    const float* Mp = M + ((long)(b * Hh + h)) * HD * HD;
    float acc = 0.f;
    #pragma unroll 8
    for (int i = 0; i < HD; i++) acc += bq[h * HD + i] * Mp[i * HD + j];
    tv[b * Dd + h * HD + j] = acc;
}

// bbig[b][n] = sum_r tv[b][r]*Wo[r][n] + bo[n]
__global__ void __launch_bounds__(256) bbig2_kernel(
    const float* __restrict__ tv, const float* __restrict__ Wo,
    const float* __restrict__ bo, float* __restrict__ bbig)
{
    const int b = blockIdx.y;
    const int t = threadIdx.x;
    const int n = blockIdx.x * 64 + (t & 63);
    const int rs = t >> 6;
    float acc = 0.f;
    #pragma unroll 8
    for (int r = rs * 256; r < rs * 256 + 256; r++)
        acc += tv[b * Dd + r] * Wo[(long)r * Dd + n];
    __shared__ float sm[256];
    sm[t] = acc; __syncthreads();
    if (t < 64)
        bbig[b * Dd + n] = sm[t] + sm[t + 64] + sm[t + 128] + sm[t + 192] + bo[n];
}

// ===========================================================================
extern "C" void kernel_launch(void* const* d_in, const int* in_sizes, int n_in,
                              void* d_out, int out_size)
{
    const float* query = (const float*)d_in[0];
    const float* key   = (const float*)d_in[1];
    const float* value = (const float*)d_in[2];
    const float* Wq    = (const float*)d_in[3];
    const float* bq    = (const float*)d_in[4];
    const float* Wk    = (const float*)d_in[5];
    const float* bk    = (const float*)d_in[6];
    const float* Wv    = (const float*)d_in[7];
    const float* bv    = (const float*)d_in[8];
    const float* Wo    = (const float*)d_in[9];
    const float* bo    = (const float*)d_in[10];
    float* out = (float*)d_out;

    float *pT1, *pM, *pMp, *pB, *pTv, *pKs, *pVs, *pKp, *pVp, *pCka, *pCvb;
    cudaGetSymbolAddress((void**)&pT1, g_T1);
    cudaGetSymbolAddress((void**)&pM,  g_M);
    cudaGetSymbolAddress((void**)&pMp, g_Mpart);
    cudaGetSymbolAddress((void**)&pB,  g_bbig);
    cudaGetSymbolAddress((void**)&pTv, g_tv);
    cudaGetSymbolAddress((void**)&pKs, g_ksum);
    cudaGetSymbolAddress((void**)&pVs, g_vsum);
    cudaGetSymbolAddress((void**)&pKp, g_kpart);
    cudaGetSymbolAddress((void**)&pVp, g_vpart);
    cudaGetSymbolAddress((void**)&pCka, g_cka);
    cudaGetSymbolAddress((void**)&pCvb, g_cvb);
    __half *qh, *kth, *vth, *wqh, *wvth, *gh, *pth, *wbth;
    cudaGetSymbolAddress((void**)&qh,  g_q_hi);
    cudaGetSymbolAddress((void**)&kth, g_kT_hi);
    cudaGetSymbolAddress((void**)&vth, g_vT_hi);
    cudaGetSymbolAddress((void**)&wqh, g_wq_hi);
    cudaGetSymbolAddress((void**)&wvth, g_wvT_hi);
    cudaGetSymbolAddress((void**)&gh,  g_G_hi);
    cudaGetSymbolAddress((void**)&pth, g_pT_hi);
    cudaGetSymbolAddress((void**)&wbth, g_wbT_hi);

    cudaFuncSetAttribute(gemm_tc<true>,
                         cudaFuncAttributeMaxDynamicSharedMemorySize, GEMM_SMEM);
    cudaFuncSetAttribute(gemm_tc<false>,
                         cudaFuncAttributeMaxDynamicSharedMemorySize, GEMM_SMEM);

    const long sBatch = (long)Ssz * Dd;

    // 1-3) query fp16; key/value transpose+fp16 (+fused colsum partials)
    split_kernel<<<GME / 1024, 256>>>(query, qh, GME);
    splitT_kernel<<<dim3(Dd / 32, Ssz / 32, Bn), dim3(32, 8)>>>(
        key, sBatch, kth, sBatch, Ssz, Dd, pKp);
    splitT_kernel<<<dim3(Dd / 32, Ssz / 32, Bn), dim3(32, 8)>>>(
        value, sBatch, vth, sBatch, Ssz, Dd, pVp);

    // 4) G_b = key_b^T @ value_b  (4th launch -> ncu profile; fp16 out)
    gemm_tc<false><<<dim3(Dd / 128, Dd / 128, Bn), 256, GEMM_SMEM>>>(
        kth, nullptr, sBatch, vth, sBatch, nullptr, 0,
        nullptr, gh, nullptr, (long)DD, Dd, Ssz);

    // 5-6) weight fp16 conversions
    split_kernel<<<DD / 1024, 256>>>(Wq, wqh, DD);
    splitT_kernel<<<dim3(32, 32, 1), dim3(32, 8)>>>(
        Wv, 0, wvth, 0, Dd, Dd, nullptr);

    // 7-9) colsum reduce + bias-correction matvecs
    colsum2_kernel<<<dim3(Dd / 256, Bn), 256>>>(pKp, pKs);
    colsum2_kernel<<<dim3(Dd / 256, Bn), 256>>>(pVp, pVs);
    corr_kernel<<<dim3(Dd / 128, Bn, 2), 256>>>(Wk, Wv, pKs, pVs, pCka, pCvb);

    // 10) T1_b = G_b @ Wv  (fp32 out)
    gemm_tc<false><<<dim3(Dd / 128, Dd / 128, Bn), 256, GEMM_SMEM>>>(
        gh, nullptr, (long)DD, wvth, 0, nullptr, 0,
        pT1, nullptr, nullptr, (long)DD, Dd, Dd);

    // 11) M diag blocks: K-split x4 partials + deterministic reduce w/ corr
    Mdiag_part_kernel<<<dim3(Hh, Bn, MSEG), 256>>>(Wk, pT1, pMp);
    Mdiag_red_kernel<<<dim3(Hh, Bn), 256>>>(pMp, bk, bv, pCka, pCvb, pM);

    // 12-14) P (writes P^T fp16 directly), t-vector, bbig
    P_kernel<<<dim3(Dd / 128, Hh, Bn), 256>>>(pM, Wo, pth);
    tvec_kernel<<<dim3(Hh, Bn), 64>>>(pM, bq, pTv);
    bbig2_kernel<<<dim3(Dd / 64, Bn), 256>>>(pTv, Wo, bo, pB);

    // 15) WbigT_b = P_b^T @ Wq^T  (fp16 out)
    gemm_tc<false><<<dim3(Dd / 128, Dd / 128, Bn), 256, GEMM_SMEM>>>(
        pth, nullptr, (long)DD, wqh, 0, nullptr, 0,
        nullptr, wbth, nullptr, (long)DD, Dd, Dd);

    // 16) out_b = query_b @ Wbig_b + bbig_b  (fp32 out)
    gemm_tc<false><<<dim3(Dd / 128, Ssz / 128, Bn), 256, GEMM_SMEM>>>(
        qh, nullptr, sBatch, wbth, (long)DD, pB, Dd,
        out, nullptr, nullptr, sBatch, Dd, Dd);
}

// round 15
// speedup vs baseline: 5.4255x; 1.2821x over previous
#include <cuda_runtime.h>
#include <cuda_fp16.h>
#include <cstdint>

// ===========================================================================
// MHA WITHOUT softmax == linear operator, fully re-associated:
//   G_b  = key_b^T @ value_b                         (mma.sync fp16 1-term)
//   T1_b = G_b @ Wv                                  (mma.sync fp16 1-term)
//   M_{b,h} = scale*( diag64(Wk^T T1)_h + rank-1 bias corrections )
//   PT_b = (stack_h(M_{b,h} @ Wo_h))^T               (SIMT, tiny, fused split)
//   WbigT_b = P_b^T @ Wq^T                           (mma.sync fp16 1-term)
//   bbig_b = (bq.M)^T @ Wo + bo                      (SIMT, tiny)
//   out_b = query_b @ Wbig_b + bbig_b                (mma.sync fp16 1-term)
// R15: gemm K-chunk 64 (half the syncs; identical accumulation order),
//      splitT 64x64 tiles with __half2 stores, key+value splitT merged,
//      colsum2 pair merged. Math identical to R14 (rel_err is a control).
// ===========================================================================

namespace {
constexpr int Bn  = 4;
constexpr int Ssz = 2048;
constexpr int Dd  = 1024;
constexpr int Hh  = 16;
constexpr int HD  = 64;
constexpr int GME = Bn * Ssz * Dd;
constexpr int DD  = Dd * Dd;
constexpr int MSEG = 4;              // Mdiag K-split factor
}

// ------------------------- scratch (device globals) ------------------------
__device__ float g_T1[(size_t)Bn * DD];
__device__ float g_M[Bn * Hh * HD * HD];
__device__ float g_Mpart[(size_t)MSEG * Bn * Hh * HD * HD];
__device__ float g_bbig[Bn * Dd];
__device__ float g_tv[Bn * Dd];
__device__ float g_ksum[Bn * Dd], g_vsum[Bn * Dd];
__device__ float g_kpart[(size_t)Bn * 64 * Dd], g_vpart[(size_t)Bn * 64 * Dd];
__device__ float g_cka[Bn * Dd], g_cvb[Bn * Dd];

__device__ __half g_q_hi[GME];
__device__ __half g_kT_hi[GME];
__device__ __half g_vT_hi[GME];
__device__ __half g_wq_hi[DD];
__device__ __half g_wvT_hi[DD];
__device__ __half g_G_hi[(size_t)Bn * DD];
__device__ __half g_pT_hi[(size_t)Bn * DD];
__device__ __half g_wbT_hi[(size_t)Bn * DD];

// ------------------------------ PTX helpers --------------------------------
__device__ __forceinline__ uint32_t smem_u32(const void* p) {
    uint32_t a;
    asm("{ .reg .u64 t; cvta.to.shared.u64 t, %1; cvt.u32.u64 %0, t; }"
        : "=r"(a) : "l"(p));
    return a;
}

#define LDSM4(r, addr)                                                        \
    asm volatile("ldmatrix.sync.aligned.m8n8.x4.shared.b16 "                  \
                 "{%0,%1,%2,%3}, [%4];"                                       \
                 : "=r"((r)[0]), "=r"((r)[1]), "=r"((r)[2]), "=r"((r)[3])     \
                 : "r"(addr))

#define MMA_F16(d, a, b)                                                      \
    asm volatile("mma.sync.aligned.m16n8k16.row.col.f32.f16.f16.f32 "         \
                 "{%0,%1,%2,%3}, {%4,%5,%6,%7}, {%8,%9}, {%0,%1,%2,%3};"      \
                 : "+f"((d)[0]), "+f"((d)[1]), "+f"((d)[2]), "+f"((d)[3])     \
                 : "r"((a)[0]), "r"((a)[1]), "r"((a)[2]), "r"((a)[3]),        \
                   "r"((b)[0]), "r"((b)[1]))

#define CP_ASYNC16(dst, src)                                                  \
    asm volatile("cp.async.cg.shared.global [%0], [%1], 16;"                  \
                 :: "r"(dst), "l"(src))
#define CP_COMMIT()  asm volatile("cp.async.commit_group;")
#define CP_WAIT1()   asm volatile("cp.async.wait_group 1;")
#define CP_WAIT0()   asm volatile("cp.async.wait_group 0;")

// ===========================================================================
// Tensor-core GEMM: C[M,N] = A[M,K] @ Bt[N,K]^T (+ bias[n]).
// Plain fp16 operands, fp32 accum. 128x128 tile, K-chunk 64 (128B rows,
// swizzle c4 ^ (row&7)), 3-stage cp.async pipeline, one sync per chunk.
// Output: Cf (fp32 + bias) OR Chi (fp16).
// ===========================================================================
namespace {
constexpr int TILE_B      = 128 * 64 * 2;          // 16 KB per fp16 tile
constexpr int STAGE_BYTES = 2 * TILE_B;            // A, B = 32 KB
constexpr int STAGES      = 3;
constexpr int GEMM_SMEM   = STAGES * STAGE_BYTES;  // 96 KB
}

__global__ void __launch_bounds__(256, 2) gemm_tc(
    const __half* __restrict__ Ah, long sA,
    const __half* __restrict__ Bh, long sB,
    const float* __restrict__ bias, long sBias,
    float* __restrict__ Cf,
    __half* __restrict__ Chi,
    long sC, int Ndim, int Kdim)
{
    extern __shared__ char smem[];
    const uint32_t sb = smem_u32(smem);
    const int tid = threadIdx.x;
    const int wid = tid >> 5;
    const int l   = tid & 31;
    const int zb  = blockIdx.z;

    Ah += (long)zb * sA;
    Bh += (long)zb * sB;
    if (bias) bias += (long)zb * sBias;

    const int m0 = blockIdx.y * 128;
    const int n0 = blockIdx.x * 128;
    const int NC = Kdim >> 6;          // chunks of 64 fp16-K

    // cp.async: 1024 16B-chunks per tile; 4 per thread per tile
    int rw[4], cw[4];
    uint32_t sw[4];
    #pragma unroll
    for (int u = 0; u < 4; u++) {
        int idx = tid + 256 * u;
        rw[u] = idx >> 3;
        cw[u] = idx & 7;
        sw[u] = rw[u] * 128 + ((cw[u] ^ (rw[u] & 7)) << 4);
    }
    const __half* gsrcA = Ah + (long)m0 * Kdim;
    const __half* gsrcB = Bh + (long)n0 * Kdim;

    auto issue_stage = [&](int s, int c) {
        const uint32_t base = sb + s * STAGE_BYTES;
        #pragma unroll
        for (int u = 0; u < 4; u++)
            CP_ASYNC16(base + sw[u],
                       gsrcA + (long)rw[u] * Kdim + c * 64 + cw[u] * 8);
        #pragma unroll
        for (int u = 0; u < 4; u++)
            CP_ASYNC16(base + TILE_B + sw[u],
                       gsrcB + (long)rw[u] * Kdim + c * 64 + cw[u] * 8);
    };

    issue_stage(0, 0); CP_COMMIT();
    issue_stage(1, 1); CP_COMMIT();

    const int wm = wid & 3;            // m-warp: rows wm*32
    const int wn = wid >> 2;           // n-warp: cols wn*64

    float acc[2][8][4];
    #pragma unroll
    for (int i = 0; i < 2; i++)
        #pragma unroll
        for (int j = 0; j < 8; j++)
            #pragma unroll
            for (int q = 0; q < 4; q++) acc[i][j][q] = 0.f;

    // ldmatrix row bases (c4 computed per ks to limit register pressure)
    int rowA[2], rowB[4];
    const int c4a = (l >> 4);          // 0..1
    const int c4b = ((l >> 3) & 1);    // 0..1
    #pragma unroll
    for (int i = 0; i < 2; i++)
        rowA[i] = wm * 32 + i * 16 + (l & 15);
    #pragma unroll
    for (int p = 0; p < 4; p++)
        rowB[p] = wn * 64 + p * 16 + (l & 7) + ((l & 16) >> 1);

    for (int c = 0; c < NC; c++) {
        if (c + 1 < NC) { CP_WAIT1(); } else { CP_WAIT0(); }
        __syncthreads();     // orders compute(c-1) before issue overwrites
                             // stage (c+2)%3
        if (c + 2 < NC) { issue_stage((c + 2) % STAGES, c + 2); CP_COMMIT(); }

        const uint32_t base = sb + (c % STAGES) * STAGE_BYTES;
        #pragma unroll
        for (int ks = 0; ks < 4; ks++) {
            uint32_t ah[2][4];
            #pragma unroll
            for (int i = 0; i < 2; i++) {
                int c4 = ks * 2 + c4a;
                LDSM4(ah[i], base + rowA[i] * 128 +
                             ((c4 ^ (rowA[i] & 7)) << 4));
            }
            // B double buffer: LDSM for p+1 issued before MMAs of p consume
            uint32_t rh[2][4];
            {
                int c4 = ks * 2 + c4b;
                LDSM4(rh[0], base + TILE_B + rowB[0] * 128 +
                             ((c4 ^ (rowB[0] & 7)) << 4));
            }
            #pragma unroll
            for (int p = 0; p < 4; p++) {
                const int cur = p & 1, nxt = cur ^ 1;
                if (p < 3) {
                    int c4 = ks * 2 + c4b;
                    LDSM4(rh[nxt], base + TILE_B + rowB[p + 1] * 128 +
                                   ((c4 ^ (rowB[p + 1] & 7)) << 4));
                }
                #pragma unroll
                for (int i = 0; i < 2; i++) {
                    MMA_F16(acc[i][2*p],     ah[i], rh[cur]);
                    MMA_F16(acc[i][2*p + 1], ah[i], rh[cur] + 2);
                }
            }
        }
    }

    const int mr = m0 + wm * 32 + (l >> 2);
    const int nc = n0 + wn * 64 + (l & 3) * 2;
    #pragma unroll
    for (int i = 0; i < 2; i++) {
        #pragma unroll
        for (int j = 0; j < 8; j++) {
            const int rr = mr + i * 16;
            const int cc = nc + j * 8;
            if (Cf) {
                float b0 = bias ? bias[cc] : 0.f;
                float b1 = bias ? bias[cc + 1] : 0.f;
                float2* p0 = (float2*)(Cf + (long)zb * sC + (long)rr * Ndim + cc);
                float2* p1 = (float2*)(Cf + (long)zb * sC + (long)(rr + 8) * Ndim + cc);
                *p0 = make_float2(acc[i][j][0] + b0, acc[i][j][1] + b1);
                *p1 = make_float2(acc[i][j][2] + b0, acc[i][j][3] + b1);
            } else {
                long o0 = (long)zb * sC + (long)rr * Ndim + cc;
                long o1 = (long)zb * sC + (long)(rr + 8) * Ndim + cc;
                __half2 hp;
                hp.x = __float2half_rn(acc[i][j][0]);
                hp.y = __float2half_rn(acc[i][j][1]);
                *(__half2*)(Chi + o0) = hp;
                hp.x = __float2half_rn(acc[i][j][2]);
                hp.y = __float2half_rn(acc[i][j][3]);
                *(__half2*)(Chi + o1) = hp;
            }
        }
    }
}

// ===========================================================================
// small kernels
// ===========================================================================

// elementwise fp32 -> fp16
__global__ void __launch_bounds__(256) split_kernel(
    const float* __restrict__ in, __half* __restrict__ hi, int n)
{
    int i = (blockIdx.x * 256 + threadIdx.x) * 4;
    if (i >= n) return;
    float4 x = *(const float4*)(in + i);
    __half2 h01; h01.x = __float2half_rn(x.x); h01.y = __float2half_rn(x.y);
    __half2 h23; h23.x = __float2half_rn(x.z); h23.y = __float2half_rn(x.w);
    *(__half2*)(hi + i)     = h01;
    *(__half2*)(hi + i + 2) = h23;
}

// transpose + fp16 convert, 64x64 tiles, __half2 stores.
// If gridDim.z > 1: z selects (b = z>>1, sel = z&1 -> key/value pair).
// part (optional): per-64-row-slab column sums.
__global__ void __launch_bounds__(256) splitT_kernel(
    const float* __restrict__ in0, const float* __restrict__ in1, long sIn,
    __half* __restrict__ hi0, __half* __restrict__ hi1, long sOut,
    int R, int C, float* __restrict__ part0, float* __restrict__ part1)
{
    __shared__ float t[64][65];
    __shared__ float ps[8][64];
    const int b   = blockIdx.z >> 1;
    const int sel = blockIdx.z & 1;
    const float* in = (sel ? in1 : in0) + (long)b * sIn;
    __half* hi      = (sel ? hi1 : hi0) + (long)b * sOut;
    float* part     = sel ? part1 : part0;

    const int c0 = blockIdx.x * 64;
    const int r0 = blockIdx.y * 64;
    const int tx = threadIdx.x, ty = threadIdx.y;   // (32, 8)

    float a0 = 0.f, a1 = 0.f;
    for (int k = ty; k < 64; k += 8) {
        float v0 = in[(long)(r0 + k) * C + c0 + tx];
        float v1 = in[(long)(r0 + k) * C + c0 + tx + 32];
        t[k][tx]      = v0;
        t[k][tx + 32] = v1;
        a0 += v0; a1 += v1;
    }
    if (part) { ps[ty][tx] = a0; ps[ty][tx + 32] = a1; }
    __syncthreads();
    if (part && ty == 0) {
        #pragma unroll
        for (int h = 0; h < 2; h++) {
            const int cx = tx + 32 * h;
            float s = ps[0][cx] + ps[1][cx] + ps[2][cx] + ps[3][cx]
                    + ps[4][cx] + ps[5][cx] + ps[6][cx] + ps[7][cx];
            part[((long)b * gridDim.y + blockIdx.y) * C + c0 + cx] = s;
        }
    }
    // write transposed: output row c0+k, cols r0+2tx, r0+2tx+1 (__half2)
    for (int k = ty; k < 64; k += 8) {
        __half2 hp;
        hp.x = __float2half_rn(t[2 * tx][k]);
        hp.y = __float2half_rn(t[2 * tx + 1][k]);
        *(__half2*)(hi + (long)(c0 + k) * R + r0 + 2 * tx) = hp;
    }
}

// reduce 32 slab partials -> colsum; z selects key/value
__global__ void __launch_bounds__(256) colsum2_kernel(
    const float* __restrict__ part0, const float* __restrict__ part1,
    float* __restrict__ out0, float* __restrict__ out1)
{
    const int b = blockIdx.y;
    const int d = blockIdx.x * 256 + threadIdx.x;
    const float* part = blockIdx.z ? part1 : part0;
    float* out        = blockIdx.z ? out1 : out0;
    float s = 0.f;
    #pragma unroll 8
    for (int k = 0; k < 32; k++) s += part[((long)b * 32 + k) * Dd + d];
    out[b * Dd + d] = s;
}

// cka[b][i] = sum_d Wk[d][i]*ksum[b][d] ; cvb likewise (z selects)
__global__ void __launch_bounds__(256) corr_kernel(
    const float* __restrict__ Wk, const float* __restrict__ Wv,
    const float* __restrict__ ksum, const float* __restrict__ vsum,
    float* __restrict__ cka, float* __restrict__ cvb)
{
    const int b = blockIdx.y;
    const float* W = blockIdx.z ? Wv : Wk;
    const float* s = (blockIdx.z ? vsum : ksum) + b * Dd;
    float* o = (blockIdx.z ? cvb : cka) + b * Dd;
    const int t = threadIdx.x;
    const int i = blockIdx.x * 128 + (t & 127);
    const int half = t >> 7;
    float acc = 0.f;
    #pragma unroll 8
    for (int d = half * 512; d < half * 512 + 512; d++)
        acc += W[(long)d * Dd + i] * s[d];
    __shared__ float sm[256];
    sm[t] = acc; __syncthreads();
    if (t < 128) o[i] = sm[t] + sm[t + 128];
}

// Mdiag partial: Mpart[seg][b,h][i][j] = sum_{d in seg} Wk[d,h64+i]*T1[b][d][h64+j]
__global__ void __launch_bounds__(256) Mdiag_part_kernel(
    const float* __restrict__ Wk, const float* __restrict__ T1,
    float* __restrict__ Mpart)
{
    const int h = blockIdx.x;
    const int b = blockIdx.y;
    const int seg = blockIdx.z;
    const float* Kp = Wk + h * HD;
    const float* Tp = T1 + (long)b * DD + h * HD;
    const int d_begin = seg * (Dd / MSEG);
    const int d_end   = d_begin + (Dd / MSEG);

    __shared__ float Kt[32][64];
    __shared__ float Vt[32][64];

    const int tid = threadIdx.x;
    const int ti = tid & 15;
    const int tj = tid >> 4;
    const int lr = tid >> 3;
    const int lc = (tid & 7) * 8;

    float acc[4][4];
    #pragma unroll
    for (int a = 0; a < 4; a++)
        #pragma unroll
        for (int c = 0; c < 4; c++) acc[a][c] = 0.f;

    for (int d0 = d_begin; d0 < d_end; d0 += 32) {
        const float* kp = Kp + (long)(d0 + lr) * Dd + lc;
        const float* vp = Tp + (long)(d0 + lr) * Dd + lc;
        float4 k0 = *(const float4*)kp;
        float4 k1 = *(const float4*)(kp + 4);
        float4 v0 = *(const float4*)vp;
        float4 v1 = *(const float4*)(vp + 4);
        __syncthreads();
        *(float4*)&Kt[lr][lc]     = k0;
        *(float4*)&Kt[lr][lc + 4] = k1;
        *(float4*)&Vt[lr][lc]     = v0;
        *(float4*)&Vt[lr][lc + 4] = v1;
        __syncthreads();

        #pragma unroll 8
        for (int ss = 0; ss < 32; ss++) {
            float4 ka = *(const float4*)&Kt[ss][ti * 4];
            float4 va = *(const float4*)&Vt[ss][tj * 4];
            float rk[4] = {ka.x, ka.y, ka.z, ka.w};
            float rv[4] = {va.x, va.y, va.z, va.w};
            #pragma unroll
            for (int a = 0; a < 4; a++)
                #pragma unroll
                for (int c = 0; c < 4; c++)
                    acc[a][c] += rk[a] * rv[c];
        }
    }

    float* Mp = Mpart + ((long)seg * Bn * Hh + (long)(b * Hh + h)) * (HD * HD);
    #pragma unroll
    for (int a = 0; a < 4; a++) {
        float4 vo = make_float4(acc[a][0], acc[a][1], acc[a][2], acc[a][3]);
        *(float4*)&Mp[(ti * 4 + a) * HD + tj * 4] = vo;
    }
}

// Mdiag reduce (+ bias corrections + scale): deterministic fixed-order sum
__global__ void __launch_bounds__(256) Mdiag_red_kernel(
    const float* __restrict__ Mpart,
    const float* __restrict__ bk, const float* __restrict__ bv,
    const float* __restrict__ cka, const float* __restrict__ cvb,
    float* __restrict__ Mout)
{
    const int h = blockIdx.x;
    const int b = blockIdx.y;
    const int t = threadIdx.x;
    const long bh = (long)(b * Hh + h);
    const long blkSz = (long)HD * HD;

    const int i  = t >> 2;            // row 0..63
    const int j0 = (t & 3) * 16;      // 16 contiguous cols

    const float bki  = bk[h * HD + i];
    const float ckai = cka[b * Dd + h * HD + i];
    const float scale = 0.125f;

    #pragma unroll
    for (int q = 0; q < 4; q++) {
        const int j = j0 + q * 4;
        const long e = (long)i * HD + j;
        float4 s = *(const float4*)&Mpart[(0 * (long)Bn * Hh + bh) * blkSz + e];
        #pragma unroll
        for (int g = 1; g < MSEG; g++) {
            float4 p = *(const float4*)&Mpart[((long)g * Bn * Hh + bh) * blkSz + e];
            s.x += p.x; s.y += p.y; s.z += p.z; s.w += p.w;
        }
        float* sv = &s.x;
        float4 vo;
        float* vp = &vo.x;
        #pragma unroll
        for (int c = 0; c < 4; c++) {
            const int jj = j + c;
            float corr = ckai * bv[h * HD + jj]
                       + bki * cvb[b * Dd + h * HD + jj]
                       + (float)Ssz * bki * bv[h * HD + jj];
            vp[c] = scale * (sv[c] + corr);
        }
        *(float4*)&Mout[bh * blkSz + e] = vo;
    }
}

// P^T fp16 directly: rows r = h*64+row0+i, cols cc -> pT[cc][r]
__global__ void __launch_bounds__(256) P_kernel(
    const float* __restrict__ Mmat, const float* __restrict__ Wo,
    __half* __restrict__ pth)
{
    const int nb = blockIdx.x;
    const int h  = blockIdx.y;
    const int b  = blockIdx.z;

    __shared__ float Ms[64][64];
    const float* Mp = Mmat + ((long)(b * Hh + h)) * HD * HD;
    for (int i = threadIdx.x; i < HD * HD; i += 256)
        Ms[i >> 6][i & 63] = Mp[i];
    __syncthreads();

    const int tid  = threadIdx.x;
    const int col  = nb * 128 + (tid & 31) * 4;
    const int row0 = (tid >> 5) * 8;

    float acc[8][4];
    #pragma unroll
    for (int i = 0; i < 8; i++)
        #pragma unroll
        for (int c = 0; c < 4; c++) acc[i][c] = 0.f;

    const float* Wp = Wo + (long)(h * HD) * Dd + col;
    #pragma unroll 8
    for (int j = 0; j < HD; j++) {
        float4 w = *(const float4*)(Wp + (long)j * Dd);
        #pragma unroll
        for (int i = 0; i < 8; i++) {
            float m = Ms[row0 + i][j];
            acc[i][0] += m * w.x;
            acc[i][1] += m * w.y;
            acc[i][2] += m * w.z;
            acc[i][3] += m * w.w;
        }
    }

    #pragma unroll
    for (int c = 0; c < 4; c++) {
        uint32_t hbuf[4];
        #pragma unroll
        for (int i = 0; i < 8; i += 2) {
            __half2 hp;
            hp.x = __float2half_rn(acc[i][c]);
            hp.y = __float2half_rn(acc[i + 1][c]);
            hbuf[i >> 1] = *(uint32_t*)&hp;
        }
        long o = (long)b * DD + (long)(col + c) * Dd + h * HD + row0;
        *(uint4*)(pth + o) = make_uint4(hbuf[0], hbuf[1], hbuf[2], hbuf[3]);
    }
}

// tv[b][h*64+j] = sum_i bq[h*64+i] * M[b,h,i,j]
__global__ void __launch_bounds__(64) tvec_kernel(
    const float* __restrict__ M, const float* __restrict__ bq,
    float* __restrict__ tv)
{
    const int h = blockIdx.x, b = blockIdx.y;
    const int j = threadIdx.x;
    const float* Mp = M + ((long)(b * Hh + h)) * HD * HD;
    float acc = 0.f;
    #pragma unroll 8
    for (int i = 0; i < HD; i++) acc += bq[h * HD + i] * Mp[i * HD + j];
    tv[b * Dd + h * HD + j] = acc;
}

// bbig[b][n] = sum_r tv[b][r]*Wo[r][n] + bo[n]
__global__ void __launch_bounds__(256) bbig2_kernel(
    const float* __restrict__ tv, const float* __restrict__ Wo,
    const float* __restrict__ bo, float* __restrict__ bbig)
{
    const int b = blockIdx.y;
    const int t = threadIdx.x;
    const int n = blockIdx.x * 64 + (t & 63);
    const int rs = t >> 6;
    float acc = 0.f;
    #pragma unroll 8
    for (int r = rs * 256; r < rs * 256 + 256; r++)
        acc += tv[b * Dd + r] * Wo[(long)r * Dd + n];
    __shared__ float sm[256];
    sm[t] = acc; __syncthreads();
    if (t < 64)
        bbig[b * Dd + n] = sm[t] + sm[t + 64] + sm[t + 128] + sm[t + 192] + bo[n];
}

// ===========================================================================
extern "C" void kernel_launch(void* const* d_in, const int* in_sizes, int n_in,
                              void* d_out, int out_size)
{
    const float* query = (const float*)d_in[0];
    const float* key   = (const float*)d_in[1];
    const float* value = (const float*)d_in[2];
    const float* Wq    = (const float*)d_in[3];
    const float* bq    = (const float*)d_in[4];
    const float* Wk    = (const float*)d_in[5];
    const float* bk    = (const float*)d_in[6];
    const float* Wv    = (const float*)d_in[7];
    const float* bv    = (const float*)d_in[8];
    const float* Wo    = (const float*)d_in[9];
    const float* bo    = (const float*)d_in[10];
    float* out = (float*)d_out;

    float *pT1, *pM, *pMp, *pB, *pTv, *pKs, *pVs, *pKp, *pVp, *pCka, *pCvb;
    cudaGetSymbolAddress((void**)&pT1, g_T1);
    cudaGetSymbolAddress((void**)&pM,  g_M);
    cudaGetSymbolAddress((void**)&pMp, g_Mpart);
    cudaGetSymbolAddress((void**)&pB,  g_bbig);
    cudaGetSymbolAddress((void**)&pTv, g_tv);
    cudaGetSymbolAddress((void**)&pKs, g_ksum);
    cudaGetSymbolAddress((void**)&pVs, g_vsum);
    cudaGetSymbolAddress((void**)&pKp, g_kpart);
    cudaGetSymbolAddress((void**)&pVp, g_vpart);
    cudaGetSymbolAddress((void**)&pCka, g_cka);
    cudaGetSymbolAddress((void**)&pCvb, g_cvb);
    __half *qh, *kth, *vth, *wqh, *wvth, *gh, *pth, *wbth;
    cudaGetSymbolAddress((void**)&qh,  g_q_hi);
    cudaGetSymbolAddress((void**)&kth, g_kT_hi);
    cudaGetSymbolAddress((void**)&vth, g_vT_hi);
    cudaGetSymbolAddress((void**)&wqh, g_wq_hi);
    cudaGetSymbolAddress((void**)&wvth, g_wvT_hi);
    cudaGetSymbolAddress((void**)&gh,  g_G_hi);
    cudaGetSymbolAddress((void**)&pth, g_pT_hi);
    cudaGetSymbolAddress((void**)&wbth, g_wbT_hi);

    cudaFuncSetAttribute(gemm_tc,
                         cudaFuncAttributeMaxDynamicSharedMemorySize, GEMM_SMEM);

    const long sBatch = (long)Ssz * Dd;

    // 1) query fp16
    split_kernel<<<GME / 1024, 256>>>(query, qh, GME);
    // 2) key+value transpose+fp16 (+fused colsum partials), ONE launch
    splitT_kernel<<<dim3(Dd / 64, Ssz / 64, 2 * Bn), dim3(32, 8)>>>(
        key, value, sBatch, kth, vth, sBatch, Ssz, Dd, pKp, pVp);
    // 3) Wq fp16
    split_kernel<<<DD / 1024, 256>>>(Wq, wqh, DD);
    // 4) G_b = key_b^T @ value_b  (4th launch -> ncu profile; fp16 out)
    gemm_tc<<<dim3(Dd / 128, Dd / 128, Bn), 256, GEMM_SMEM>>>(
        kth, sBatch, vth, sBatch, nullptr, 0,
        nullptr, gh, (long)DD, Dd, Ssz);

    // 5) Wv transpose+fp16
    splitT_kernel<<<dim3(Dd / 64, Dd / 64, 1), dim3(32, 8)>>>(
        Wv, nullptr, 0, wvth, nullptr, 0, Dd, Dd, nullptr, nullptr);

    // 6-7) colsum reduce (k+v in one launch) + bias-correction matvecs
    colsum2_kernel<<<dim3(Dd / 256, Bn, 2), 256>>>(pKp, pVp, pKs, pVs);
    corr_kernel<<<dim3(Dd / 128, Bn, 2), 256>>>(Wk, Wv, pKs, pVs, pCka, pCvb);

    // 8) T1_b = G_b @ Wv  (fp32 out)
    gemm_tc<<<dim3(Dd / 128, Dd / 128, Bn), 256, GEMM_SMEM>>>(
        gh, (long)DD, wvth, 0, nullptr, 0,
        pT1, nullptr, (long)DD, Dd, Dd);

    // 9-10) M diag blocks: K-split x4 partials + deterministic reduce w/ corr
    Mdiag_part_kernel<<<dim3(Hh, Bn, MSEG), 256>>>(Wk, pT1, pMp);
    Mdiag_red_kernel<<<dim3(Hh, Bn), 256>>>(pMp, bk, bv, pCka, pCvb, pM);

    // 11-13) P (writes P^T fp16 directly), t-vector, bbig
    P_kernel<<<dim3(Dd / 128, Hh, Bn), 256>>>(pM, Wo, pth);
    tvec_kernel<<<dim3(Hh, Bn), 64>>>(pM, bq, pTv);
    bbig2_kernel<<<dim3(Dd / 64, Bn), 256>>>(pTv, Wo, bo, pB);

    // 14) WbigT_b = P_b^T @ Wq^T  (fp16 out)
    gemm_tc<<<dim3(Dd / 128, Dd / 128, Bn), 256, GEMM_SMEM>>>(
        pth, (long)DD, wqh, 0, nullptr, 0,
        nullptr, wbth, (long)DD, Dd, Dd);

    // 15) out_b = query_b @ Wbig_b + bbig_b  (fp32 out)
    gemm_tc<<<dim3(Dd / 128, Ssz / 128, Bn), 256, GEMM_SMEM>>>(
        qh, sBatch, wbth, (long)DD, pB, Dd,
        out, nullptr, sBatch, Dd, Dd);
}